// round 5
// baseline (speedup 1.0000x reference)
#include <cuda_runtime.h>
#include <cuda_bf16.h>
#include <cstdint>

#define NPIX 262144
#define AZI_C 0.006135923151542565f
#define INC_C 0.008267349088394194f

// scratch (device globals; no runtime alloc)
__device__ float g_UT[(size_t)NPIX * 64];   // pixel-major U  [pix][64]
__device__ float g_VT[(size_t)NPIX * 64];   // pixel-major V' [pix][64]
__device__ float g_mean[128], g_rstd[128];
__device__ float2 g_part[1024];

// ---------------- helpers ----------------
__device__ __forceinline__ uint32_t smem_u32(const void* p) {
    uint32_t a;
    asm("{ .reg .u64 t; cvta.to.shared.u64 t, %1; cvt.u32.u64 %0, t; }" : "=r"(a) : "l"(p));
    return a;
}
#define LDSM4(r0, r1, r2, r3, a) \
    asm volatile("ldmatrix.sync.aligned.m8n8.x4.shared.b16 {%0,%1,%2,%3}, [%4];" \
        : "=r"(r0), "=r"(r1), "=r"(r2), "=r"(r3) : "r"(a))
#define MMA(c0, c1, c2, c3, a0, a1, a2, a3, b0, b1) \
    asm volatile("mma.sync.aligned.m16n8k16.row.col.f32.bf16.bf16.f32 " \
        "{%0,%1,%2,%3},{%4,%5,%6,%7},{%8,%9},{%0,%1,%2,%3};" \
        : "+f"(c0), "+f"(c1), "+f"(c2), "+f"(c3) \
        : "r"(a0), "r"(a1), "r"(a2), "r"(a3), "r"(b0), "r"(b1))

__device__ __forceinline__ void split2(float a, float b, uint32_t& h, uint32_t& l) {
    __nv_bfloat162 hb = __floats2bfloat162_rn(a, b);
    float fa = __low2float(hb), fb = __high2float(hb);
    __nv_bfloat162 lb = __floats2bfloat162_rn(a - fa, b - fb);
    h = *reinterpret_cast<uint32_t*>(&hb);
    l = *reinterpret_cast<uint32_t*>(&lb);
}

// ---------------- GroupNorm stats, two-phase ----------------
__global__ void gn_part_kernel(const float* __restrict__ in) {
    int c = blockIdx.x, t = threadIdx.x;
    const float4* base = reinterpret_cast<const float4*>(in + (size_t)c * 16384);
    float s = 0.f, q = 0.f;
    for (int i = t; i < 4096; i += 256) {
        float4 v = base[i];
        s += (v.x + v.y) + (v.z + v.w);
        q += (v.x * v.x + v.y * v.y) + (v.z * v.z + v.w * v.w);
    }
    __shared__ float rs[256], rq[256];
    rs[t] = s; rq[t] = q;
    __syncthreads();
    for (int off = 128; off > 0; off >>= 1) {
        if (t < off) { rs[t] += rs[t + off]; rq[t] += rq[t + off]; }
        __syncthreads();
    }
    if (t == 0) g_part[c] = make_float2(rs[0], rq[0]);
}
__global__ void gn_fin_kernel() {
    int t = threadIdx.x;
    if (t < 128) {
        float s = 0.f, q = 0.f;
#pragma unroll
        for (int i = 0; i < 8; i++) { float2 p = g_part[t * 8 + i]; s += p.x; q += p.y; }
        float m = s * (1.f / 131072.f);
        g_mean[t] = m;
        g_rstd[t] = rsqrtf(q * (1.f / 131072.f) - m * m + 1e-6f);
    }
}

// ---------------- GEMM1: U,V' = relu(gn(x)) @ [Wa;Wb]^T via mma.sync ----------------
#define GA_H 0
#define GA_L 18432
#define GB_H 36864
#define GB_L 55296
#define G_CF 73728
#define G_SZ 74752

__global__ __launch_bounds__(256, 2) void gemm_mm_kernel(
    const float* __restrict__ xin, const float* __restrict__ r,
    const float* __restrict__ w1, const float* __restrict__ b1,
    const float* __restrict__ gnw, const float* __restrict__ gnb)
{
    extern __shared__ char smc[];
    uint32_t sb = smem_u32(smc);
    float* scf  = (float*)(smc + G_CF);
    float* bif  = scf + 64;
    float* b1f  = scf + 128;
    float* wp0f = scf + 192;

    int t = threadIdx.x, wid = t >> 5, ln = t & 31;
    int p0 = blockIdx.x << 7;
    int b = p0 >> 16, pl = p0 & 65535;

    if (t < 64) {
        int grp = (b << 5) + (t >> 1);
        float sc = g_rstd[grp] * gnw[t];
        scf[t]  = sc;
        bif[t]  = gnb[t] - g_mean[grp] * sc;
        b1f[t]  = b1[t];
        wp0f[t] = w1[t * 131 + 128];
    }
    for (int e = t; e < 8192; e += 256) {
        int n = e >> 6, k = e & 63;
        float v = (n < 64) ? w1[n * 131 + k] : w1[(n - 64) * 131 + 64 + k];
        __nv_bfloat16 h = __float2bfloat16(v);
        __nv_bfloat16 l = __float2bfloat16(v - __bfloat162float(h));
        *(__nv_bfloat16*)(smc + GB_H + n * 144 + k * 2) = h;
        *(__nv_bfloat16*)(smc + GB_L + n * 144 + k * 2) = l;
    }
    {
        int p = t & 127, co = (t >> 7) << 5;
        const float* xb = xin + (((size_t)(b * 64 + co)) << 16) + pl + p;
#pragma unroll
        for (int kc = 0; kc < 4; kc++) {
            float xv[8];
#pragma unroll
            for (int i = 0; i < 8; i++) {
                int k = co + kc * 8 + i;
                float raw = xb[((size_t)(kc * 8 + i)) << 16];
                xv[i] = fmaxf(fmaf(raw, scf[k], bif[k]), 0.f);
            }
            uint32_t h0, l0, h1, l1, h2, l2, h3, l3;
            split2(xv[0], xv[1], h0, l0);
            split2(xv[2], xv[3], h1, l1);
            split2(xv[4], xv[5], h2, l2);
            split2(xv[6], xv[7], h3, l3);
            uint32_t off = (uint32_t)(p * 144 + (co + kc * 8) * 2);
            *(uint4*)(smc + GA_H + off) = make_uint4(h0, h1, h2, h3);
            *(uint4*)(smc + GA_L + off) = make_uint4(l0, l1, l2, l3);
        }
    }
    __syncthreads();

    int wm = wid << 4;
    uint32_t aRow = sb + GA_H + (uint32_t)((wm + (ln & 15)) * 144 + ((ln >> 4) << 4));
    uint32_t bRow = sb + GB_H + (uint32_t)(((ln & 7)) * 144 + ((ln >> 3) << 4));

    float acc[16][4];
#pragma unroll
    for (int nb = 0; nb < 16; nb++)
#pragma unroll
        for (int j = 0; j < 4; j++) acc[nb][j] = 0.f;

#pragma unroll
    for (int kh = 0; kh < 2; kh++) {
        uint32_t ah[8], al[8];
        LDSM4(ah[0], ah[1], ah[2], ah[3], aRow + kh * 64);
        LDSM4(ah[4], ah[5], ah[6], ah[7], aRow + kh * 64 + 32);
        LDSM4(al[0], al[1], al[2], al[3], aRow + 18432 + kh * 64);
        LDSM4(al[4], al[5], al[6], al[7], aRow + 18432 + kh * 64 + 32);
#pragma unroll
        for (int nb = 0; nb < 16; nb++) {
            uint32_t bh[4], bl[4];
            uint32_t ba = bRow + (uint32_t)(nb * 1152 + kh * 64);
            LDSM4(bh[0], bh[1], bh[2], bh[3], ba);
            LDSM4(bl[0], bl[1], bl[2], bl[3], ba + 18432);
            MMA(acc[nb][0], acc[nb][1], acc[nb][2], acc[nb][3],
                ah[0], ah[1], ah[2], ah[3], bh[0], bh[1]);
            MMA(acc[nb][0], acc[nb][1], acc[nb][2], acc[nb][3],
                ah[4], ah[5], ah[6], ah[7], bh[2], bh[3]);
            MMA(acc[nb][0], acc[nb][1], acc[nb][2], acc[nb][3],
                ah[0], ah[1], ah[2], ah[3], bl[0], bl[1]);
            MMA(acc[nb][0], acc[nb][1], acc[nb][2], acc[nb][3],
                ah[4], ah[5], ah[6], ah[7], bl[2], bl[3]);
            MMA(acc[nb][0], acc[nb][1], acc[nb][2], acc[nb][3],
                al[0], al[1], al[2], al[3], bh[0], bh[1]);
            MMA(acc[nb][0], acc[nb][1], acc[nb][2], acc[nb][3],
                al[4], al[5], al[6], al[7], bh[2], bh[3]);
        }
    }

    int pr0 = wm + (ln >> 2), pr1 = pr0 + 8;
    int cx = (ln & 3) << 1;
    size_t gp0 = (size_t)((b << 16) + pl + pr0);
    size_t gp1 = (size_t)((b << 16) + pl + pr1);
    float r0 = r[gp0], r1 = r[gp1];
#pragma unroll
    for (int nb = 0; nb < 16; nb++) {
        if (nb < 8) {
            int ch = nb * 8 + cx;
            *(float2*)(g_UT + gp0 * 64 + ch) = make_float2(acc[nb][0], acc[nb][1]);
            *(float2*)(g_UT + gp1 * 64 + ch) = make_float2(acc[nb][2], acc[nb][3]);
        } else {
            int ch = (nb - 8) * 8 + cx;
            float bb0 = b1f[ch], bb1 = b1f[ch + 1];
            float w0 = wp0f[ch], w1v = wp0f[ch + 1];
            *(float2*)(g_VT + gp0 * 64 + ch) =
                make_float2(acc[nb][0] + bb0 - r0 * w0, acc[nb][1] + bb1 - r0 * w1v);
            *(float2*)(g_VT + gp1 * 64 + ch) =
                make_float2(acc[nb][2] + bb0 - r1 * w0, acc[nb][3] + bb1 - r1 * w1v);
        }
    }
}

// ---------------- Edge-max via mma.sync, B hoisted in regs, dbl-buffered A ----------------
// smem: A buf0 hi 0..18431, lo 18432..36863; buf1 hi 36864..55295, lo 55296..73727
// B staging (prologue only) overlays buf1-hi: hi@36864, lo@46080
#define EB_ST 36864
#define E_V   73728     // float [128][65]
#define E_Q   107008    // float [9][64]
#define E_B2  109312    // float [64]
#define E_SZ  109568

__global__ __launch_bounds__(256, 1) void edge_mm_kernel(
    const float* __restrict__ r, const float* __restrict__ w1,
    const float* __restrict__ w2, const float* __restrict__ b2,
    const float* __restrict__ xres, float* __restrict__ out, int add_res)
{
    extern __shared__ char smc[];
    uint32_t sb = smem_u32(smc);
    float* sV  = (float*)(smc + E_V);
    float* sQ  = (float*)(smc + E_Q);
    float* sB2 = (float*)(smc + E_B2);

    int t = threadIdx.x, wid = t >> 5, ln = t & 31;
    int p0 = blockIdx.x << 7;
    int b = p0 >> 16, pl = p0 & 65535;
    int w0 = pl >> 10, h0 = pl & 1023;

    // ---- prologue staging ----
    for (int e = t; e < 4096; e += 256) {          // B = w2 [o][k] bf16 split
        int o = e >> 6, k = e & 63;
        float v = w2[e];
        __nv_bfloat16 h = __float2bfloat16(v);
        __nv_bfloat16 l = __float2bfloat16(v - __bfloat162float(h));
        *(__nv_bfloat16*)(smc + EB_ST + o * 144 + k * 2) = h;
        *(__nv_bfloat16*)(smc + EB_ST + 9216 + o * 144 + k * 2) = l;
    }
    int p = t & 127, co = (t >> 7) << 5;
    {   // V' -> smem, pitch 65 (conflict-free reads), scalar stores
        const float4* vb = reinterpret_cast<const float4*>(
            g_VT + ((size_t)((b << 16) + pl + p)) * 64 + co);
        float* d = sV + p * 65 + co;
#pragma unroll
        for (int i = 0; i < 8; i++) {
            float4 v = vb[i];
            d[i * 4 + 0] = v.x; d[i * 4 + 1] = v.y;
            d[i * 4 + 2] = v.z; d[i * 4 + 3] = v.w;
        }
    }
    for (int e = t; e < 576; e += 256) {
        int s = e >> 6, k = e & 63;
        int swv = s / 3 - 1, shv = s % 3 - 1;
        float ca = cosf(swv * AZI_C), sa = sinf(swv * AZI_C);
        float ci = cosf(shv * INC_C), si = sinf(shv * INC_C);
        sQ[e] = ca * ci * w1[k * 131 + 128] + ca * si * w1[k * 131 + 129]
              + sa * w1[k * 131 + 130];
    }
    if (t < 64) sB2[t] = b2[t];
    __syncthreads();

    // ---- hoist B fragments into registers (once) ----
    int wm = (wid & 3) << 5;          // M stripe base (4 stripes of 32)
    int wn = (wid >> 2) << 5;         // N half base (2 halves of 32)
    uint32_t bh[4][2][4], bl[4][2][4];
    {
        uint32_t bBase = sb + EB_ST + (uint32_t)((wn + (ln & 7)) * 144 + ((ln >> 3) << 4));
#pragma unroll
        for (int nb = 0; nb < 4; nb++)
#pragma unroll
            for (int kh = 0; kh < 2; kh++) {
                uint32_t ba = bBase + (uint32_t)(nb * 1152 + kh * 64);
                LDSM4(bh[nb][kh][0], bh[nb][kh][1], bh[nb][kh][2], bh[nb][kh][3], ba);
                LDSM4(bl[nb][kh][0], bl[nb][kh][1], bl[nb][kh][2], bl[nb][kh][3], ba + 9216);
            }
    }

    // ---- A build helper (into buffer buf) ----
    auto buildA = [&](int s, int buf) {
        int swv = s / 3 - 1, shv = s % 3 - 1;
        int wsrc = (w0 - swv) & 63;
        size_t rowb = ((size_t)(b << 16)) + ((size_t)wsrc << 10);
        int hs = (h0 + p - shv) & 1023;
        const float* ub = g_UT + (rowb + hs) * 64 + co;
        float rs = __ldg(r + rowb + hs);
        const float* qv = sQ + s * 64 + co;
        const float* vv = sV + p * 65 + co;
        char* AH = smc + buf * 36864;
        char* AL = AH + 18432;
#pragma unroll
        for (int kc = 0; kc < 4; kc++) {
            float4 u0 = *reinterpret_cast<const float4*>(ub + kc * 8);
            float4 u1 = *reinterpret_cast<const float4*>(ub + kc * 8 + 4);
            float uu[8] = {u0.x, u0.y, u0.z, u0.w, u1.x, u1.y, u1.z, u1.w};
            float xv[8];
#pragma unroll
            for (int i = 0; i < 8; i++) {
                int k = kc * 8 + i;
                xv[i] = fmaxf(fmaf(rs, qv[k], uu[i] + vv[k]), 0.f);
            }
            uint32_t h0r, l0r, h1r, l1r, h2r, l2r, h3r, l3r;
            split2(xv[0], xv[1], h0r, l0r);
            split2(xv[2], xv[3], h1r, l1r);
            split2(xv[4], xv[5], h2r, l2r);
            split2(xv[6], xv[7], h3r, l3r);
            uint32_t off = (uint32_t)(p * 144 + (co + kc * 8) * 2);
            *(uint4*)(AH + off) = make_uint4(h0r, h1r, h2r, h3r);
            *(uint4*)(AL + off) = make_uint4(l0r, l1r, l2r, l3r);
        }
    };

    buildA(0, 0);
    __syncthreads();

    float best[2][4][4];
#pragma unroll
    for (int m = 0; m < 2; m++)
#pragma unroll
        for (int nb = 0; nb < 4; nb++)
#pragma unroll
            for (int j = 0; j < 4; j++) best[m][nb][j] = -1e30f;

    uint32_t aOff = (uint32_t)((wm + (ln & 15)) * 144 + ((ln >> 4) << 4));

    for (int s = 0; s < 9; s++) {
        int buf = s & 1;
        if (s < 8) buildA(s + 1, buf ^ 1);    // overlap next build with this MMA

        float acc[2][4][4];
#pragma unroll
        for (int m = 0; m < 2; m++)
#pragma unroll
            for (int nb = 0; nb < 4; nb++)
#pragma unroll
                for (int j = 0; j < 4; j++) acc[m][nb][j] = 0.f;

        uint32_t aBase = sb + buf * 36864 + aOff;
#pragma unroll
        for (int kh = 0; kh < 2; kh++) {
            uint32_t ah[2][8], al[2][8];
#pragma unroll
            for (int m = 0; m < 2; m++) {
                uint32_t ar = aBase + (uint32_t)(m * 2304 + kh * 64);
                LDSM4(ah[m][0], ah[m][1], ah[m][2], ah[m][3], ar);
                LDSM4(ah[m][4], ah[m][5], ah[m][6], ah[m][7], ar + 32);
                LDSM4(al[m][0], al[m][1], al[m][2], al[m][3], ar + 18432);
                LDSM4(al[m][4], al[m][5], al[m][6], al[m][7], ar + 18432 + 32);
            }
#pragma unroll
            for (int m = 0; m < 2; m++)
#pragma unroll
                for (int nb = 0; nb < 4; nb++) {
                    MMA(acc[m][nb][0], acc[m][nb][1], acc[m][nb][2], acc[m][nb][3],
                        ah[m][0], ah[m][1], ah[m][2], ah[m][3],
                        bh[nb][kh][0], bh[nb][kh][1]);
                    MMA(acc[m][nb][0], acc[m][nb][1], acc[m][nb][2], acc[m][nb][3],
                        ah[m][4], ah[m][5], ah[m][6], ah[m][7],
                        bh[nb][kh][2], bh[nb][kh][3]);
                    MMA(acc[m][nb][0], acc[m][nb][1], acc[m][nb][2], acc[m][nb][3],
                        ah[m][0], ah[m][1], ah[m][2], ah[m][3],
                        bl[nb][kh][0], bl[nb][kh][1]);
                    MMA(acc[m][nb][0], acc[m][nb][1], acc[m][nb][2], acc[m][nb][3],
                        ah[m][4], ah[m][5], ah[m][6], ah[m][7],
                        bl[nb][kh][2], bl[nb][kh][3]);
                    MMA(acc[m][nb][0], acc[m][nb][1], acc[m][nb][2], acc[m][nb][3],
                        al[m][0], al[m][1], al[m][2], al[m][3],
                        bh[nb][kh][0], bh[nb][kh][1]);
                    MMA(acc[m][nb][0], acc[m][nb][1], acc[m][nb][2], acc[m][nb][3],
                        al[m][4], al[m][5], al[m][6], al[m][7],
                        bh[nb][kh][2], bh[nb][kh][3]);
                }
        }
#pragma unroll
        for (int m = 0; m < 2; m++)
#pragma unroll
            for (int nb = 0; nb < 4; nb++)
#pragma unroll
                for (int j = 0; j < 4; j++)
                    best[m][nb][j] = fmaxf(best[m][nb][j], acc[m][nb][j]);
        __syncthreads();
    }

    // ---- transpose through smem (reuse buf0), coalesced channel-major store ----
    float* sTr = (float*)smc;    // [128][66]
    {
        int q = ln >> 2, cx = (ln & 3) << 1;
#pragma unroll
        for (int m = 0; m < 2; m++) {
            int pr0 = wm + m * 16 + q, pr1 = pr0 + 8;
#pragma unroll
            for (int nb = 0; nb < 4; nb++) {
                int ch = wn + nb * 8 + cx;
                *(float2*)(sTr + pr0 * 66 + ch) = make_float2(best[m][nb][0], best[m][nb][1]);
                *(float2*)(sTr + pr1 * 66 + ch) = make_float2(best[m][nb][2], best[m][nb][3]);
            }
        }
    }
    __syncthreads();
#pragma unroll
    for (int i = 0; i < 32; i++) {
        int e = t + i * 256;
        int o = e >> 7, pix = e & 127;
        float v = sTr[pix * 66 + o] + sB2[o];
        size_t idx = (((size_t)(b * 64 + o)) << 16) + (pl + pix);
        if (add_res) v += xres[idx];
        out[idx] = v;
    }
}

// ---------------------------------------------------------------------------
extern "C" void kernel_launch(void* const* d_in, const int* in_sizes, int n_in,
                              void* d_out, int out_size) {
    const float* x     = (const float*)d_in[0];
    const float* r     = (const float*)d_in[1];
    const float* n1_w  = (const float*)d_in[2];
    const float* n1_b  = (const float*)d_in[3];
    const float* c1_w1 = (const float*)d_in[4];
    const float* c1_b1 = (const float*)d_in[5];
    const float* c1_w2 = (const float*)d_in[6];
    const float* c1_b2 = (const float*)d_in[7];
    const float* n2_w  = (const float*)d_in[8];
    const float* n2_b  = (const float*)d_in[9];
    const float* c2_w1 = (const float*)d_in[10];
    const float* c2_b1 = (const float*)d_in[11];
    const float* c2_w2 = (const float*)d_in[12];
    const float* c2_b2 = (const float*)d_in[13];
    float* out = (float*)d_out;

    cudaFuncSetAttribute(gemm_mm_kernel,
                         cudaFuncAttributeMaxDynamicSharedMemorySize, G_SZ);
    cudaFuncSetAttribute(edge_mm_kernel,
                         cudaFuncAttributeMaxDynamicSharedMemorySize, E_SZ);

    gn_part_kernel<<<1024, 256>>>(x);
    gn_fin_kernel<<<1, 128>>>();
    gemm_mm_kernel<<<2048, 256, G_SZ>>>(x, r, c1_w1, c1_b1, n1_w, n1_b);
    edge_mm_kernel<<<2048, 256, E_SZ>>>(r, c1_w1, c1_w2, c1_b2, nullptr, out, 0);

    gn_part_kernel<<<1024, 256>>>(out);
    gn_fin_kernel<<<1, 128>>>();
    gemm_mm_kernel<<<2048, 256, G_SZ>>>(out, r, c2_w1, c2_b1, n2_w, n2_b);
    edge_mm_kernel<<<2048, 256, E_SZ>>>(r, c2_w1, c2_w2, c2_b2, x, out, 1);
}

// round 6
// speedup vs baseline: 1.0335x; 1.0335x over previous
#include <cuda_runtime.h>
#include <cuda_bf16.h>
#include <cstdint>

#define NPIX 262144
#define AZI_C 0.006135923151542565f
#define INC_C 0.008267349088394194f

// scratch (device globals; no runtime alloc)
__device__ float g_UT[(size_t)NPIX * 64];   // pixel-major U  [pix][64]
__device__ float g_VT[(size_t)NPIX * 64];   // pixel-major V' [pix][64]
__device__ float g_mean[128], g_rstd[128];
__device__ float2 g_part[1024];

// ---------------- helpers ----------------
__device__ __forceinline__ uint32_t smem_u32(const void* p) {
    uint32_t a;
    asm("{ .reg .u64 t; cvta.to.shared.u64 t, %1; cvt.u32.u64 %0, t; }" : "=r"(a) : "l"(p));
    return a;
}
#define LDSM4(r0, r1, r2, r3, a) \
    asm volatile("ldmatrix.sync.aligned.m8n8.x4.shared.b16 {%0,%1,%2,%3}, [%4];" \
        : "=r"(r0), "=r"(r1), "=r"(r2), "=r"(r3) : "r"(a))
#define MMA(c0, c1, c2, c3, a0, a1, a2, a3, b0, b1) \
    asm volatile("mma.sync.aligned.m16n8k16.row.col.f32.bf16.bf16.f32 " \
        "{%0,%1,%2,%3},{%4,%5,%6,%7},{%8,%9},{%0,%1,%2,%3};" \
        : "+f"(c0), "+f"(c1), "+f"(c2), "+f"(c3) \
        : "r"(a0), "r"(a1), "r"(a2), "r"(a3), "r"(b0), "r"(b1))

__device__ __forceinline__ void split2(float a, float b, uint32_t& h, uint32_t& l) {
    __nv_bfloat162 hb = __floats2bfloat162_rn(a, b);
    float fa = __low2float(hb), fb = __high2float(hb);
    __nv_bfloat162 lb = __floats2bfloat162_rn(a - fa, b - fb);
    h = *reinterpret_cast<uint32_t*>(&hb);
    l = *reinterpret_cast<uint32_t*>(&lb);
}

// ---------------- GroupNorm stats, two-phase ----------------
__global__ void gn_part_kernel(const float* __restrict__ in) {
    int c = blockIdx.x, t = threadIdx.x;
    const float4* base = reinterpret_cast<const float4*>(in + (size_t)c * 16384);
    float s = 0.f, q = 0.f;
    for (int i = t; i < 4096; i += 256) {
        float4 v = base[i];
        s += (v.x + v.y) + (v.z + v.w);
        q += (v.x * v.x + v.y * v.y) + (v.z * v.z + v.w * v.w);
    }
    __shared__ float rs[256], rq[256];
    rs[t] = s; rq[t] = q;
    __syncthreads();
    for (int off = 128; off > 0; off >>= 1) {
        if (t < off) { rs[t] += rs[t + off]; rq[t] += rq[t + off]; }
        __syncthreads();
    }
    if (t == 0) g_part[c] = make_float2(rs[0], rq[0]);
}
__global__ void gn_fin_kernel() {
    int t = threadIdx.x;
    if (t < 128) {
        float s = 0.f, q = 0.f;
#pragma unroll
        for (int i = 0; i < 8; i++) { float2 p = g_part[t * 8 + i]; s += p.x; q += p.y; }
        float m = s * (1.f / 131072.f);
        g_mean[t] = m;
        g_rstd[t] = rsqrtf(q * (1.f / 131072.f) - m * m + 1e-6f);
    }
}

// ---------------- GEMM1: U,V' = relu(gn(x)) @ [Wa;Wb]^T via mma.sync ----------------
#define GA_H 0
#define GA_L 18432
#define GB_H 36864
#define GB_L 55296
#define G_CF 73728
#define G_SZ 74752

__global__ __launch_bounds__(256, 2) void gemm_mm_kernel(
    const float* __restrict__ xin, const float* __restrict__ r,
    const float* __restrict__ w1, const float* __restrict__ b1,
    const float* __restrict__ gnw, const float* __restrict__ gnb)
{
    extern __shared__ char smc[];
    uint32_t sb = smem_u32(smc);
    float* scf  = (float*)(smc + G_CF);
    float* bif  = scf + 64;
    float* b1f  = scf + 128;
    float* wp0f = scf + 192;

    int t = threadIdx.x, wid = t >> 5, ln = t & 31;
    int p0 = blockIdx.x << 7;
    int b = p0 >> 16, pl = p0 & 65535;

    if (t < 64) {
        int grp = (b << 5) + (t >> 1);
        float sc = g_rstd[grp] * gnw[t];
        scf[t]  = sc;
        bif[t]  = gnb[t] - g_mean[grp] * sc;
        b1f[t]  = b1[t];
        wp0f[t] = w1[t * 131 + 128];
    }
    for (int e = t; e < 8192; e += 256) {
        int n = e >> 6, k = e & 63;
        float v = (n < 64) ? w1[n * 131 + k] : w1[(n - 64) * 131 + 64 + k];
        __nv_bfloat16 h = __float2bfloat16(v);
        __nv_bfloat16 l = __float2bfloat16(v - __bfloat162float(h));
        *(__nv_bfloat16*)(smc + GB_H + n * 144 + k * 2) = h;
        *(__nv_bfloat16*)(smc + GB_L + n * 144 + k * 2) = l;
    }
    {
        int p = t & 127, co = (t >> 7) << 5;
        const float* xb = xin + (((size_t)(b * 64 + co)) << 16) + pl + p;
#pragma unroll
        for (int kc = 0; kc < 4; kc++) {
            float xv[8];
#pragma unroll
            for (int i = 0; i < 8; i++) {
                int k = co + kc * 8 + i;
                float raw = xb[((size_t)(kc * 8 + i)) << 16];
                xv[i] = fmaxf(fmaf(raw, scf[k], bif[k]), 0.f);
            }
            uint32_t h0, l0, h1, l1, h2, l2, h3, l3;
            split2(xv[0], xv[1], h0, l0);
            split2(xv[2], xv[3], h1, l1);
            split2(xv[4], xv[5], h2, l2);
            split2(xv[6], xv[7], h3, l3);
            uint32_t off = (uint32_t)(p * 144 + (co + kc * 8) * 2);
            *(uint4*)(smc + GA_H + off) = make_uint4(h0, h1, h2, h3);
            *(uint4*)(smc + GA_L + off) = make_uint4(l0, l1, l2, l3);
        }
    }
    __syncthreads();

    int wm = wid << 4;
    uint32_t aRow = sb + GA_H + (uint32_t)((wm + (ln & 15)) * 144 + ((ln >> 4) << 4));
    uint32_t bRow = sb + GB_H + (uint32_t)(((ln & 7)) * 144 + ((ln >> 3) << 4));

    float acc[16][4];
#pragma unroll
    for (int nb = 0; nb < 16; nb++)
#pragma unroll
        for (int j = 0; j < 4; j++) acc[nb][j] = 0.f;

#pragma unroll
    for (int kh = 0; kh < 2; kh++) {
        uint32_t ah[8], al[8];
        LDSM4(ah[0], ah[1], ah[2], ah[3], aRow + kh * 64);
        LDSM4(ah[4], ah[5], ah[6], ah[7], aRow + kh * 64 + 32);
        LDSM4(al[0], al[1], al[2], al[3], aRow + 18432 + kh * 64);
        LDSM4(al[4], al[5], al[6], al[7], aRow + 18432 + kh * 64 + 32);
#pragma unroll
        for (int nb = 0; nb < 16; nb++) {
            uint32_t bh[4], bl[4];
            uint32_t ba = bRow + (uint32_t)(nb * 1152 + kh * 64);
            LDSM4(bh[0], bh[1], bh[2], bh[3], ba);
            LDSM4(bl[0], bl[1], bl[2], bl[3], ba + 18432);
            MMA(acc[nb][0], acc[nb][1], acc[nb][2], acc[nb][3],
                ah[0], ah[1], ah[2], ah[3], bh[0], bh[1]);
            MMA(acc[nb][0], acc[nb][1], acc[nb][2], acc[nb][3],
                ah[4], ah[5], ah[6], ah[7], bh[2], bh[3]);
            MMA(acc[nb][0], acc[nb][1], acc[nb][2], acc[nb][3],
                ah[0], ah[1], ah[2], ah[3], bl[0], bl[1]);
            MMA(acc[nb][0], acc[nb][1], acc[nb][2], acc[nb][3],
                ah[4], ah[5], ah[6], ah[7], bl[2], bl[3]);
            MMA(acc[nb][0], acc[nb][1], acc[nb][2], acc[nb][3],
                al[0], al[1], al[2], al[3], bh[0], bh[1]);
            MMA(acc[nb][0], acc[nb][1], acc[nb][2], acc[nb][3],
                al[4], al[5], al[6], al[7], bh[2], bh[3]);
        }
    }

    int pr0 = wm + (ln >> 2), pr1 = pr0 + 8;
    int cx = (ln & 3) << 1;
    size_t gp0 = (size_t)((b << 16) + pl + pr0);
    size_t gp1 = (size_t)((b << 16) + pl + pr1);
    float r0 = r[gp0], r1 = r[gp1];
#pragma unroll
    for (int nb = 0; nb < 16; nb++) {
        if (nb < 8) {
            int ch = nb * 8 + cx;
            *(float2*)(g_UT + gp0 * 64 + ch) = make_float2(acc[nb][0], acc[nb][1]);
            *(float2*)(g_UT + gp1 * 64 + ch) = make_float2(acc[nb][2], acc[nb][3]);
        } else {
            int ch = (nb - 8) * 8 + cx;
            float bb0 = b1f[ch], bb1 = b1f[ch + 1];
            float w0 = wp0f[ch], w1v = wp0f[ch + 1];
            *(float2*)(g_VT + gp0 * 64 + ch) =
                make_float2(acc[nb][0] + bb0 - r0 * w0, acc[nb][1] + bb1 - r0 * w1v);
            *(float2*)(g_VT + gp1 * 64 + ch) =
                make_float2(acc[nb][2] + bb0 - r1 * w0, acc[nb][3] + bb1 - r1 * w1v);
        }
    }
}

// ---------------- Edge-max: B hoisted, U prefetched, swizzled conflict-free A ----------------
// A buffers: swizzled pitch 128B: addr = row*128 + 16*((chunk)^(row&7))
// A0H 0 | A0L 16384 | A1H 32768 | A1L 49152 | BH 65536 | BL 73728 |
// sV 81920 ([128][68] f32) | sQ 116736 ([9][64]) | sB2 119040
#define EB_H 65536
#define EB_L 73728
#define E_V  81920
#define E_Q  116736
#define E_B2 119040
#define E_SZ 119296

__global__ __launch_bounds__(256, 1) void edge_mm_kernel(
    const float* __restrict__ r, const float* __restrict__ w1,
    const float* __restrict__ w2, const float* __restrict__ b2,
    const float* __restrict__ xres, float* __restrict__ out, int add_res)
{
    extern __shared__ char smc[];
    uint32_t sb = smem_u32(smc);
    float* sV  = (float*)(smc + E_V);
    float* sQ  = (float*)(smc + E_Q);
    float* sB2 = (float*)(smc + E_B2);

    int t = threadIdx.x, wid = t >> 5, ln = t & 31;
    int p0 = blockIdx.x << 7;
    int b = p0 >> 16, pl = p0 & 65535;
    int w0 = pl >> 10, h0 = pl & 1023;
    int p = t & 127, co = (t >> 7) << 5;

    // ---- prologue staging ----
    for (int e = t; e < 4096; e += 256) {      // B = w2 [o][k], swizzled pitch 128
        int o = e >> 6, k = e & 63;
        float v = w2[e];
        __nv_bfloat16 h = __float2bfloat16(v);
        __nv_bfloat16 l = __float2bfloat16(v - __bfloat162float(h));
        uint32_t off = (uint32_t)(o * 128 + ((((k >> 3) ^ (o & 7))) << 4) + (k & 7) * 2);
        *(__nv_bfloat16*)(smc + EB_H + off) = h;
        *(__nv_bfloat16*)(smc + EB_L + off) = l;
    }
    {   // V' -> smem, pitch 68 floats
        const float4* vb = reinterpret_cast<const float4*>(
            g_VT + ((size_t)((b << 16) + pl + p)) * 64 + co);
        float4* d = reinterpret_cast<float4*>(sV + p * 68 + co);
#pragma unroll
        for (int i = 0; i < 8; i++) d[i] = vb[i];
    }
    for (int e = t; e < 576; e += 256) {
        int s = e >> 6, k = e & 63;
        int swv = s / 3 - 1, shv = s % 3 - 1;
        float ca = cosf(swv * AZI_C), sa = sinf(swv * AZI_C);
        float ci = cosf(shv * INC_C), si = sinf(shv * INC_C);
        sQ[e] = ca * ci * w1[k * 131 + 128] + ca * si * w1[k * 131 + 129]
              + sa * w1[k * 131 + 130];
    }
    if (t < 64) sB2[t] = b2[t];
    __syncthreads();

    // ---- hoist B fragments into registers (once) ----
    int wm = (wid & 3) << 5;          // M stripe (4 stripes of 32 pixels)
    int wn = (wid >> 2) << 5;         // N half (2 halves of 32 channels)
    uint32_t bh[4][2][4], bl[4][2][4];
    {
        int brow = wn + (ln & 7);
#pragma unroll
        for (int nb = 0; nb < 4; nb++) {
            int row = brow + nb * 8;
#pragma unroll
            for (int kh = 0; kh < 2; kh++) {
                int c = kh * 4 + (ln >> 3);
                uint32_t ad = sb + (uint32_t)(row * 128 + ((c ^ (row & 7)) << 4));
                LDSM4(bh[nb][kh][0], bh[nb][kh][1], bh[nb][kh][2], bh[nb][kh][3],
                      ad + EB_H);
                LDSM4(bl[nb][kh][0], bl[nb][kh][1], bl[nb][kh][2], bl[nb][kh][3],
                      ad + EB_L);
            }
        }
    }

    // ---- U prefetch (regs) + A finish (split + swizzled STS) ----
    float4 uR[8];
    float rsR;
    auto prefetchU = [&](int s) {
        int swv = s / 3 - 1, shv = s % 3 - 1;
        int wsrc = (w0 - swv) & 63;
        size_t rowb = ((size_t)(b << 16)) + ((size_t)wsrc << 10);
        int hs = (h0 + p - shv) & 1023;
        const float4* ub = reinterpret_cast<const float4*>(
            g_UT + (rowb + hs) * 64 + co);
#pragma unroll
        for (int i = 0; i < 8; i++) uR[i] = ub[i];
        rsR = __ldg(r + rowb + hs);
    };
    auto storeA = [&](int s, int buf) {
        const float* qv = sQ + s * 64 + co;
        const float* vv = sV + p * 68 + co;
        char* AH = smc + buf * 32768;
        char* AL = AH + 16384;
        float rs = rsR;
#pragma unroll
        for (int kc = 0; kc < 4; kc++) {
            float4 u0 = uR[kc * 2], u1 = uR[kc * 2 + 1];
            float uu[8] = {u0.x, u0.y, u0.z, u0.w, u1.x, u1.y, u1.z, u1.w};
            float xv[8];
#pragma unroll
            for (int i = 0; i < 8; i++) {
                int k = kc * 8 + i;
                xv[i] = fmaxf(fmaf(rs, qv[k], uu[i] + vv[k]), 0.f);
            }
            uint32_t h0r, l0r, h1r, l1r, h2r, l2r, h3r, l3r;
            split2(xv[0], xv[1], h0r, l0r);
            split2(xv[2], xv[3], h1r, l1r);
            split2(xv[4], xv[5], h2r, l2r);
            split2(xv[6], xv[7], h3r, l3r);
            int c = (co >> 3) + kc;
            uint32_t off = (uint32_t)(p * 128 + ((c ^ (p & 7)) << 4));
            *(uint4*)(AH + off) = make_uint4(h0r, h1r, h2r, h3r);
            *(uint4*)(AL + off) = make_uint4(l0r, l1r, l2r, l3r);
        }
    };

    prefetchU(0);
    storeA(0, 0);
    __syncthreads();

    float best[2][4][4];
#pragma unroll
    for (int m = 0; m < 2; m++)
#pragma unroll
        for (int nb = 0; nb < 4; nb++)
#pragma unroll
            for (int j = 0; j < 4; j++) best[m][nb][j] = -1e30f;

    for (int s = 0; s < 9; s++) {
        int buf = s & 1;
        if (s < 8) prefetchU(s + 1);        // LDG issued; consumed after MMAs

        float acc[2][4][4];
#pragma unroll
        for (int m = 0; m < 2; m++)
#pragma unroll
            for (int nb = 0; nb < 4; nb++)
#pragma unroll
                for (int j = 0; j < 4; j++) acc[m][nb][j] = 0.f;

        uint32_t aBase = sb + buf * 32768;
#pragma unroll
        for (int kh = 0; kh < 2; kh++) {
            uint32_t ah[2][8], al[2][8];
#pragma unroll
            for (int m = 0; m < 2; m++) {
                int row = wm + m * 16 + (ln & 15);
                int c0 = kh * 4 + (ln >> 4);
                uint32_t ad0 = aBase + (uint32_t)(row * 128 + ((c0 ^ (row & 7)) << 4));
                uint32_t ad1 = aBase + (uint32_t)(row * 128 + (((c0 + 2) ^ (row & 7)) << 4));
                LDSM4(ah[m][0], ah[m][1], ah[m][2], ah[m][3], ad0);
                LDSM4(ah[m][4], ah[m][5], ah[m][6], ah[m][7], ad1);
                LDSM4(al[m][0], al[m][1], al[m][2], al[m][3], ad0 + 16384);
                LDSM4(al[m][4], al[m][5], al[m][6], al[m][7], ad1 + 16384);
            }
#pragma unroll
            for (int m = 0; m < 2; m++)
#pragma unroll
                for (int nb = 0; nb < 4; nb++) {
                    MMA(acc[m][nb][0], acc[m][nb][1], acc[m][nb][2], acc[m][nb][3],
                        ah[m][0], ah[m][1], ah[m][2], ah[m][3],
                        bh[nb][kh][0], bh[nb][kh][1]);
                    MMA(acc[m][nb][0], acc[m][nb][1], acc[m][nb][2], acc[m][nb][3],
                        ah[m][4], ah[m][5], ah[m][6], ah[m][7],
                        bh[nb][kh][2], bh[nb][kh][3]);
                    MMA(acc[m][nb][0], acc[m][nb][1], acc[m][nb][2], acc[m][nb][3],
                        ah[m][0], ah[m][1], ah[m][2], ah[m][3],
                        bl[nb][kh][0], bl[nb][kh][1]);
                    MMA(acc[m][nb][0], acc[m][nb][1], acc[m][nb][2], acc[m][nb][3],
                        ah[m][4], ah[m][5], ah[m][6], ah[m][7],
                        bl[nb][kh][2], bl[nb][kh][3]);
                    MMA(acc[m][nb][0], acc[m][nb][1], acc[m][nb][2], acc[m][nb][3],
                        al[m][0], al[m][1], al[m][2], al[m][3],
                        bh[nb][kh][0], bh[nb][kh][1]);
                    MMA(acc[m][nb][0], acc[m][nb][1], acc[m][nb][2], acc[m][nb][3],
                        al[m][4], al[m][5], al[m][6], al[m][7],
                        bh[nb][kh][2], bh[nb][kh][3]);
                }
        }
#pragma unroll
        for (int m = 0; m < 2; m++)
#pragma unroll
            for (int nb = 0; nb < 4; nb++)
#pragma unroll
                for (int j = 0; j < 4; j++)
                    best[m][nb][j] = fmaxf(best[m][nb][j], acc[m][nb][j]);

        if (s < 8) {
            storeA(s + 1, buf ^ 1);         // write other buffer; safe pre-sync
            __syncthreads();
        }
    }
    __syncthreads();

    // ---- transpose through smem (reuse A0), coalesced channel-major store ----
    float* sTr = (float*)smc;    // [128][66]
    {
        int q = ln >> 2, cx = (ln & 3) << 1;
#pragma unroll
        for (int m = 0; m < 2; m++) {
            int pr0 = wm + m * 16 + q, pr1 = pr0 + 8;
#pragma unroll
            for (int nb = 0; nb < 4; nb++) {
                int ch = wn + nb * 8 + cx;
                *(float2*)(sTr + pr0 * 66 + ch) = make_float2(best[m][nb][0], best[m][nb][1]);
                *(float2*)(sTr + pr1 * 66 + ch) = make_float2(best[m][nb][2], best[m][nb][3]);
            }
        }
    }
    __syncthreads();
#pragma unroll
    for (int i = 0; i < 32; i++) {
        int e = t + i * 256;
        int o = e >> 7, pix = e & 127;
        float v = sTr[pix * 66 + o] + sB2[o];
        size_t idx = (((size_t)(b * 64 + o)) << 16) + (pl + pix);
        if (add_res) v += xres[idx];
        out[idx] = v;
    }
}

// ---------------------------------------------------------------------------
extern "C" void kernel_launch(void* const* d_in, const int* in_sizes, int n_in,
                              void* d_out, int out_size) {
    const float* x     = (const float*)d_in[0];
    const float* r     = (const float*)d_in[1];
    const float* n1_w  = (const float*)d_in[2];
    const float* n1_b  = (const float*)d_in[3];
    const float* c1_w1 = (const float*)d_in[4];
    const float* c1_b1 = (const float*)d_in[5];
    const float* c1_w2 = (const float*)d_in[6];
    const float* c1_b2 = (const float*)d_in[7];
    const float* n2_w  = (const float*)d_in[8];
    const float* n2_b  = (const float*)d_in[9];
    const float* c2_w1 = (const float*)d_in[10];
    const float* c2_b1 = (const float*)d_in[11];
    const float* c2_w2 = (const float*)d_in[12];
    const float* c2_b2 = (const float*)d_in[13];
    float* out = (float*)d_out;

    cudaFuncSetAttribute(gemm_mm_kernel,
                         cudaFuncAttributeMaxDynamicSharedMemorySize, G_SZ);
    cudaFuncSetAttribute(edge_mm_kernel,
                         cudaFuncAttributeMaxDynamicSharedMemorySize, E_SZ);

    gn_part_kernel<<<1024, 256>>>(x);
    gn_fin_kernel<<<1, 128>>>();
    gemm_mm_kernel<<<2048, 256, G_SZ>>>(x, r, c1_w1, c1_b1, n1_w, n1_b);
    edge_mm_kernel<<<2048, 256, E_SZ>>>(r, c1_w1, c1_w2, c1_b2, nullptr, out, 0);

    gn_part_kernel<<<1024, 256>>>(out);
    gn_fin_kernel<<<1, 128>>>();
    gemm_mm_kernel<<<2048, 256, G_SZ>>>(out, r, c2_w1, c2_b1, n2_w, n2_b);
    edge_mm_kernel<<<2048, 256, E_SZ>>>(r, c2_w1, c2_w2, c2_b2, x, out, 1);
}

// round 7
// speedup vs baseline: 1.1366x; 1.0998x over previous
#include <cuda_runtime.h>
#include <cuda_bf16.h>
#include <cstdint>

#define NPIX 262144
#define AZI_C 0.006135923151542565f
#define INC_C 0.008267349088394194f

// scratch (device globals; no runtime alloc)
__device__ float g_UT[(size_t)NPIX * 64];   // pixel-major U  [pix][64]
__device__ float g_VT[(size_t)NPIX * 64];   // pixel-major V' [pix][64]
__device__ float g_mean[128], g_rstd[128];
__device__ float2 g_part[1024];

// ---------------- helpers ----------------
__device__ __forceinline__ uint32_t smem_u32(const void* p) {
    uint32_t a;
    asm("{ .reg .u64 t; cvta.to.shared.u64 t, %1; cvt.u32.u64 %0, t; }" : "=r"(a) : "l"(p));
    return a;
}
#define LDSM4(r0, r1, r2, r3, a) \
    asm volatile("ldmatrix.sync.aligned.m8n8.x4.shared.b16 {%0,%1,%2,%3}, [%4];" \
        : "=r"(r0), "=r"(r1), "=r"(r2), "=r"(r3) : "r"(a))
#define MMA(c0, c1, c2, c3, a0, a1, a2, a3, b0, b1) \
    asm volatile("mma.sync.aligned.m16n8k16.row.col.f32.bf16.bf16.f32 " \
        "{%0,%1,%2,%3},{%4,%5,%6,%7},{%8,%9},{%0,%1,%2,%3};" \
        : "+f"(c0), "+f"(c1), "+f"(c2), "+f"(c3) \
        : "r"(a0), "r"(a1), "r"(a2), "r"(a3), "r"(b0), "r"(b1))

__device__ __forceinline__ void split2(float a, float b, uint32_t& h, uint32_t& l) {
    __nv_bfloat162 hb = __floats2bfloat162_rn(a, b);
    float fa = __low2float(hb), fb = __high2float(hb);
    __nv_bfloat162 lb = __floats2bfloat162_rn(a - fa, b - fb);
    h = *reinterpret_cast<uint32_t*>(&hb);
    l = *reinterpret_cast<uint32_t*>(&lb);
}

// ---------------- GroupNorm stats, two-phase ----------------
__global__ void gn_part_kernel(const float* __restrict__ in) {
    int c = blockIdx.x, t = threadIdx.x;
    const float4* base = reinterpret_cast<const float4*>(in + (size_t)c * 16384);
    float s = 0.f, q = 0.f;
    for (int i = t; i < 4096; i += 256) {
        float4 v = base[i];
        s += (v.x + v.y) + (v.z + v.w);
        q += (v.x * v.x + v.y * v.y) + (v.z * v.z + v.w * v.w);
    }
    __shared__ float rs[256], rq[256];
    rs[t] = s; rq[t] = q;
    __syncthreads();
    for (int off = 128; off > 0; off >>= 1) {
        if (t < off) { rs[t] += rs[t + off]; rq[t] += rq[t + off]; }
        __syncthreads();
    }
    if (t == 0) g_part[c] = make_float2(rs[0], rq[0]);
}
__global__ void gn_fin_kernel() {
    int t = threadIdx.x;
    if (t < 128) {
        float s = 0.f, q = 0.f;
#pragma unroll
        for (int i = 0; i < 8; i++) { float2 p = g_part[t * 8 + i]; s += p.x; q += p.y; }
        float m = s * (1.f / 131072.f);
        g_mean[t] = m;
        g_rstd[t] = rsqrtf(q * (1.f / 131072.f) - m * m + 1e-6f);
    }
}

// ---------------- GEMM1: U,V' = relu(gn(x)) @ [Wa;Wb]^T via mma.sync ----------------
#define GA_H 0
#define GA_L 18432
#define GB_H 36864
#define GB_L 55296
#define G_CF 73728
#define G_SZ 74752

__global__ __launch_bounds__(256, 2) void gemm_mm_kernel(
    const float* __restrict__ xin, const float* __restrict__ r,
    const float* __restrict__ w1, const float* __restrict__ b1,
    const float* __restrict__ gnw, const float* __restrict__ gnb)
{
    extern __shared__ char smc[];
    uint32_t sb = smem_u32(smc);
    float* scf  = (float*)(smc + G_CF);
    float* bif  = scf + 64;
    float* b1f  = scf + 128;
    float* wp0f = scf + 192;

    int t = threadIdx.x, wid = t >> 5, ln = t & 31;
    int p0 = blockIdx.x << 7;
    int b = p0 >> 16, pl = p0 & 65535;

    if (t < 64) {
        int grp = (b << 5) + (t >> 1);
        float sc = g_rstd[grp] * gnw[t];
        scf[t]  = sc;
        bif[t]  = gnb[t] - g_mean[grp] * sc;
        b1f[t]  = b1[t];
        wp0f[t] = w1[t * 131 + 128];
    }
    for (int e = t; e < 8192; e += 256) {
        int n = e >> 6, k = e & 63;
        float v = (n < 64) ? w1[n * 131 + k] : w1[(n - 64) * 131 + 64 + k];
        __nv_bfloat16 h = __float2bfloat16(v);
        __nv_bfloat16 l = __float2bfloat16(v - __bfloat162float(h));
        *(__nv_bfloat16*)(smc + GB_H + n * 144 + k * 2) = h;
        *(__nv_bfloat16*)(smc + GB_L + n * 144 + k * 2) = l;
    }
    {
        int p = t & 127, co = (t >> 7) << 5;
        const float* xb = xin + (((size_t)(b * 64 + co)) << 16) + pl + p;
#pragma unroll
        for (int kc = 0; kc < 4; kc++) {
            float xv[8];
#pragma unroll
            for (int i = 0; i < 8; i++) {
                int k = co + kc * 8 + i;
                float raw = xb[((size_t)(kc * 8 + i)) << 16];
                xv[i] = fmaxf(fmaf(raw, scf[k], bif[k]), 0.f);
            }
            uint32_t h0, l0, h1, l1, h2, l2, h3, l3;
            split2(xv[0], xv[1], h0, l0);
            split2(xv[2], xv[3], h1, l1);
            split2(xv[4], xv[5], h2, l2);
            split2(xv[6], xv[7], h3, l3);
            uint32_t off = (uint32_t)(p * 144 + (co + kc * 8) * 2);
            *(uint4*)(smc + GA_H + off) = make_uint4(h0, h1, h2, h3);
            *(uint4*)(smc + GA_L + off) = make_uint4(l0, l1, l2, l3);
        }
    }
    __syncthreads();

    int wm = wid << 4;
    uint32_t aRow = sb + GA_H + (uint32_t)((wm + (ln & 15)) * 144 + ((ln >> 4) << 4));
    uint32_t bRow = sb + GB_H + (uint32_t)(((ln & 7)) * 144 + ((ln >> 3) << 4));

    float acc[16][4];
#pragma unroll
    for (int nb = 0; nb < 16; nb++)
#pragma unroll
        for (int j = 0; j < 4; j++) acc[nb][j] = 0.f;

#pragma unroll
    for (int kh = 0; kh < 2; kh++) {
        uint32_t ah[8], al[8];
        LDSM4(ah[0], ah[1], ah[2], ah[3], aRow + kh * 64);
        LDSM4(ah[4], ah[5], ah[6], ah[7], aRow + kh * 64 + 32);
        LDSM4(al[0], al[1], al[2], al[3], aRow + 18432 + kh * 64);
        LDSM4(al[4], al[5], al[6], al[7], aRow + 18432 + kh * 64 + 32);
#pragma unroll
        for (int nb = 0; nb < 16; nb++) {
            uint32_t bh[4], bl[4];
            uint32_t ba = bRow + (uint32_t)(nb * 1152 + kh * 64);
            LDSM4(bh[0], bh[1], bh[2], bh[3], ba);
            LDSM4(bl[0], bl[1], bl[2], bl[3], ba + 18432);
            MMA(acc[nb][0], acc[nb][1], acc[nb][2], acc[nb][3],
                ah[0], ah[1], ah[2], ah[3], bh[0], bh[1]);
            MMA(acc[nb][0], acc[nb][1], acc[nb][2], acc[nb][3],
                ah[4], ah[5], ah[6], ah[7], bh[2], bh[3]);
            MMA(acc[nb][0], acc[nb][1], acc[nb][2], acc[nb][3],
                ah[0], ah[1], ah[2], ah[3], bl[0], bl[1]);
            MMA(acc[nb][0], acc[nb][1], acc[nb][2], acc[nb][3],
                ah[4], ah[5], ah[6], ah[7], bl[2], bl[3]);
            MMA(acc[nb][0], acc[nb][1], acc[nb][2], acc[nb][3],
                al[0], al[1], al[2], al[3], bh[0], bh[1]);
            MMA(acc[nb][0], acc[nb][1], acc[nb][2], acc[nb][3],
                al[4], al[5], al[6], al[7], bh[2], bh[3]);
        }
    }

    int pr0 = wm + (ln >> 2), pr1 = pr0 + 8;
    int cx = (ln & 3) << 1;
    size_t gp0 = (size_t)((b << 16) + pl + pr0);
    size_t gp1 = (size_t)((b << 16) + pl + pr1);
    float r0 = r[gp0], r1 = r[gp1];
#pragma unroll
    for (int nb = 0; nb < 16; nb++) {
        if (nb < 8) {
            int ch = nb * 8 + cx;
            *(float2*)(g_UT + gp0 * 64 + ch) = make_float2(acc[nb][0], acc[nb][1]);
            *(float2*)(g_UT + gp1 * 64 + ch) = make_float2(acc[nb][2], acc[nb][3]);
        } else {
            int ch = (nb - 8) * 8 + cx;
            float bb0 = b1f[ch], bb1 = b1f[ch + 1];
            float w0 = wp0f[ch], w1v = wp0f[ch + 1];
            *(float2*)(g_VT + gp0 * 64 + ch) =
                make_float2(acc[nb][0] + bb0 - r0 * w0, acc[nb][1] + bb1 - r0 * w1v);
            *(float2*)(g_VT + gp1 * 64 + ch) =
                make_float2(acc[nb][2] + bb0 - r1 * w0, acc[nb][3] + bb1 - r1 * w1v);
        }
    }
}

// ---------------- Edge-max via mma.sync (R4 skeleton, sV pitch 65 conflict-free) ----------------
#define EA_H 0
#define EA_L 18432
#define EB_H 36864
#define EB_L 46080
#define E_V  55296     // float [128][65] = 33280 B
#define E_Q  88576     // float [9][64]
#define E_B2 90880     // float [64]
#define E_SZ 91136

__global__ __launch_bounds__(256, 2) void edge_mm_kernel(
    const float* __restrict__ r, const float* __restrict__ w1,
    const float* __restrict__ w2, const float* __restrict__ b2,
    const float* __restrict__ xres, float* __restrict__ out, int add_res)
{
    extern __shared__ char smc[];
    uint32_t sb = smem_u32(smc);
    float* sV  = (float*)(smc + E_V);    // [128][65]
    float* sQ  = (float*)(smc + E_Q);    // [9][64]
    float* sB2 = (float*)(smc + E_B2);   // [64]

    int t = threadIdx.x, wid = t >> 5, ln = t & 31;
    int p0 = blockIdx.x << 7;
    int b = p0 >> 16, pl = p0 & 65535;
    int w0 = pl >> 10, h0 = pl & 1023;

    // B = w2 [o][k] bf16 split, pitch 144 (conflict-free LDSM)
    for (int e = t; e < 4096; e += 256) {
        int o = e >> 6, k = e & 63;
        float v = w2[e];
        __nv_bfloat16 h = __float2bfloat16(v);
        __nv_bfloat16 l = __float2bfloat16(v - __bfloat162float(h));
        *(__nv_bfloat16*)(smc + EB_H + o * 144 + k * 2) = h;
        *(__nv_bfloat16*)(smc + EB_L + o * 144 + k * 2) = l;
    }
    int p = t & 127, co = (t >> 7) << 5;
    {   // V' tile into smem, pitch 65 -> scalar loads are conflict-free
        const float4* vb = reinterpret_cast<const float4*>(
            g_VT + ((size_t)((b << 16) + pl + p)) * 64 + co);
        float* d = sV + p * 65 + co;
#pragma unroll
        for (int i = 0; i < 8; i++) {
            float4 v = vb[i];
            d[i * 4 + 0] = v.x; d[i * 4 + 1] = v.y;
            d[i * 4 + 2] = v.z; d[i * 4 + 3] = v.w;
        }
    }
    for (int e = t; e < 576; e += 256) {
        int s = e >> 6, k = e & 63;
        int swv = s / 3 - 1, shv = s % 3 - 1;
        float ca = cosf(swv * AZI_C), sa = sinf(swv * AZI_C);
        float ci = cosf(shv * INC_C), si = sinf(shv * INC_C);
        sQ[e] = ca * ci * w1[k * 131 + 128] + ca * si * w1[k * 131 + 129]
              + sa * w1[k * 131 + 130];
    }
    if (t < 64) sB2[t] = b2[t];
    __syncthreads();

    int wm = wid << 4;
    uint32_t aRow = sb + EA_H + (uint32_t)((wm + (ln & 15)) * 144 + ((ln >> 4) << 4));
    uint32_t bRow = sb + EB_H + (uint32_t)(((ln & 7)) * 144 + ((ln >> 3) << 4));

    float best[8][4];
#pragma unroll
    for (int nb = 0; nb < 8; nb++)
#pragma unroll
        for (int j = 0; j < 4; j++) best[nb][j] = -1e30f;

    for (int s = 0; s < 9; s++) {
        int swv = s / 3 - 1, shv = s % 3 - 1;
        int wsrc = (w0 - swv) & 63;
        size_t rowb = ((size_t)(b << 16)) + ((size_t)wsrc << 10);
        // A build: t_s = relu(U_s + V' + r_s*q)
        {
            int hs = (h0 + p - shv) & 1023;
            const float* ub = g_UT + (rowb + hs) * 64 + co;
            float rs = __ldg(r + rowb + hs);
            const float* qv = sQ + s * 64 + co;
            const float* vv = sV + p * 65 + co;
#pragma unroll
            for (int kc = 0; kc < 4; kc++) {
                float4 u0 = *reinterpret_cast<const float4*>(ub + kc * 8);
                float4 u1 = *reinterpret_cast<const float4*>(ub + kc * 8 + 4);
                float uu[8] = {u0.x, u0.y, u0.z, u0.w, u1.x, u1.y, u1.z, u1.w};
                float xv[8];
#pragma unroll
                for (int i = 0; i < 8; i++) {
                    int k = kc * 8 + i;
                    xv[i] = fmaxf(fmaf(rs, qv[k], uu[i] + vv[k]), 0.f);
                }
                uint32_t h0r, l0r, h1r, l1r, h2r, l2r, h3r, l3r;
                split2(xv[0], xv[1], h0r, l0r);
                split2(xv[2], xv[3], h1r, l1r);
                split2(xv[4], xv[5], h2r, l2r);
                split2(xv[6], xv[7], h3r, l3r);
                uint32_t off = (uint32_t)(p * 144 + (co + kc * 8) * 2);
                *(uint4*)(smc + EA_H + off) = make_uint4(h0r, h1r, h2r, h3r);
                *(uint4*)(smc + EA_L + off) = make_uint4(l0r, l1r, l2r, l3r);
            }
        }
        __syncthreads();

        float acc[8][4];
#pragma unroll
        for (int nb = 0; nb < 8; nb++)
#pragma unroll
            for (int j = 0; j < 4; j++) acc[nb][j] = 0.f;

#pragma unroll
        for (int kh = 0; kh < 2; kh++) {
            uint32_t ah[8], al[8];
            LDSM4(ah[0], ah[1], ah[2], ah[3], aRow + kh * 64);
            LDSM4(ah[4], ah[5], ah[6], ah[7], aRow + kh * 64 + 32);
            LDSM4(al[0], al[1], al[2], al[3], aRow + 18432 + kh * 64);
            LDSM4(al[4], al[5], al[6], al[7], aRow + 18432 + kh * 64 + 32);
#pragma unroll
            for (int nb = 0; nb < 8; nb++) {
                uint32_t bh[4], bl[4];
                uint32_t ba = bRow + (uint32_t)(nb * 1152 + kh * 64);
                LDSM4(bh[0], bh[1], bh[2], bh[3], ba);
                LDSM4(bl[0], bl[1], bl[2], bl[3], ba + 9216);
                MMA(acc[nb][0], acc[nb][1], acc[nb][2], acc[nb][3],
                    ah[0], ah[1], ah[2], ah[3], bh[0], bh[1]);
                MMA(acc[nb][0], acc[nb][1], acc[nb][2], acc[nb][3],
                    ah[4], ah[5], ah[6], ah[7], bh[2], bh[3]);
                MMA(acc[nb][0], acc[nb][1], acc[nb][2], acc[nb][3],
                    ah[0], ah[1], ah[2], ah[3], bl[0], bl[1]);
                MMA(acc[nb][0], acc[nb][1], acc[nb][2], acc[nb][3],
                    ah[4], ah[5], ah[6], ah[7], bl[2], bl[3]);
                MMA(acc[nb][0], acc[nb][1], acc[nb][2], acc[nb][3],
                    al[0], al[1], al[2], al[3], bh[0], bh[1]);
                MMA(acc[nb][0], acc[nb][1], acc[nb][2], acc[nb][3],
                    al[4], al[5], al[6], al[7], bh[2], bh[3]);
            }
        }
#pragma unroll
        for (int nb = 0; nb < 8; nb++)
#pragma unroll
            for (int j = 0; j < 4; j++)
                best[nb][j] = fmaxf(best[nb][j], acc[nb][j]);
        __syncthreads();
    }

    // transpose through smem (reuse A region), then coalesced channel-major store
    float* sTr = (float*)(smc + EA_H);   // [128][66]
    {
        int pr0 = wm + (ln >> 2), pr1 = pr0 + 8;
        int cx = (ln & 3) << 1;
#pragma unroll
        for (int nb = 0; nb < 8; nb++) {
            int ch = nb * 8 + cx;
            *(float2*)(sTr + pr0 * 66 + ch) = make_float2(best[nb][0], best[nb][1]);
            *(float2*)(sTr + pr1 * 66 + ch) = make_float2(best[nb][2], best[nb][3]);
        }
    }
    __syncthreads();
#pragma unroll
    for (int i = 0; i < 32; i++) {
        int e = t + i * 256;
        int o = e >> 7, pix = e & 127;
        float v = sTr[pix * 66 + o] + sB2[o];
        size_t idx = (((size_t)(b * 64 + o)) << 16) + (pl + pix);
        if (add_res) v += xres[idx];
        out[idx] = v;
    }
}

// ---------------------------------------------------------------------------
extern "C" void kernel_launch(void* const* d_in, const int* in_sizes, int n_in,
                              void* d_out, int out_size) {
    const float* x     = (const float*)d_in[0];
    const float* r     = (const float*)d_in[1];
    const float* n1_w  = (const float*)d_in[2];
    const float* n1_b  = (const float*)d_in[3];
    const float* c1_w1 = (const float*)d_in[4];
    const float* c1_b1 = (const float*)d_in[5];
    const float* c1_w2 = (const float*)d_in[6];
    const float* c1_b2 = (const float*)d_in[7];
    const float* n2_w  = (const float*)d_in[8];
    const float* n2_b  = (const float*)d_in[9];
    const float* c2_w1 = (const float*)d_in[10];
    const float* c2_b1 = (const float*)d_in[11];
    const float* c2_w2 = (const float*)d_in[12];
    const float* c2_b2 = (const float*)d_in[13];
    float* out = (float*)d_out;

    cudaFuncSetAttribute(gemm_mm_kernel,
                         cudaFuncAttributeMaxDynamicSharedMemorySize, G_SZ);
    cudaFuncSetAttribute(edge_mm_kernel,
                         cudaFuncAttributeMaxDynamicSharedMemorySize, E_SZ);

    gn_part_kernel<<<1024, 256>>>(x);
    gn_fin_kernel<<<1, 128>>>();
    gemm_mm_kernel<<<2048, 256, G_SZ>>>(x, r, c1_w1, c1_b1, n1_w, n1_b);
    edge_mm_kernel<<<2048, 256, E_SZ>>>(r, c1_w1, c1_w2, c1_b2, nullptr, out, 0);

    gn_part_kernel<<<1024, 256>>>(out);
    gn_fin_kernel<<<1, 128>>>();
    gemm_mm_kernel<<<2048, 256, G_SZ>>>(out, r, c2_w1, c2_b1, n2_w, n2_b);
    edge_mm_kernel<<<2048, 256, E_SZ>>>(r, c2_w1, c2_w2, c2_b2, x, out, 1);
}

// round 8
// speedup vs baseline: 1.1606x; 1.0211x over previous
#include <cuda_runtime.h>
#include <cuda_bf16.h>
#include <cstdint>

#define NPIX 262144
#define AZI_C 0.006135923151542565f
#define INC_C 0.008267349088394194f

// scratch (device globals; no runtime alloc)
__device__ float g_UT[(size_t)NPIX * 64];   // pixel-major U  [pix][64]
__device__ float g_VT[(size_t)NPIX * 64];   // pixel-major V' [pix][64]
__device__ float g_mean[128], g_rstd[128];
__device__ float2 g_part[1024];

// ---------------- helpers ----------------
__device__ __forceinline__ uint32_t smem_u32(const void* p) {
    uint32_t a;
    asm("{ .reg .u64 t; cvta.to.shared.u64 t, %1; cvt.u32.u64 %0, t; }" : "=r"(a) : "l"(p));
    return a;
}
#define LDSM4(r0, r1, r2, r3, a) \
    asm volatile("ldmatrix.sync.aligned.m8n8.x4.shared.b16 {%0,%1,%2,%3}, [%4];" \
        : "=r"(r0), "=r"(r1), "=r"(r2), "=r"(r3) : "r"(a))
#define MMA(c0, c1, c2, c3, a0, a1, a2, a3, b0, b1) \
    asm volatile("mma.sync.aligned.m16n8k16.row.col.f32.bf16.bf16.f32 " \
        "{%0,%1,%2,%3},{%4,%5,%6,%7},{%8,%9},{%0,%1,%2,%3};" \
        : "+f"(c0), "+f"(c1), "+f"(c2), "+f"(c3) \
        : "r"(a0), "r"(a1), "r"(a2), "r"(a3), "r"(b0), "r"(b1))

__device__ __forceinline__ void split2(float a, float b, uint32_t& h, uint32_t& l) {
    __nv_bfloat162 hb = __floats2bfloat162_rn(a, b);
    float fa = __low2float(hb), fb = __high2float(hb);
    __nv_bfloat162 lb = __floats2bfloat162_rn(a - fa, b - fb);
    h = *reinterpret_cast<uint32_t*>(&hb);
    l = *reinterpret_cast<uint32_t*>(&lb);
}
// swizzled tile addressing: pitch 128B, chunk = 16B unit
__device__ __forceinline__ uint32_t swadr(int row, int chunk) {
    return (uint32_t)(row * 128 + ((chunk ^ (row & 7)) << 4));
}

// ---------------- GroupNorm stats, two-phase ----------------
__global__ void gn_part_kernel(const float* __restrict__ in) {
    int c = blockIdx.x, t = threadIdx.x;
    const float4* base = reinterpret_cast<const float4*>(in + (size_t)c * 16384);
    float s = 0.f, q = 0.f;
    for (int i = t; i < 4096; i += 256) {
        float4 v = base[i];
        s += (v.x + v.y) + (v.z + v.w);
        q += (v.x * v.x + v.y * v.y) + (v.z * v.z + v.w * v.w);
    }
    __shared__ float rs[256], rq[256];
    rs[t] = s; rq[t] = q;
    __syncthreads();
    for (int off = 128; off > 0; off >>= 1) {
        if (t < off) { rs[t] += rs[t + off]; rq[t] += rq[t + off]; }
        __syncthreads();
    }
    if (t == 0) g_part[c] = make_float2(rs[0], rq[0]);
}
__global__ void gn_fin_kernel() {
    int t = threadIdx.x;
    if (t < 128) {
        float s = 0.f, q = 0.f;
#pragma unroll
        for (int i = 0; i < 8; i++) { float2 p = g_part[t * 8 + i]; s += p.x; q += p.y; }
        float m = s * (1.f / 131072.f);
        g_mean[t] = m;
        g_rstd[t] = rsqrtf(q * (1.f / 131072.f) - m * m + 1e-6f);
    }
}

// ---------------- GEMM1: U,V' = relu(gn(x)) @ [Wa;Wb]^T via mma.sync ----------------
// swizzled tiles: A [128p][64k], B [128n][64k]
#define GA_H 0
#define GA_L 16384
#define GB_H 32768
#define GB_L 49152
#define G_CF 65536
#define G_SZ 66560

__global__ __launch_bounds__(256, 2) void gemm_mm_kernel(
    const float* __restrict__ xin, const float* __restrict__ r,
    const float* __restrict__ w1, const float* __restrict__ b1,
    const float* __restrict__ gnw, const float* __restrict__ gnb)
{
    extern __shared__ char smc[];
    uint32_t sb = smem_u32(smc);
    float* scf  = (float*)(smc + G_CF);
    float* bif  = scf + 64;
    float* b1f  = scf + 128;
    float* wp0f = scf + 192;

    int t = threadIdx.x, wid = t >> 5, ln = t & 31;
    int p0 = blockIdx.x << 7;
    int b = p0 >> 16, pl = p0 & 65535;

    if (t < 64) {
        int grp = (b << 5) + (t >> 1);
        float sc = g_rstd[grp] * gnw[t];
        scf[t]  = sc;
        bif[t]  = gnb[t] - g_mean[grp] * sc;
        b1f[t]  = b1[t];
        wp0f[t] = w1[t * 131 + 128];
    }
    // B = [Wa;Wb] swizzled
    for (int e = t; e < 8192; e += 256) {
        int n = e >> 6, k = e & 63;
        float v = (n < 64) ? w1[n * 131 + k] : w1[(n - 64) * 131 + 64 + k];
        __nv_bfloat16 h = __float2bfloat16(v);
        __nv_bfloat16 l = __float2bfloat16(v - __bfloat162float(h));
        uint32_t off = swadr(n, k >> 3) + (k & 7) * 2;
        *(__nv_bfloat16*)(smc + GB_H + off) = h;
        *(__nv_bfloat16*)(smc + GB_L + off) = l;
    }
    {
        int p = t & 127, co = (t >> 7) << 5;
        const float* xb = xin + (((size_t)(b * 64 + co)) << 16) + pl + p;
#pragma unroll
        for (int kc = 0; kc < 4; kc++) {
            float xv[8];
#pragma unroll
            for (int i = 0; i < 8; i++) {
                int k = co + kc * 8 + i;
                float raw = xb[((size_t)(kc * 8 + i)) << 16];
                xv[i] = fmaxf(fmaf(raw, scf[k], bif[k]), 0.f);
            }
            uint32_t h0, l0, h1, l1, h2, l2, h3, l3;
            split2(xv[0], xv[1], h0, l0);
            split2(xv[2], xv[3], h1, l1);
            split2(xv[4], xv[5], h2, l2);
            split2(xv[6], xv[7], h3, l3);
            uint32_t off = swadr(p, (co >> 3) + kc);
            *(uint4*)(smc + GA_H + off) = make_uint4(h0, h1, h2, h3);
            *(uint4*)(smc + GA_L + off) = make_uint4(l0, l1, l2, l3);
        }
    }
    __syncthreads();

    int wm = wid << 4;
    float acc[16][4];
#pragma unroll
    for (int nb = 0; nb < 16; nb++)
#pragma unroll
        for (int j = 0; j < 4; j++) acc[nb][j] = 0.f;

#pragma unroll
    for (int kh = 0; kh < 2; kh++) {
        uint32_t ah[8], al[8];
        {
            int row = wm + (ln & 15);
            int c0 = kh * 4 + (ln >> 4);
            uint32_t ad0 = sb + GA_H + swadr(row, c0);
            uint32_t ad1 = sb + GA_H + swadr(row, c0 + 2);
            LDSM4(ah[0], ah[1], ah[2], ah[3], ad0);
            LDSM4(ah[4], ah[5], ah[6], ah[7], ad1);
            LDSM4(al[0], al[1], al[2], al[3], ad0 + 16384);
            LDSM4(al[4], al[5], al[6], al[7], ad1 + 16384);
        }
#pragma unroll
        for (int nb = 0; nb < 16; nb++) {
            int brow = nb * 8 + (ln & 7);
            int bc = kh * 4 + (ln >> 3);
            uint32_t bad = sb + GB_H + swadr(brow, bc);
            uint32_t bh[4], bl[4];
            LDSM4(bh[0], bh[1], bh[2], bh[3], bad);
            LDSM4(bl[0], bl[1], bl[2], bl[3], bad + 16384);
            MMA(acc[nb][0], acc[nb][1], acc[nb][2], acc[nb][3],
                ah[0], ah[1], ah[2], ah[3], bh[0], bh[1]);
            MMA(acc[nb][0], acc[nb][1], acc[nb][2], acc[nb][3],
                ah[4], ah[5], ah[6], ah[7], bh[2], bh[3]);
            MMA(acc[nb][0], acc[nb][1], acc[nb][2], acc[nb][3],
                ah[0], ah[1], ah[2], ah[3], bl[0], bl[1]);
            MMA(acc[nb][0], acc[nb][1], acc[nb][2], acc[nb][3],
                ah[4], ah[5], ah[6], ah[7], bl[2], bl[3]);
            MMA(acc[nb][0], acc[nb][1], acc[nb][2], acc[nb][3],
                al[0], al[1], al[2], al[3], bh[0], bh[1]);
            MMA(acc[nb][0], acc[nb][1], acc[nb][2], acc[nb][3],
                al[4], al[5], al[6], al[7], bh[2], bh[3]);
        }
    }

    int pr0 = wm + (ln >> 2), pr1 = pr0 + 8;
    int cx = (ln & 3) << 1;
    size_t gp0 = (size_t)((b << 16) + pl + pr0);
    size_t gp1 = (size_t)((b << 16) + pl + pr1);
    float r0 = r[gp0], r1 = r[gp1];
#pragma unroll
    for (int nb = 0; nb < 16; nb++) {
        if (nb < 8) {
            int ch = nb * 8 + cx;
            *(float2*)(g_UT + gp0 * 64 + ch) = make_float2(acc[nb][0], acc[nb][1]);
            *(float2*)(g_UT + gp1 * 64 + ch) = make_float2(acc[nb][2], acc[nb][3]);
        } else {
            int ch = (nb - 8) * 8 + cx;
            float bb0 = b1f[ch], bb1 = b1f[ch + 1];
            float w0 = wp0f[ch], w1v = wp0f[ch + 1];
            *(float2*)(g_VT + gp0 * 64 + ch) =
                make_float2(acc[nb][0] + bb0 - r0 * w0, acc[nb][1] + bb1 - r0 * w1v);
            *(float2*)(g_VT + gp1 * 64 + ch) =
                make_float2(acc[nb][2] + bb0 - r1 * w0, acc[nb][3] + bb1 - r1 * w1v);
        }
    }
}

// ---------------- Edge-max: swizzled conflict-free tiles, warp tile M32xN32 ----------------
#define EA_H 0
#define EA_L 16384
#define EB_H 32768
#define EB_L 40960
#define E_V  49152     // float [128][65] = 33280 B
#define E_Q  82432     // float [9][64]
#define E_B2 84736     // float [64]
#define E_SZ 84992

__global__ __launch_bounds__(256, 2) void edge_mm_kernel(
    const float* __restrict__ r, const float* __restrict__ w1,
    const float* __restrict__ w2, const float* __restrict__ b2,
    const float* __restrict__ xres, float* __restrict__ out, int add_res)
{
    extern __shared__ char smc[];
    uint32_t sb = smem_u32(smc);
    float* sV  = (float*)(smc + E_V);    // [128][65]
    float* sQ  = (float*)(smc + E_Q);    // [9][64]
    float* sB2 = (float*)(smc + E_B2);   // [64]

    int t = threadIdx.x, wid = t >> 5, ln = t & 31;
    int p0 = blockIdx.x << 7;
    int b = p0 >> 16, pl = p0 & 65535;
    int w0 = pl >> 10, h0 = pl & 1023;

    // B = w2 [o][k] bf16 split, swizzled
    for (int e = t; e < 4096; e += 256) {
        int o = e >> 6, k = e & 63;
        float v = w2[e];
        __nv_bfloat16 h = __float2bfloat16(v);
        __nv_bfloat16 l = __float2bfloat16(v - __bfloat162float(h));
        uint32_t off = swadr(o, k >> 3) + (k & 7) * 2;
        *(__nv_bfloat16*)(smc + EB_H + off) = h;
        *(__nv_bfloat16*)(smc + EB_L + off) = l;
    }
    int p = t & 127, co = (t >> 7) << 5;
    {   // V' tile, pitch 65 (conflict-free scalar access)
        const float4* vb = reinterpret_cast<const float4*>(
            g_VT + ((size_t)((b << 16) + pl + p)) * 64 + co);
        float* d = sV + p * 65 + co;
#pragma unroll
        for (int i = 0; i < 8; i++) {
            float4 v = vb[i];
            d[i * 4 + 0] = v.x; d[i * 4 + 1] = v.y;
            d[i * 4 + 2] = v.z; d[i * 4 + 3] = v.w;
        }
    }
    for (int e = t; e < 576; e += 256) {
        int s = e >> 6, k = e & 63;
        int swv = s / 3 - 1, shv = s % 3 - 1;
        float ca = cosf(swv * AZI_C), sa = sinf(swv * AZI_C);
        float ci = cosf(shv * INC_C), si = sinf(shv * INC_C);
        sQ[e] = ca * ci * w1[k * 131 + 128] + ca * si * w1[k * 131 + 129]
              + sa * w1[k * 131 + 130];
    }
    if (t < 64) sB2[t] = b2[t];
    __syncthreads();

    int wm = (wid & 3) << 5;          // M stripe (32 pixels)
    int wn = (wid >> 2) << 5;         // N half (32 channels)

    float best[2][4][4];
#pragma unroll
    for (int m = 0; m < 2; m++)
#pragma unroll
        for (int nb = 0; nb < 4; nb++)
#pragma unroll
            for (int j = 0; j < 4; j++) best[m][nb][j] = -1e30f;

    for (int s = 0; s < 9; s++) {
        int swv = s / 3 - 1, shv = s % 3 - 1;
        int wsrc = (w0 - swv) & 63;
        size_t rowb = ((size_t)(b << 16)) + ((size_t)wsrc << 10);
        // A build: t_s = relu(U_s + V' + r_s*q), swizzled stores
        {
            int hs = (h0 + p - shv) & 1023;
            const float* ub = g_UT + (rowb + hs) * 64 + co;
            float rs = __ldg(r + rowb + hs);
            const float* qv = sQ + s * 64 + co;
            const float* vv = sV + p * 65 + co;
#pragma unroll
            for (int kc = 0; kc < 4; kc++) {
                float4 u0 = *reinterpret_cast<const float4*>(ub + kc * 8);
                float4 u1 = *reinterpret_cast<const float4*>(ub + kc * 8 + 4);
                float uu[8] = {u0.x, u0.y, u0.z, u0.w, u1.x, u1.y, u1.z, u1.w};
                float xv[8];
#pragma unroll
                for (int i = 0; i < 8; i++) {
                    int k = kc * 8 + i;
                    xv[i] = fmaxf(fmaf(rs, qv[k], uu[i] + vv[k]), 0.f);
                }
                uint32_t h0r, l0r, h1r, l1r, h2r, l2r, h3r, l3r;
                split2(xv[0], xv[1], h0r, l0r);
                split2(xv[2], xv[3], h1r, l1r);
                split2(xv[4], xv[5], h2r, l2r);
                split2(xv[6], xv[7], h3r, l3r);
                uint32_t off = swadr(p, (co >> 3) + kc);
                *(uint4*)(smc + EA_H + off) = make_uint4(h0r, h1r, h2r, h3r);
                *(uint4*)(smc + EA_L + off) = make_uint4(l0r, l1r, l2r, l3r);
            }
        }
        __syncthreads();

        float acc[2][4][4];
#pragma unroll
        for (int m = 0; m < 2; m++)
#pragma unroll
            for (int nb = 0; nb < 4; nb++)
#pragma unroll
                for (int j = 0; j < 4; j++) acc[m][nb][j] = 0.f;

#pragma unroll
        for (int kh = 0; kh < 2; kh++) {
            uint32_t ah[2][8], al[2][8];
#pragma unroll
            for (int m = 0; m < 2; m++) {
                int row = wm + m * 16 + (ln & 15);
                int c0 = kh * 4 + (ln >> 4);
                uint32_t ad0 = sb + EA_H + swadr(row, c0);
                uint32_t ad1 = sb + EA_H + swadr(row, c0 + 2);
                LDSM4(ah[m][0], ah[m][1], ah[m][2], ah[m][3], ad0);
                LDSM4(ah[m][4], ah[m][5], ah[m][6], ah[m][7], ad1);
                LDSM4(al[m][0], al[m][1], al[m][2], al[m][3], ad0 + 16384);
                LDSM4(al[m][4], al[m][5], al[m][6], al[m][7], ad1 + 16384);
            }
#pragma unroll
            for (int nb = 0; nb < 4; nb++) {
                int brow = wn + nb * 8 + (ln & 7);
                int bc = kh * 4 + (ln >> 3);
                uint32_t bad = sb + EB_H + swadr(brow, bc);
                uint32_t bh[4], bl[4];
                LDSM4(bh[0], bh[1], bh[2], bh[3], bad);
                LDSM4(bl[0], bl[1], bl[2], bl[3], bad + 8192);
#pragma unroll
                for (int m = 0; m < 2; m++) {
                    MMA(acc[m][nb][0], acc[m][nb][1], acc[m][nb][2], acc[m][nb][3],
                        ah[m][0], ah[m][1], ah[m][2], ah[m][3], bh[0], bh[1]);
                    MMA(acc[m][nb][0], acc[m][nb][1], acc[m][nb][2], acc[m][nb][3],
                        ah[m][4], ah[m][5], ah[m][6], ah[m][7], bh[2], bh[3]);
                    MMA(acc[m][nb][0], acc[m][nb][1], acc[m][nb][2], acc[m][nb][3],
                        ah[m][0], ah[m][1], ah[m][2], ah[m][3], bl[0], bl[1]);
                    MMA(acc[m][nb][0], acc[m][nb][1], acc[m][nb][2], acc[m][nb][3],
                        ah[m][4], ah[m][5], ah[m][6], ah[m][7], bl[2], bl[3]);
                    MMA(acc[m][nb][0], acc[m][nb][1], acc[m][nb][2], acc[m][nb][3],
                        al[m][0], al[m][1], al[m][2], al[m][3], bh[0], bh[1]);
                    MMA(acc[m][nb][0], acc[m][nb][1], acc[m][nb][2], acc[m][nb][3],
                        al[m][4], al[m][5], al[m][6], al[m][7], bh[2], bh[3]);
                }
            }
        }
#pragma unroll
        for (int m = 0; m < 2; m++)
#pragma unroll
            for (int nb = 0; nb < 4; nb++)
#pragma unroll
                for (int j = 0; j < 4; j++)
                    best[m][nb][j] = fmaxf(best[m][nb][j], acc[m][nb][j]);
        __syncthreads();
    }

    // transpose through smem (reuse A region), then coalesced channel-major store
    float* sTr = (float*)(smc + EA_H);   // [128][66]
    {
        int q = ln >> 2, cx = (ln & 3) << 1;
#pragma unroll
        for (int m = 0; m < 2; m++) {
            int pr0 = wm + m * 16 + q, pr1 = pr0 + 8;
#pragma unroll
            for (int nb = 0; nb < 4; nb++) {
                int ch = wn + nb * 8 + cx;
                *(float2*)(sTr + pr0 * 66 + ch) = make_float2(best[m][nb][0], best[m][nb][1]);
                *(float2*)(sTr + pr1 * 66 + ch) = make_float2(best[m][nb][2], best[m][nb][3]);
            }
        }
    }
    __syncthreads();
#pragma unroll
    for (int i = 0; i < 32; i++) {
        int e = t + i * 256;
        int o = e >> 7, pix = e & 127;
        float v = sTr[pix * 66 + o] + sB2[o];
        size_t idx = (((size_t)(b * 64 + o)) << 16) + (pl + pix);
        if (add_res) v += xres[idx];
        out[idx] = v;
    }
}

// ---------------------------------------------------------------------------
extern "C" void kernel_launch(void* const* d_in, const int* in_sizes, int n_in,
                              void* d_out, int out_size) {
    const float* x     = (const float*)d_in[0];
    const float* r     = (const float*)d_in[1];
    const float* n1_w  = (const float*)d_in[2];
    const float* n1_b  = (const float*)d_in[3];
    const float* c1_w1 = (const float*)d_in[4];
    const float* c1_b1 = (const float*)d_in[5];
    const float* c1_w2 = (const float*)d_in[6];
    const float* c1_b2 = (const float*)d_in[7];
    const float* n2_w  = (const float*)d_in[8];
    const float* n2_b  = (const float*)d_in[9];
    const float* c2_w1 = (const float*)d_in[10];
    const float* c2_b1 = (const float*)d_in[11];
    const float* c2_w2 = (const float*)d_in[12];
    const float* c2_b2 = (const float*)d_in[13];
    float* out = (float*)d_out;

    cudaFuncSetAttribute(gemm_mm_kernel,
                         cudaFuncAttributeMaxDynamicSharedMemorySize, G_SZ);
    cudaFuncSetAttribute(edge_mm_kernel,
                         cudaFuncAttributeMaxDynamicSharedMemorySize, E_SZ);

    gn_part_kernel<<<1024, 256>>>(x);
    gn_fin_kernel<<<1, 128>>>();
    gemm_mm_kernel<<<2048, 256, G_SZ>>>(x, r, c1_w1, c1_b1, n1_w, n1_b);
    edge_mm_kernel<<<2048, 256, E_SZ>>>(r, c1_w1, c1_w2, c1_b2, nullptr, out, 0);

    gn_part_kernel<<<1024, 256>>>(out);
    gn_fin_kernel<<<1, 128>>>();
    gemm_mm_kernel<<<2048, 256, G_SZ>>>(out, r, c2_w1, c2_b1, n2_w, n2_b);
    edge_mm_kernel<<<2048, 256, E_SZ>>>(r, c2_w1, c2_w2, c2_b2, x, out, 1);
}

// round 9
// speedup vs baseline: 1.3734x; 1.1834x over previous
#include <cuda_runtime.h>
#include <cuda_bf16.h>
#include <cuda_fp16.h>
#include <cstdint>

#define NPIX 262144
#define AZI_C 0.006135923151542565f
#define INC_C 0.008267349088394194f

// scratch (device globals; no runtime alloc)
__device__ float g_UT[(size_t)NPIX * 64];   // pixel-major U  [pix][64]
__device__ float g_VT[(size_t)NPIX * 64];   // pixel-major V' [pix][64]
__device__ float g_mean[128], g_rstd[128];
__device__ float2 g_part[1024];

// ---------------- helpers ----------------
__device__ __forceinline__ uint32_t smem_u32(const void* p) {
    uint32_t a;
    asm("{ .reg .u64 t; cvta.to.shared.u64 t, %1; cvt.u32.u64 %0, t; }" : "=r"(a) : "l"(p));
    return a;
}
#define LDSM4(r0, r1, r2, r3, a) \
    asm volatile("ldmatrix.sync.aligned.m8n8.x4.shared.b16 {%0,%1,%2,%3}, [%4];" \
        : "=r"(r0), "=r"(r1), "=r"(r2), "=r"(r3) : "r"(a))
#define MMABF(c0, c1, c2, c3, a0, a1, a2, a3, b0, b1) \
    asm volatile("mma.sync.aligned.m16n8k16.row.col.f32.bf16.bf16.f32 " \
        "{%0,%1,%2,%3},{%4,%5,%6,%7},{%8,%9},{%0,%1,%2,%3};" \
        : "+f"(c0), "+f"(c1), "+f"(c2), "+f"(c3) \
        : "r"(a0), "r"(a1), "r"(a2), "r"(a3), "r"(b0), "r"(b1))
#define MMAF16(c0, c1, c2, c3, a0, a1, a2, a3, b0, b1) \
    asm volatile("mma.sync.aligned.m16n8k16.row.col.f32.f16.f16.f32 " \
        "{%0,%1,%2,%3},{%4,%5,%6,%7},{%8,%9},{%0,%1,%2,%3};" \
        : "+f"(c0), "+f"(c1), "+f"(c2), "+f"(c3) \
        : "r"(a0), "r"(a1), "r"(a2), "r"(a3), "r"(b0), "r"(b1))

__device__ __forceinline__ void split2(float a, float b, uint32_t& h, uint32_t& l) {
    __nv_bfloat162 hb = __floats2bfloat162_rn(a, b);
    float fa = __low2float(hb), fb = __high2float(hb);
    __nv_bfloat162 lb = __floats2bfloat162_rn(a - fa, b - fb);
    h = *reinterpret_cast<uint32_t*>(&hb);
    l = *reinterpret_cast<uint32_t*>(&lb);
}
// swizzled tile addressing: pitch 128B, chunk = 16B unit
__device__ __forceinline__ uint32_t swadr(int row, int chunk) {
    return (uint32_t)(row * 128 + ((chunk ^ (row & 7)) << 4));
}

// ---------------- GroupNorm stats, two-phase ----------------
__global__ void gn_part_kernel(const float* __restrict__ in) {
    int c = blockIdx.x, t = threadIdx.x;
    const float4* base = reinterpret_cast<const float4*>(in + (size_t)c * 16384);
    float s = 0.f, q = 0.f;
    for (int i = t; i < 4096; i += 256) {
        float4 v = base[i];
        s += (v.x + v.y) + (v.z + v.w);
        q += (v.x * v.x + v.y * v.y) + (v.z * v.z + v.w * v.w);
    }
    __shared__ float rs[256], rq[256];
    rs[t] = s; rq[t] = q;
    __syncthreads();
    for (int off = 128; off > 0; off >>= 1) {
        if (t < off) { rs[t] += rs[t + off]; rq[t] += rq[t + off]; }
        __syncthreads();
    }
    if (t == 0) g_part[c] = make_float2(rs[0], rq[0]);
}
__global__ void gn_fin_kernel() {
    int t = threadIdx.x;
    if (t < 128) {
        float s = 0.f, q = 0.f;
#pragma unroll
        for (int i = 0; i < 8; i++) { float2 p = g_part[t * 8 + i]; s += p.x; q += p.y; }
        float m = s * (1.f / 131072.f);
        g_mean[t] = m;
        g_rstd[t] = rsqrtf(q * (1.f / 131072.f) - m * m + 1e-6f);
    }
}

// ---------------- GEMM1: U,V' = relu(gn(x)) @ [Wa;Wb]^T (3-pass bf16, full precision) ----------------
#define GA_H 0
#define GA_L 16384
#define GB_H 32768
#define GB_L 49152
#define G_CF 65536
#define G_SZ 66560

__global__ __launch_bounds__(256, 2) void gemm_mm_kernel(
    const float* __restrict__ xin, const float* __restrict__ r,
    const float* __restrict__ w1, const float* __restrict__ b1,
    const float* __restrict__ gnw, const float* __restrict__ gnb)
{
    extern __shared__ char smc[];
    uint32_t sb = smem_u32(smc);
    float* scf  = (float*)(smc + G_CF);
    float* bif  = scf + 64;
    float* b1f  = scf + 128;
    float* wp0f = scf + 192;

    int t = threadIdx.x, wid = t >> 5, ln = t & 31;
    int p0 = blockIdx.x << 7;
    int b = p0 >> 16, pl = p0 & 65535;

    if (t < 64) {
        int grp = (b << 5) + (t >> 1);
        float sc = g_rstd[grp] * gnw[t];
        scf[t]  = sc;
        bif[t]  = gnb[t] - g_mean[grp] * sc;
        b1f[t]  = b1[t];
        wp0f[t] = w1[t * 131 + 128];
    }
    for (int e = t; e < 8192; e += 256) {
        int n = e >> 6, k = e & 63;
        float v = (n < 64) ? w1[n * 131 + k] : w1[(n - 64) * 131 + 64 + k];
        __nv_bfloat16 h = __float2bfloat16(v);
        __nv_bfloat16 l = __float2bfloat16(v - __bfloat162float(h));
        uint32_t off = swadr(n, k >> 3) + (k & 7) * 2;
        *(__nv_bfloat16*)(smc + GB_H + off) = h;
        *(__nv_bfloat16*)(smc + GB_L + off) = l;
    }
    {
        int p = t & 127, co = (t >> 7) << 5;
        const float* xb = xin + (((size_t)(b * 64 + co)) << 16) + pl + p;
#pragma unroll
        for (int kc = 0; kc < 4; kc++) {
            float xv[8];
#pragma unroll
            for (int i = 0; i < 8; i++) {
                int k = co + kc * 8 + i;
                float raw = xb[((size_t)(kc * 8 + i)) << 16];
                xv[i] = fmaxf(fmaf(raw, scf[k], bif[k]), 0.f);
            }
            uint32_t h0, l0, h1, l1, h2, l2, h3, l3;
            split2(xv[0], xv[1], h0, l0);
            split2(xv[2], xv[3], h1, l1);
            split2(xv[4], xv[5], h2, l2);
            split2(xv[6], xv[7], h3, l3);
            uint32_t off = swadr(p, (co >> 3) + kc);
            *(uint4*)(smc + GA_H + off) = make_uint4(h0, h1, h2, h3);
            *(uint4*)(smc + GA_L + off) = make_uint4(l0, l1, l2, l3);
        }
    }
    __syncthreads();

    int wm = wid << 4;
    float acc[16][4];
#pragma unroll
    for (int nb = 0; nb < 16; nb++)
#pragma unroll
        for (int j = 0; j < 4; j++) acc[nb][j] = 0.f;

#pragma unroll
    for (int kh = 0; kh < 2; kh++) {
        uint32_t ah[8], al[8];
        {
            int row = wm + (ln & 15);
            int c0 = kh * 4 + (ln >> 4);
            uint32_t ad0 = sb + GA_H + swadr(row, c0);
            uint32_t ad1 = sb + GA_H + swadr(row, c0 + 2);
            LDSM4(ah[0], ah[1], ah[2], ah[3], ad0);
            LDSM4(ah[4], ah[5], ah[6], ah[7], ad1);
            LDSM4(al[0], al[1], al[2], al[3], ad0 + 16384);
            LDSM4(al[4], al[5], al[6], al[7], ad1 + 16384);
        }
#pragma unroll
        for (int nb = 0; nb < 16; nb++) {
            int brow = nb * 8 + (ln & 7);
            int bc = kh * 4 + (ln >> 3);
            uint32_t bad = sb + GB_H + swadr(brow, bc);
            uint32_t bh[4], bl[4];
            LDSM4(bh[0], bh[1], bh[2], bh[3], bad);
            LDSM4(bl[0], bl[1], bl[2], bl[3], bad + 16384);
            MMABF(acc[nb][0], acc[nb][1], acc[nb][2], acc[nb][3],
                  ah[0], ah[1], ah[2], ah[3], bh[0], bh[1]);
            MMABF(acc[nb][0], acc[nb][1], acc[nb][2], acc[nb][3],
                  ah[4], ah[5], ah[6], ah[7], bh[2], bh[3]);
            MMABF(acc[nb][0], acc[nb][1], acc[nb][2], acc[nb][3],
                  ah[0], ah[1], ah[2], ah[3], bl[0], bl[1]);
            MMABF(acc[nb][0], acc[nb][1], acc[nb][2], acc[nb][3],
                  ah[4], ah[5], ah[6], ah[7], bl[2], bl[3]);
            MMABF(acc[nb][0], acc[nb][1], acc[nb][2], acc[nb][3],
                  al[0], al[1], al[2], al[3], bh[0], bh[1]);
            MMABF(acc[nb][0], acc[nb][1], acc[nb][2], acc[nb][3],
                  al[4], al[5], al[6], al[7], bh[2], bh[3]);
        }
    }

    int pr0 = wm + (ln >> 2), pr1 = pr0 + 8;
    int cx = (ln & 3) << 1;
    size_t gp0 = (size_t)((b << 16) + pl + pr0);
    size_t gp1 = (size_t)((b << 16) + pl + pr1);
    float r0 = r[gp0], r1 = r[gp1];
#pragma unroll
    for (int nb = 0; nb < 16; nb++) {
        if (nb < 8) {
            int ch = nb * 8 + cx;
            *(float2*)(g_UT + gp0 * 64 + ch) = make_float2(acc[nb][0], acc[nb][1]);
            *(float2*)(g_UT + gp1 * 64 + ch) = make_float2(acc[nb][2], acc[nb][3]);
        } else {
            int ch = (nb - 8) * 8 + cx;
            float bb0 = b1f[ch], bb1 = b1f[ch + 1];
            float w0 = wp0f[ch], w1v = wp0f[ch + 1];
            *(float2*)(g_VT + gp0 * 64 + ch) =
                make_float2(acc[nb][0] + bb0 - r0 * w0, acc[nb][1] + bb1 - r0 * w1v);
            *(float2*)(g_VT + gp1 * 64 + ch) =
                make_float2(acc[nb][2] + bb0 - r1 * w0, acc[nb][3] + bb1 - r1 * w1v);
        }
    }
}

// ---------------- Edge-max: single-pass fp16, vectorized V/q, swizzled tiles ----------------
// EA halfs [128][64] swizzled (16KB) | EB halfs [64][64] swizzled (8KB)
// sV float [128][68] | sQ float [9][64] | sB2 float [64]
#define EA   0
#define EB   16384
#define E_V  24576
#define E_Q  59392
#define E_B2 61696
#define E_SZ 61952

__global__ __launch_bounds__(256, 2) void edge_mm_kernel(
    const float* __restrict__ r, const float* __restrict__ w1,
    const float* __restrict__ w2, const float* __restrict__ b2,
    const float* __restrict__ xres, float* __restrict__ out, int add_res)
{
    extern __shared__ char smc[];
    uint32_t sb = smem_u32(smc);
    float* sV  = (float*)(smc + E_V);    // [128][68]
    float* sQ  = (float*)(smc + E_Q);    // [9][64]
    float* sB2 = (float*)(smc + E_B2);   // [64]

    int t = threadIdx.x, wid = t >> 5, ln = t & 31;
    int p0 = blockIdx.x << 7;
    int b = p0 >> 16, pl = p0 & 65535;
    int w0 = pl >> 10, h0 = pl & 1023;

    // B = w2 [o][k] fp16, swizzled
    for (int e = t; e < 4096; e += 256) {
        int o = e >> 6, k = e & 63;
        uint32_t off = swadr(o, k >> 3) + (k & 7) * 2;
        *(__half*)(smc + EB + off) = __float2half_rn(w2[e]);
    }
    int p = t & 127, co = (t >> 7) << 5;
    {   // V' tile, pitch 68 floats (float4, conflict-free)
        const float4* vb = reinterpret_cast<const float4*>(
            g_VT + ((size_t)((b << 16) + pl + p)) * 64 + co);
        float4* d = reinterpret_cast<float4*>(sV + p * 68 + co);
#pragma unroll
        for (int i = 0; i < 8; i++) d[i] = vb[i];
    }
    for (int e = t; e < 576; e += 256) {
        int s = e >> 6, k = e & 63;
        int swv = s / 3 - 1, shv = s % 3 - 1;
        float ca = cosf(swv * AZI_C), sa = sinf(swv * AZI_C);
        float ci = cosf(shv * INC_C), si = sinf(shv * INC_C);
        sQ[e] = ca * ci * w1[k * 131 + 128] + ca * si * w1[k * 131 + 129]
              + sa * w1[k * 131 + 130];
    }
    if (t < 64) sB2[t] = b2[t];
    __syncthreads();

    int wm = (wid & 3) << 5;          // M stripe (32 pixels)
    int wn = (wid >> 2) << 5;         // N half (32 channels)

    float best[2][4][4];
#pragma unroll
    for (int m = 0; m < 2; m++)
#pragma unroll
        for (int nb = 0; nb < 4; nb++)
#pragma unroll
            for (int j = 0; j < 4; j++) best[m][nb][j] = -1e30f;

    for (int s = 0; s < 9; s++) {
        int swv = s / 3 - 1, shv = s % 3 - 1;
        int wsrc = (w0 - swv) & 63;
        size_t rowb = ((size_t)(b << 16)) + ((size_t)wsrc << 10);
        // A build: t_s = relu(U_s + V' + r_s*q) -> fp16 single
        {
            int hs = (h0 + p - shv) & 1023;
            const float4* ub = reinterpret_cast<const float4*>(
                g_UT + (rowb + hs) * 64 + co);
            float rs = __ldg(r + rowb + hs);
            const float4* qv = reinterpret_cast<const float4*>(sQ + s * 64 + co);
            const float4* vv = reinterpret_cast<const float4*>(sV + p * 68 + co);
#pragma unroll
            for (int kc = 0; kc < 4; kc++) {
                float4 u0 = ub[kc * 2],  u1 = ub[kc * 2 + 1];
                float4 v0 = vv[kc * 2],  v1 = vv[kc * 2 + 1];
                float4 q0 = qv[kc * 2],  q1 = qv[kc * 2 + 1];
                float x0 = fmaxf(fmaf(rs, q0.x, u0.x + v0.x), 0.f);
                float x1 = fmaxf(fmaf(rs, q0.y, u0.y + v0.y), 0.f);
                float x2 = fmaxf(fmaf(rs, q0.z, u0.z + v0.z), 0.f);
                float x3 = fmaxf(fmaf(rs, q0.w, u0.w + v0.w), 0.f);
                float x4 = fmaxf(fmaf(rs, q1.x, u1.x + v1.x), 0.f);
                float x5 = fmaxf(fmaf(rs, q1.y, u1.y + v1.y), 0.f);
                float x6 = fmaxf(fmaf(rs, q1.z, u1.z + v1.z), 0.f);
                float x7 = fmaxf(fmaf(rs, q1.w, u1.w + v1.w), 0.f);
                __half2 p0h = __floats2half2_rn(x0, x1);
                __half2 p1h = __floats2half2_rn(x2, x3);
                __half2 p2h = __floats2half2_rn(x4, x5);
                __half2 p3h = __floats2half2_rn(x6, x7);
                uint32_t off = swadr(p, (co >> 3) + kc);
                *(uint4*)(smc + EA + off) = make_uint4(
                    *reinterpret_cast<uint32_t*>(&p0h), *reinterpret_cast<uint32_t*>(&p1h),
                    *reinterpret_cast<uint32_t*>(&p2h), *reinterpret_cast<uint32_t*>(&p3h));
            }
        }
        __syncthreads();

        float acc[2][4][4];
#pragma unroll
        for (int m = 0; m < 2; m++)
#pragma unroll
            for (int nb = 0; nb < 4; nb++)
#pragma unroll
                for (int j = 0; j < 4; j++) acc[m][nb][j] = 0.f;

#pragma unroll
        for (int kh = 0; kh < 2; kh++) {
            uint32_t ah[2][8];
#pragma unroll
            for (int m = 0; m < 2; m++) {
                int row = wm + m * 16 + (ln & 15);
                int c0 = kh * 4 + (ln >> 4);
                LDSM4(ah[m][0], ah[m][1], ah[m][2], ah[m][3], sb + EA + swadr(row, c0));
                LDSM4(ah[m][4], ah[m][5], ah[m][6], ah[m][7], sb + EA + swadr(row, c0 + 2));
            }
#pragma unroll
            for (int nb = 0; nb < 4; nb++) {
                int brow = wn + nb * 8 + (ln & 7);
                int bc = kh * 4 + (ln >> 3);
                uint32_t bh[4];
                LDSM4(bh[0], bh[1], bh[2], bh[3], sb + EB + swadr(brow, bc));
#pragma unroll
                for (int m = 0; m < 2; m++) {
                    MMAF16(acc[m][nb][0], acc[m][nb][1], acc[m][nb][2], acc[m][nb][3],
                           ah[m][0], ah[m][1], ah[m][2], ah[m][3], bh[0], bh[1]);
                    MMAF16(acc[m][nb][0], acc[m][nb][1], acc[m][nb][2], acc[m][nb][3],
                           ah[m][4], ah[m][5], ah[m][6], ah[m][7], bh[2], bh[3]);
                }
            }
        }
#pragma unroll
        for (int m = 0; m < 2; m++)
#pragma unroll
            for (int nb = 0; nb < 4; nb++)
#pragma unroll
                for (int j = 0; j < 4; j++)
                    best[m][nb][j] = fmaxf(best[m][nb][j], acc[m][nb][j]);
        __syncthreads();
    }

    // transpose through smem (reuse EA/EB/sV region), coalesced channel-major store
    float* sTr = (float*)smc;    // [128][66]
    {
        int q = ln >> 2, cx = (ln & 3) << 1;
#pragma unroll
        for (int m = 0; m < 2; m++) {
            int pr0 = wm + m * 16 + q, pr1 = pr0 + 8;
#pragma unroll
            for (int nb = 0; nb < 4; nb++) {
                int ch = wn + nb * 8 + cx;
                *(float2*)(sTr + pr0 * 66 + ch) = make_float2(best[m][nb][0], best[m][nb][1]);
                *(float2*)(sTr + pr1 * 66 + ch) = make_float2(best[m][nb][2], best[m][nb][3]);
            }
        }
    }
    __syncthreads();
#pragma unroll
    for (int i = 0; i < 32; i++) {
        int e = t + i * 256;
        int o = e >> 7, pix = e & 127;
        float v = sTr[pix * 66 + o] + sB2[o];
        size_t idx = (((size_t)(b * 64 + o)) << 16) + (pl + pix);
        if (add_res) v += xres[idx];
        out[idx] = v;
    }
}

// ---------------------------------------------------------------------------
extern "C" void kernel_launch(void* const* d_in, const int* in_sizes, int n_in,
                              void* d_out, int out_size) {
    const float* x     = (const float*)d_in[0];
    const float* r     = (const float*)d_in[1];
    const float* n1_w  = (const float*)d_in[2];
    const float* n1_b  = (const float*)d_in[3];
    const float* c1_w1 = (const float*)d_in[4];
    const float* c1_b1 = (const float*)d_in[5];
    const float* c1_w2 = (const float*)d_in[6];
    const float* c1_b2 = (const float*)d_in[7];
    const float* n2_w  = (const float*)d_in[8];
    const float* n2_b  = (const float*)d_in[9];
    const float* c2_w1 = (const float*)d_in[10];
    const float* c2_b1 = (const float*)d_in[11];
    const float* c2_w2 = (const float*)d_in[12];
    const float* c2_b2 = (const float*)d_in[13];
    float* out = (float*)d_out;

    cudaFuncSetAttribute(gemm_mm_kernel,
                         cudaFuncAttributeMaxDynamicSharedMemorySize, G_SZ);
    cudaFuncSetAttribute(edge_mm_kernel,
                         cudaFuncAttributeMaxDynamicSharedMemorySize, E_SZ);

    gn_part_kernel<<<1024, 256>>>(x);
    gn_fin_kernel<<<1, 128>>>();
    gemm_mm_kernel<<<2048, 256, G_SZ>>>(x, r, c1_w1, c1_b1, n1_w, n1_b);
    edge_mm_kernel<<<2048, 256, E_SZ>>>(r, c1_w1, c1_w2, c1_b2, nullptr, out, 0);

    gn_part_kernel<<<1024, 256>>>(out);
    gn_fin_kernel<<<1, 128>>>();
    gemm_mm_kernel<<<2048, 256, G_SZ>>>(out, r, c2_w1, c2_b1, n2_w, n2_b);
    edge_mm_kernel<<<2048, 256, E_SZ>>>(r, c2_w1, c2_w2, c2_b2, x, out, 1);
}

// round 10
// speedup vs baseline: 1.8643x; 1.3574x over previous
#include <cuda_runtime.h>
#include <cuda_bf16.h>
#include <cuda_fp16.h>
#include <cstdint>

#define NPIX 262144
#define AZI_C 0.006135923151542565f
#define INC_C 0.008267349088394194f

// scratch (device globals; no runtime alloc)
__device__ __half g_UTh[(size_t)NPIX * 64];   // pixel-major U  [pix][64] fp16
__device__ __half g_VTh[(size_t)NPIX * 64];   // pixel-major V' [pix][64] fp16
__device__ float g_mean[128], g_rstd[128];
__device__ float2 g_part[1024];

// ---------------- helpers ----------------
__device__ __forceinline__ uint32_t smem_u32(const void* p) {
    uint32_t a;
    asm("{ .reg .u64 t; cvta.to.shared.u64 t, %1; cvt.u32.u64 %0, t; }" : "=r"(a) : "l"(p));
    return a;
}
#define LDSM4(r0, r1, r2, r3, a) \
    asm volatile("ldmatrix.sync.aligned.m8n8.x4.shared.b16 {%0,%1,%2,%3}, [%4];" \
        : "=r"(r0), "=r"(r1), "=r"(r2), "=r"(r3) : "r"(a))
#define MMABF(c0, c1, c2, c3, a0, a1, a2, a3, b0, b1) \
    asm volatile("mma.sync.aligned.m16n8k16.row.col.f32.bf16.bf16.f32 " \
        "{%0,%1,%2,%3},{%4,%5,%6,%7},{%8,%9},{%0,%1,%2,%3};" \
        : "+f"(c0), "+f"(c1), "+f"(c2), "+f"(c3) \
        : "r"(a0), "r"(a1), "r"(a2), "r"(a3), "r"(b0), "r"(b1))
#define MMAF16(c0, c1, c2, c3, a0, a1, a2, a3, b0, b1) \
    asm volatile("mma.sync.aligned.m16n8k16.row.col.f32.f16.f16.f32 " \
        "{%0,%1,%2,%3},{%4,%5,%6,%7},{%8,%9},{%0,%1,%2,%3};" \
        : "+f"(c0), "+f"(c1), "+f"(c2), "+f"(c3) \
        : "r"(a0), "r"(a1), "r"(a2), "r"(a3), "r"(b0), "r"(b1))

__device__ __forceinline__ void split2(float a, float b, uint32_t& h, uint32_t& l) {
    __nv_bfloat162 hb = __floats2bfloat162_rn(a, b);
    float fa = __low2float(hb), fb = __high2float(hb);
    __nv_bfloat162 lb = __floats2bfloat162_rn(a - fa, b - fb);
    h = *reinterpret_cast<uint32_t*>(&hb);
    l = *reinterpret_cast<uint32_t*>(&lb);
}
// swizzled tile addressing: pitch 128B, chunk = 16B unit
__device__ __forceinline__ uint32_t swadr(int row, int chunk) {
    return (uint32_t)(row * 128 + ((chunk ^ (row & 7)) << 4));
}

// ---------------- GroupNorm stats, two-phase ----------------
__global__ void gn_part_kernel(const float* __restrict__ in) {
    int c = blockIdx.x, t = threadIdx.x;
    const float4* base = reinterpret_cast<const float4*>(in + (size_t)c * 16384);
    float s = 0.f, q = 0.f;
    for (int i = t; i < 4096; i += 256) {
        float4 v = base[i];
        s += (v.x + v.y) + (v.z + v.w);
        q += (v.x * v.x + v.y * v.y) + (v.z * v.z + v.w * v.w);
    }
    __shared__ float rs[256], rq[256];
    rs[t] = s; rq[t] = q;
    __syncthreads();
    for (int off = 128; off > 0; off >>= 1) {
        if (t < off) { rs[t] += rs[t + off]; rq[t] += rq[t + off]; }
        __syncthreads();
    }
    if (t == 0) g_part[c] = make_float2(rs[0], rq[0]);
}
__global__ void gn_fin_kernel() {
    int t = threadIdx.x;
    if (t < 128) {
        float s = 0.f, q = 0.f;
#pragma unroll
        for (int i = 0; i < 8; i++) { float2 p = g_part[t * 8 + i]; s += p.x; q += p.y; }
        float m = s * (1.f / 131072.f);
        g_mean[t] = m;
        g_rstd[t] = rsqrtf(q * (1.f / 131072.f) - m * m + 1e-6f);
    }
}

// ---------------- GEMM1: U,V' = relu(gn(x)) @ [Wa;Wb]^T (3-pass bf16) ----------------
#define GA_H 0
#define GA_L 16384
#define GB_H 32768
#define GB_L 49152
#define G_CF 65536
#define G_SZ 66560

__global__ __launch_bounds__(256, 2) void gemm_mm_kernel(
    const float* __restrict__ xin, const float* __restrict__ r,
    const float* __restrict__ w1, const float* __restrict__ b1,
    const float* __restrict__ gnw, const float* __restrict__ gnb)
{
    extern __shared__ char smc[];
    uint32_t sb = smem_u32(smc);
    float* scf  = (float*)(smc + G_CF);
    float* bif  = scf + 64;
    float* b1f  = scf + 128;
    float* wp0f = scf + 192;

    int t = threadIdx.x, wid = t >> 5, ln = t & 31;
    int p0 = blockIdx.x << 7;
    int b = p0 >> 16, pl = p0 & 65535;

    if (t < 64) {
        int grp = (b << 5) + (t >> 1);
        float sc = g_rstd[grp] * gnw[t];
        scf[t]  = sc;
        bif[t]  = gnb[t] - g_mean[grp] * sc;
        b1f[t]  = b1[t];
        wp0f[t] = w1[t * 131 + 128];
    }
    for (int e = t; e < 8192; e += 256) {
        int n = e >> 6, k = e & 63;
        float v = (n < 64) ? w1[n * 131 + k] : w1[(n - 64) * 131 + 64 + k];
        __nv_bfloat16 h = __float2bfloat16(v);
        __nv_bfloat16 l = __float2bfloat16(v - __bfloat162float(h));
        uint32_t off = swadr(n, k >> 3) + (k & 7) * 2;
        *(__nv_bfloat16*)(smc + GB_H + off) = h;
        *(__nv_bfloat16*)(smc + GB_L + off) = l;
    }
    {
        int p = t & 127, co = (t >> 7) << 5;
        const float* xb = xin + (((size_t)(b * 64 + co)) << 16) + pl + p;
#pragma unroll
        for (int kc = 0; kc < 4; kc++) {
            float xv[8];
#pragma unroll
            for (int i = 0; i < 8; i++) {
                int k = co + kc * 8 + i;
                float raw = xb[((size_t)(kc * 8 + i)) << 16];
                xv[i] = fmaxf(fmaf(raw, scf[k], bif[k]), 0.f);
            }
            uint32_t h0, l0, h1, l1, h2, l2, h3, l3;
            split2(xv[0], xv[1], h0, l0);
            split2(xv[2], xv[3], h1, l1);
            split2(xv[4], xv[5], h2, l2);
            split2(xv[6], xv[7], h3, l3);
            uint32_t off = swadr(p, (co >> 3) + kc);
            *(uint4*)(smc + GA_H + off) = make_uint4(h0, h1, h2, h3);
            *(uint4*)(smc + GA_L + off) = make_uint4(l0, l1, l2, l3);
        }
    }
    __syncthreads();

    int wm = wid << 4;
    float acc[16][4];
#pragma unroll
    for (int nb = 0; nb < 16; nb++)
#pragma unroll
        for (int j = 0; j < 4; j++) acc[nb][j] = 0.f;

#pragma unroll
    for (int kh = 0; kh < 2; kh++) {
        uint32_t ah[8], al[8];
        {
            int row = wm + (ln & 15);
            int c0 = kh * 4 + (ln >> 4);
            uint32_t ad0 = sb + GA_H + swadr(row, c0);
            uint32_t ad1 = sb + GA_H + swadr(row, c0 + 2);
            LDSM4(ah[0], ah[1], ah[2], ah[3], ad0);
            LDSM4(ah[4], ah[5], ah[6], ah[7], ad1);
            LDSM4(al[0], al[1], al[2], al[3], ad0 + 16384);
            LDSM4(al[4], al[5], al[6], al[7], ad1 + 16384);
        }
#pragma unroll
        for (int nb = 0; nb < 16; nb++) {
            int brow = nb * 8 + (ln & 7);
            int bc = kh * 4 + (ln >> 3);
            uint32_t bad = sb + GB_H + swadr(brow, bc);
            uint32_t bh[4], bl[4];
            LDSM4(bh[0], bh[1], bh[2], bh[3], bad);
            LDSM4(bl[0], bl[1], bl[2], bl[3], bad + 16384);
            MMABF(acc[nb][0], acc[nb][1], acc[nb][2], acc[nb][3],
                  ah[0], ah[1], ah[2], ah[3], bh[0], bh[1]);
            MMABF(acc[nb][0], acc[nb][1], acc[nb][2], acc[nb][3],
                  ah[4], ah[5], ah[6], ah[7], bh[2], bh[3]);
            MMABF(acc[nb][0], acc[nb][1], acc[nb][2], acc[nb][3],
                  ah[0], ah[1], ah[2], ah[3], bl[0], bl[1]);
            MMABF(acc[nb][0], acc[nb][1], acc[nb][2], acc[nb][3],
                  ah[4], ah[5], ah[6], ah[7], bl[2], bl[3]);
            MMABF(acc[nb][0], acc[nb][1], acc[nb][2], acc[nb][3],
                  al[0], al[1], al[2], al[3], bh[0], bh[1]);
            MMABF(acc[nb][0], acc[nb][1], acc[nb][2], acc[nb][3],
                  al[4], al[5], al[6], al[7], bh[2], bh[3]);
        }
    }

    int pr0 = wm + (ln >> 2), pr1 = pr0 + 8;
    int cx = (ln & 3) << 1;
    size_t gp0 = (size_t)((b << 16) + pl + pr0);
    size_t gp1 = (size_t)((b << 16) + pl + pr1);
    float r0 = r[gp0], r1 = r[gp1];
#pragma unroll
    for (int nb = 0; nb < 16; nb++) {
        if (nb < 8) {
            int ch = nb * 8 + cx;
            *(__half2*)(g_UTh + gp0 * 64 + ch) = __floats2half2_rn(acc[nb][0], acc[nb][1]);
            *(__half2*)(g_UTh + gp1 * 64 + ch) = __floats2half2_rn(acc[nb][2], acc[nb][3]);
        } else {
            int ch = (nb - 8) * 8 + cx;
            float bb0 = b1f[ch], bb1 = b1f[ch + 1];
            float w0 = wp0f[ch], w1v = wp0f[ch + 1];
            *(__half2*)(g_VTh + gp0 * 64 + ch) =
                __floats2half2_rn(acc[nb][0] + bb0 - r0 * w0, acc[nb][1] + bb1 - r0 * w1v);
            *(__half2*)(g_VTh + gp1 * 64 + ch) =
                __floats2half2_rn(acc[nb][2] + bb0 - r1 * w0, acc[nb][3] + bb1 - r1 * w1v);
        }
    }
}

// ---------------- Edge-max: w2 frags hoisted (A=weights M, B=pixels N), fp16 U/V ----------------
// ET t-tile fp16 [128px][64k] swizzled 16KB | EW w2 fp16 [64o][64k] swizzled 8KB
// EV V' fp16 [128][64] swizzled 16KB | EQ float [9][64] | EB2 float[64]
#define ET   0
#define EW   16384
#define EV   24576
#define EQ   40960
#define EB2  43264
#define E_SZ 43520

__global__ __launch_bounds__(256, 2) void edge_mm_kernel(
    const float* __restrict__ r, const float* __restrict__ w1,
    const float* __restrict__ w2, const float* __restrict__ b2,
    const float* __restrict__ xres, float* __restrict__ out, int add_res)
{
    extern __shared__ char smc[];
    uint32_t sb = smem_u32(smc);
    float* sQ  = (float*)(smc + EQ);
    float* sB2 = (float*)(smc + EB2);

    int t = threadIdx.x, wid = t >> 5, ln = t & 31;
    int p0 = blockIdx.x << 7;
    int b = p0 >> 16, pl = p0 & 65535;
    int w0 = pl >> 10, h0 = pl & 1023;
    int p = t & 127, co = (t >> 7) << 5, co8 = co >> 3;

    // w2 [o][k] fp16 swizzled
    for (int e = t; e < 4096; e += 256) {
        int o = e >> 6, k = e & 63;
        *(__half*)(smc + EW + swadr(o, k >> 3) + (k & 7) * 2) = __float2half_rn(w2[e]);
    }
    {   // V' fp16 -> EV (swizzled)
        const uint4* vsrc = reinterpret_cast<const uint4*>(
            g_VTh + ((size_t)((b << 16) + pl + p)) * 64 + co);
#pragma unroll
        for (int kc = 0; kc < 4; kc++)
            *(uint4*)(smc + EV + swadr(p, co8 + kc)) = vsrc[kc];
    }
    for (int e = t; e < 576; e += 256) {
        int s = e >> 6, k = e & 63;
        int swv = s / 3 - 1, shv = s % 3 - 1;
        float ca = cosf(swv * AZI_C), sa = sinf(swv * AZI_C);
        float ci = cosf(shv * INC_C), si = sinf(shv * INC_C);
        sQ[e] = ca * ci * w1[k * 131 + 128] + ca * si * w1[k * 131 + 129]
              + sa * w1[k * 131 + 130];
    }
    if (t < 64) sB2[t] = b2[t];
    __syncthreads();

    // hoist w2 A-fragments: warp = (mi: 2 x 32ch, ni: 4 x 32px)
    int mi = wid & 1, ni = wid >> 1;
    uint32_t wa[2][4][4];
#pragma unroll
    for (int m = 0; m < 2; m++) {
        int row = mi * 32 + m * 16 + (ln & 15);
#pragma unroll
        for (int q = 0; q < 4; q++)
            LDSM4(wa[m][q][0], wa[m][q][1], wa[m][q][2], wa[m][q][3],
                  sb + EW + swadr(row, q * 2 + (ln >> 4)));
    }

    float best[2][4][4];
#pragma unroll
    for (int m = 0; m < 2; m++)
#pragma unroll
        for (int ng = 0; ng < 4; ng++)
#pragma unroll
            for (int j = 0; j < 4; j++) best[m][ng][j] = -1e30f;

    for (int s = 0; s < 9; s++) {
        int swv = s / 3 - 1, shv = s % 3 - 1;
        int wsrc = (w0 - swv) & 63;
        size_t rowb = ((size_t)(b << 16)) + ((size_t)wsrc << 10);
        // t-build: t_s = relu(U_s + V' + r_s*q) in fp32, packed fp16
        {
            int hs = (h0 + p - shv) & 1023;
            const uint4* ub = reinterpret_cast<const uint4*>(
                g_UTh + (rowb + hs) * 64 + co);
            float rs = __ldg(r + rowb + hs);
            const float4* qv = reinterpret_cast<const float4*>(sQ + s * 64 + co);
#pragma unroll
            for (int kc = 0; kc < 4; kc++) {
                uint4 uu = ub[kc];
                uint4 vv = *(const uint4*)(smc + EV + swadr(p, co8 + kc));
                const __half2* uh = reinterpret_cast<const __half2*>(&uu);
                const __half2* vh = reinterpret_cast<const __half2*>(&vv);
                float4 q0 = qv[kc * 2], q1 = qv[kc * 2 + 1];
                float2 u0 = __half22float2(uh[0]), v0 = __half22float2(vh[0]);
                float2 u1 = __half22float2(uh[1]), v1 = __half22float2(vh[1]);
                float2 u2 = __half22float2(uh[2]), v2 = __half22float2(vh[2]);
                float2 u3 = __half22float2(uh[3]), v3 = __half22float2(vh[3]);
                float x0 = fmaxf(fmaf(rs, q0.x, u0.x + v0.x), 0.f);
                float x1 = fmaxf(fmaf(rs, q0.y, u0.y + v0.y), 0.f);
                float x2 = fmaxf(fmaf(rs, q0.z, u1.x + v1.x), 0.f);
                float x3 = fmaxf(fmaf(rs, q0.w, u1.y + v1.y), 0.f);
                float x4 = fmaxf(fmaf(rs, q1.x, u2.x + v2.x), 0.f);
                float x5 = fmaxf(fmaf(rs, q1.y, u2.y + v2.y), 0.f);
                float x6 = fmaxf(fmaf(rs, q1.z, u3.x + v3.x), 0.f);
                float x7 = fmaxf(fmaf(rs, q1.w, u3.y + v3.y), 0.f);
                __half2 p0h = __floats2half2_rn(x0, x1);
                __half2 p1h = __floats2half2_rn(x2, x3);
                __half2 p2h = __floats2half2_rn(x4, x5);
                __half2 p3h = __floats2half2_rn(x6, x7);
                *(uint4*)(smc + ET + swadr(p, co8 + kc)) = make_uint4(
                    *reinterpret_cast<uint32_t*>(&p0h), *reinterpret_cast<uint32_t*>(&p1h),
                    *reinterpret_cast<uint32_t*>(&p2h), *reinterpret_cast<uint32_t*>(&p3h));
            }
        }
        __syncthreads();

#pragma unroll
        for (int ng = 0; ng < 4; ng++) {
            int rowt = ni * 32 + ng * 8 + (ln & 7);
            uint32_t tb0[4], tb1[4];
            LDSM4(tb0[0], tb0[1], tb0[2], tb0[3], sb + ET + swadr(rowt, (ln >> 3)));
            LDSM4(tb1[0], tb1[1], tb1[2], tb1[3], sb + ET + swadr(rowt, 4 + (ln >> 3)));
            float acc[2][4];
#pragma unroll
            for (int m = 0; m < 2; m++)
#pragma unroll
                for (int j = 0; j < 4; j++) acc[m][j] = 0.f;
#pragma unroll
            for (int m = 0; m < 2; m++) {
                MMAF16(acc[m][0], acc[m][1], acc[m][2], acc[m][3],
                       wa[m][0][0], wa[m][0][1], wa[m][0][2], wa[m][0][3],
                       tb0[0], tb0[1]);
                MMAF16(acc[m][0], acc[m][1], acc[m][2], acc[m][3],
                       wa[m][1][0], wa[m][1][1], wa[m][1][2], wa[m][1][3],
                       tb0[2], tb0[3]);
                MMAF16(acc[m][0], acc[m][1], acc[m][2], acc[m][3],
                       wa[m][2][0], wa[m][2][1], wa[m][2][2], wa[m][2][3],
                       tb1[0], tb1[1]);
                MMAF16(acc[m][0], acc[m][1], acc[m][2], acc[m][3],
                       wa[m][3][0], wa[m][3][1], wa[m][3][2], wa[m][3][3],
                       tb1[2], tb1[3]);
            }
#pragma unroll
            for (int m = 0; m < 2; m++)
#pragma unroll
                for (int j = 0; j < 4; j++)
                    best[m][ng][j] = fmaxf(best[m][ng][j], acc[m][j]);
        }
        __syncthreads();
    }

    // epilogue: D frag rows = channels, cols = pixels -> sTr[ch][136], coalesced store
    float* sTr = (float*)smc;    // [64][136] floats = 34816 B (overlays ET/EW/EV)
    {
        int cr = ln >> 2, cx2 = (ln & 3) << 1;
#pragma unroll
        for (int m = 0; m < 2; m++) {
            int ch0 = mi * 32 + m * 16 + cr, ch1 = ch0 + 8;
#pragma unroll
            for (int ng = 0; ng < 4; ng++) {
                int px = ni * 32 + ng * 8 + cx2;
                *(float2*)(sTr + ch0 * 136 + px) = make_float2(best[m][ng][0], best[m][ng][1]);
                *(float2*)(sTr + ch1 * 136 + px) = make_float2(best[m][ng][2], best[m][ng][3]);
            }
        }
    }
    __syncthreads();
#pragma unroll
    for (int i = 0; i < 32; i++) {
        int e = t + i * 256;
        int o = e >> 7, pix = e & 127;
        float v = sTr[o * 136 + pix] + sB2[o];
        size_t idx = (((size_t)(b * 64 + o)) << 16) + (pl + pix);
        if (add_res) v += xres[idx];
        out[idx] = v;
    }
}

// ---------------------------------------------------------------------------
extern "C" void kernel_launch(void* const* d_in, const int* in_sizes, int n_in,
                              void* d_out, int out_size) {
    const float* x     = (const float*)d_in[0];
    const float* r     = (const float*)d_in[1];
    const float* n1_w  = (const float*)d_in[2];
    const float* n1_b  = (const float*)d_in[3];
    const float* c1_w1 = (const float*)d_in[4];
    const float* c1_b1 = (const float*)d_in[5];
    const float* c1_w2 = (const float*)d_in[6];
    const float* c1_b2 = (const float*)d_in[7];
    const float* n2_w  = (const float*)d_in[8];
    const float* n2_b  = (const float*)d_in[9];
    const float* c2_w1 = (const float*)d_in[10];
    const float* c2_b1 = (const float*)d_in[11];
    const float* c2_w2 = (const float*)d_in[12];
    const float* c2_b2 = (const float*)d_in[13];
    float* out = (float*)d_out;

    cudaFuncSetAttribute(gemm_mm_kernel,
                         cudaFuncAttributeMaxDynamicSharedMemorySize, G_SZ);
    cudaFuncSetAttribute(edge_mm_kernel,
                         cudaFuncAttributeMaxDynamicSharedMemorySize, E_SZ);

    gn_part_kernel<<<1024, 256>>>(x);
    gn_fin_kernel<<<1, 128>>>();
    gemm_mm_kernel<<<2048, 256, G_SZ>>>(x, r, c1_w1, c1_b1, n1_w, n1_b);
    edge_mm_kernel<<<2048, 256, E_SZ>>>(r, c1_w1, c1_w2, c1_b2, nullptr, out, 0);

    gn_part_kernel<<<1024, 256>>>(out);
    gn_fin_kernel<<<1, 128>>>();
    gemm_mm_kernel<<<2048, 256, G_SZ>>>(out, r, c2_w1, c2_b1, n2_w, n2_b);
    edge_mm_kernel<<<2048, 256, E_SZ>>>(r, c2_w1, c2_w2, c2_b2, x, out, 1);
}

// round 11
// speedup vs baseline: 1.9587x; 1.0506x over previous
#include <cuda_runtime.h>
#include <cuda_bf16.h>
#include <cuda_fp16.h>
#include <cstdint>

#define NPIX 262144
#define AZI_C 0.006135923151542565f
#define INC_C 0.008267349088394194f

// scratch (device globals; no runtime alloc)
__device__ __half g_UTh[(size_t)NPIX * 64];   // pixel-major U  [pix][64] fp16
__device__ __half g_VTh[(size_t)NPIX * 64];   // pixel-major V' [pix][64] fp16
__device__ float g_mean[128], g_rstd[128];
__device__ float2 g_part[1024];

// ---------------- helpers ----------------
__device__ __forceinline__ uint32_t smem_u32(const void* p) {
    uint32_t a;
    asm("{ .reg .u64 t; cvta.to.shared.u64 t, %1; cvt.u32.u64 %0, t; }" : "=r"(a) : "l"(p));
    return a;
}
#define LDSM4(r0, r1, r2, r3, a) \
    asm volatile("ldmatrix.sync.aligned.m8n8.x4.shared.b16 {%0,%1,%2,%3}, [%4];" \
        : "=r"(r0), "=r"(r1), "=r"(r2), "=r"(r3) : "r"(a))
#define MMABF(c0, c1, c2, c3, a0, a1, a2, a3, b0, b1) \
    asm volatile("mma.sync.aligned.m16n8k16.row.col.f32.bf16.bf16.f32 " \
        "{%0,%1,%2,%3},{%4,%5,%6,%7},{%8,%9},{%0,%1,%2,%3};" \
        : "+f"(c0), "+f"(c1), "+f"(c2), "+f"(c3) \
        : "r"(a0), "r"(a1), "r"(a2), "r"(a3), "r"(b0), "r"(b1))
#define MMAF16(c0, c1, c2, c3, a0, a1, a2, a3, b0, b1) \
    asm volatile("mma.sync.aligned.m16n8k16.row.col.f32.f16.f16.f32 " \
        "{%0,%1,%2,%3},{%4,%5,%6,%7},{%8,%9},{%0,%1,%2,%3};" \
        : "+f"(c0), "+f"(c1), "+f"(c2), "+f"(c3) \
        : "r"(a0), "r"(a1), "r"(a2), "r"(a3), "r"(b0), "r"(b1))

__device__ __forceinline__ void split2(float a, float b, uint32_t& h, uint32_t& l) {
    __nv_bfloat162 hb = __floats2bfloat162_rn(a, b);
    float fa = __low2float(hb), fb = __high2float(hb);
    __nv_bfloat162 lb = __floats2bfloat162_rn(a - fa, b - fb);
    h = *reinterpret_cast<uint32_t*>(&hb);
    l = *reinterpret_cast<uint32_t*>(&lb);
}
// swizzled tile addressing: pitch 128B, chunk = 16B unit
__device__ __forceinline__ uint32_t swadr(int row, int chunk) {
    return (uint32_t)(row * 128 + ((chunk ^ (row & 7)) << 4));
}

// ---------------- GroupNorm stats, two-phase ----------------
__global__ void gn_part_kernel(const float* __restrict__ in) {
    int c = blockIdx.x, t = threadIdx.x;
    const float4* base = reinterpret_cast<const float4*>(in + (size_t)c * 16384);
    float s = 0.f, q = 0.f;
    for (int i = t; i < 4096; i += 256) {
        float4 v = base[i];
        s += (v.x + v.y) + (v.z + v.w);
        q += (v.x * v.x + v.y * v.y) + (v.z * v.z + v.w * v.w);
    }
    __shared__ float rs[256], rq[256];
    rs[t] = s; rq[t] = q;
    __syncthreads();
    for (int off = 128; off > 0; off >>= 1) {
        if (t < off) { rs[t] += rs[t + off]; rq[t] += rq[t + off]; }
        __syncthreads();
    }
    if (t == 0) g_part[c] = make_float2(rs[0], rq[0]);
}
__global__ void gn_fin_kernel() {
    int t = threadIdx.x;
    if (t < 128) {
        float s = 0.f, q = 0.f;
#pragma unroll
        for (int i = 0; i < 8; i++) { float2 p = g_part[t * 8 + i]; s += p.x; q += p.y; }
        float m = s * (1.f / 131072.f);
        g_mean[t] = m;
        g_rstd[t] = rsqrtf(q * (1.f / 131072.f) - m * m + 1e-6f);
    }
}

// ---------------- GEMM1: U,V' = relu(gn(x)) @ [Wa;Wb]^T (3-pass bf16) ----------------
#define GA_H 0
#define GA_L 16384
#define GB_H 32768
#define GB_L 49152
#define G_CF 65536
#define G_SZ 66560

__global__ __launch_bounds__(256, 2) void gemm_mm_kernel(
    const float* __restrict__ xin, const float* __restrict__ r,
    const float* __restrict__ w1, const float* __restrict__ b1,
    const float* __restrict__ gnw, const float* __restrict__ gnb)
{
    extern __shared__ char smc[];
    uint32_t sb = smem_u32(smc);
    float* scf  = (float*)(smc + G_CF);
    float* bif  = scf + 64;
    float* b1f  = scf + 128;
    float* wp0f = scf + 192;

    int t = threadIdx.x, wid = t >> 5, ln = t & 31;
    int p0 = blockIdx.x << 7;
    int b = p0 >> 16, pl = p0 & 65535;

    if (t < 64) {
        int grp = (b << 5) + (t >> 1);
        float sc = g_rstd[grp] * gnw[t];
        scf[t]  = sc;
        bif[t]  = gnb[t] - g_mean[grp] * sc;
        b1f[t]  = b1[t];
        wp0f[t] = w1[t * 131 + 128];
    }
    for (int e = t; e < 8192; e += 256) {
        int n = e >> 6, k = e & 63;
        float v = (n < 64) ? w1[n * 131 + k] : w1[(n - 64) * 131 + 64 + k];
        __nv_bfloat16 h = __float2bfloat16(v);
        __nv_bfloat16 l = __float2bfloat16(v - __bfloat162float(h));
        uint32_t off = swadr(n, k >> 3) + (k & 7) * 2;
        *(__nv_bfloat16*)(smc + GB_H + off) = h;
        *(__nv_bfloat16*)(smc + GB_L + off) = l;
    }
    {
        int p = t & 127, co = (t >> 7) << 5;
        const float* xb = xin + (((size_t)(b * 64 + co)) << 16) + pl + p;
#pragma unroll
        for (int kc = 0; kc < 4; kc++) {
            float xv[8];
#pragma unroll
            for (int i = 0; i < 8; i++) {
                int k = co + kc * 8 + i;
                float raw = xb[((size_t)(kc * 8 + i)) << 16];
                xv[i] = fmaxf(fmaf(raw, scf[k], bif[k]), 0.f);
            }
            uint32_t h0, l0, h1, l1, h2, l2, h3, l3;
            split2(xv[0], xv[1], h0, l0);
            split2(xv[2], xv[3], h1, l1);
            split2(xv[4], xv[5], h2, l2);
            split2(xv[6], xv[7], h3, l3);
            uint32_t off = swadr(p, (co >> 3) + kc);
            *(uint4*)(smc + GA_H + off) = make_uint4(h0, h1, h2, h3);
            *(uint4*)(smc + GA_L + off) = make_uint4(l0, l1, l2, l3);
        }
    }
    __syncthreads();

    int wm = wid << 4;
    float acc[16][4];
#pragma unroll
    for (int nb = 0; nb < 16; nb++)
#pragma unroll
        for (int j = 0; j < 4; j++) acc[nb][j] = 0.f;

#pragma unroll
    for (int kh = 0; kh < 2; kh++) {
        uint32_t ah[8], al[8];
        {
            int row = wm + (ln & 15);
            int c0 = kh * 4 + (ln >> 4);
            uint32_t ad0 = sb + GA_H + swadr(row, c0);
            uint32_t ad1 = sb + GA_H + swadr(row, c0 + 2);
            LDSM4(ah[0], ah[1], ah[2], ah[3], ad0);
            LDSM4(ah[4], ah[5], ah[6], ah[7], ad1);
            LDSM4(al[0], al[1], al[2], al[3], ad0 + 16384);
            LDSM4(al[4], al[5], al[6], al[7], ad1 + 16384);
        }
#pragma unroll
        for (int nb = 0; nb < 16; nb++) {
            int brow = nb * 8 + (ln & 7);
            int bc = kh * 4 + (ln >> 3);
            uint32_t bad = sb + GB_H + swadr(brow, bc);
            uint32_t bh[4], bl[4];
            LDSM4(bh[0], bh[1], bh[2], bh[3], bad);
            LDSM4(bl[0], bl[1], bl[2], bl[3], bad + 16384);
            MMABF(acc[nb][0], acc[nb][1], acc[nb][2], acc[nb][3],
                  ah[0], ah[1], ah[2], ah[3], bh[0], bh[1]);
            MMABF(acc[nb][0], acc[nb][1], acc[nb][2], acc[nb][3],
                  ah[4], ah[5], ah[6], ah[7], bh[2], bh[3]);
            MMABF(acc[nb][0], acc[nb][1], acc[nb][2], acc[nb][3],
                  ah[0], ah[1], ah[2], ah[3], bl[0], bl[1]);
            MMABF(acc[nb][0], acc[nb][1], acc[nb][2], acc[nb][3],
                  ah[4], ah[5], ah[6], ah[7], bl[2], bl[3]);
            MMABF(acc[nb][0], acc[nb][1], acc[nb][2], acc[nb][3],
                  al[0], al[1], al[2], al[3], bh[0], bh[1]);
            MMABF(acc[nb][0], acc[nb][1], acc[nb][2], acc[nb][3],
                  al[4], al[5], al[6], al[7], bh[2], bh[3]);
        }
    }

    int pr0 = wm + (ln >> 2), pr1 = pr0 + 8;
    int cx = (ln & 3) << 1;
    size_t gp0 = (size_t)((b << 16) + pl + pr0);
    size_t gp1 = (size_t)((b << 16) + pl + pr1);
    float r0 = r[gp0], r1 = r[gp1];
#pragma unroll
    for (int nb = 0; nb < 16; nb++) {
        if (nb < 8) {
            int ch = nb * 8 + cx;
            *(__half2*)(g_UTh + gp0 * 64 + ch) = __floats2half2_rn(acc[nb][0], acc[nb][1]);
            *(__half2*)(g_UTh + gp1 * 64 + ch) = __floats2half2_rn(acc[nb][2], acc[nb][3]);
        } else {
            int ch = (nb - 8) * 8 + cx;
            float bb0 = b1f[ch], bb1 = b1f[ch + 1];
            float w0 = wp0f[ch], w1v = wp0f[ch + 1];
            *(__half2*)(g_VTh + gp0 * 64 + ch) =
                __floats2half2_rn(acc[nb][0] + bb0 - r0 * w0, acc[nb][1] + bb1 - r0 * w1v);
            *(__half2*)(g_VTh + gp1 * 64 + ch) =
                __floats2half2_rn(acc[nb][2] + bb0 - r1 * w0, acc[nb][3] + bb1 - r1 * w1v);
        }
    }
}

// ---------------- Edge-max: hoisted w2, half2 t-build, double-buffered ET, 1 sync/shift ----------------
// ET0 16KB | ET1 16KB | EW 8KB | EV 16KB | EQH (9*64 half) | EB2
#define ET0  0
#define ET1  16384
#define EW   32768
#define EV   40960
#define EQH  57344
#define EB2  58496
#define E_SZ 58752

__global__ __launch_bounds__(256, 2) void edge_mm_kernel(
    const float* __restrict__ r, const float* __restrict__ w1,
    const float* __restrict__ w2, const float* __restrict__ b2,
    const float* __restrict__ xres, float* __restrict__ out, int add_res)
{
    extern __shared__ char smc[];
    uint32_t sb = smem_u32(smc);
    float* sB2 = (float*)(smc + EB2);
    __half* sQh = (__half*)(smc + EQH);

    int t = threadIdx.x, wid = t >> 5, ln = t & 31;
    int p0 = blockIdx.x << 7;
    int b = p0 >> 16, pl = p0 & 65535;
    int w0 = pl >> 10, h0 = pl & 1023;
    int p = t & 127, co = (t >> 7) << 5, co8 = co >> 3;

    // w2 [o][k] fp16 swizzled
    for (int e = t; e < 4096; e += 256) {
        int o = e >> 6, k = e & 63;
        *(__half*)(smc + EW + swadr(o, k >> 3) + (k & 7) * 2) = __float2half_rn(w2[e]);
    }
    {   // V' fp16 -> EV (swizzled)
        const uint4* vsrc = reinterpret_cast<const uint4*>(
            g_VTh + ((size_t)((b << 16) + pl + p)) * 64 + co);
#pragma unroll
        for (int kc = 0; kc < 4; kc++)
            *(uint4*)(smc + EV + swadr(p, co8 + kc)) = vsrc[kc];
    }
    for (int e = t; e < 576; e += 256) {
        int s = e >> 6, k = e & 63;
        int swv = s / 3 - 1, shv = s % 3 - 1;
        float ca = cosf(swv * AZI_C), sa = sinf(swv * AZI_C);
        float ci = cosf(shv * INC_C), si = sinf(shv * INC_C);
        sQh[e] = __float2half_rn(ca * ci * w1[k * 131 + 128]
                               + ca * si * w1[k * 131 + 129]
                               + sa * w1[k * 131 + 130]);
    }
    if (t < 64) sB2[t] = b2[t];
    __syncthreads();

    // hoist w2 A-fragments: warp = (mi: 2 x 32ch, ni: 4 x 32px)
    int mi = wid & 1, ni = wid >> 1;
    uint32_t wa[2][4][4];
#pragma unroll
    for (int m = 0; m < 2; m++) {
        int row = mi * 32 + m * 16 + (ln & 15);
#pragma unroll
        for (int q = 0; q < 4; q++)
            LDSM4(wa[m][q][0], wa[m][q][1], wa[m][q][2], wa[m][q][3],
                  sb + EW + swadr(row, q * 2 + (ln >> 4)));
    }

    const __half2 z2 = __float2half2_rn(0.f);
    // half2 t-build into buffer `base`
    auto buildT = [&](int s, uint32_t base) {
        int swv = s / 3 - 1, shv = s % 3 - 1;
        int wsrc = (w0 - swv) & 63;
        size_t rowb = ((size_t)(b << 16)) + ((size_t)wsrc << 10);
        int hs = (h0 + p - shv) & 1023;
        const uint4* ub = reinterpret_cast<const uint4*>(
            g_UTh + (rowb + hs) * 64 + co);
        __half2 rs2 = __float2half2_rn(__ldg(r + rowb + hs));
        const __half2* qh = reinterpret_cast<const __half2*>(sQh + s * 64 + co);
#pragma unroll
        for (int kc = 0; kc < 4; kc++) {
            uint4 uu = ub[kc];
            uint4 vv = *(const uint4*)(smc + EV + swadr(p, co8 + kc));
            const __half2* u2 = reinterpret_cast<const __half2*>(&uu);
            const __half2* v2 = reinterpret_cast<const __half2*>(&vv);
            uint4 ov;
            __half2* o2 = reinterpret_cast<__half2*>(&ov);
#pragma unroll
            for (int j = 0; j < 4; j++)
                o2[j] = __hmax2(__hfma2(rs2, qh[kc * 4 + j],
                                        __hadd2(u2[j], v2[j])), z2);
            *(uint4*)(smc + base + swadr(p, co8 + kc)) = ov;
        }
    };

    float best[2][4][4];
#pragma unroll
    for (int m = 0; m < 2; m++)
#pragma unroll
        for (int ng = 0; ng < 4; ng++)
#pragma unroll
            for (int j = 0; j < 4; j++) best[m][ng][j] = -1e30f;

    buildT(0, ET0);
    __syncthreads();

    for (int s = 0; s < 9; s++) {
        uint32_t cur = (s & 1) ? ET1 : ET0;
#pragma unroll
        for (int ng = 0; ng < 4; ng++) {
            int rowt = ni * 32 + ng * 8 + (ln & 7);
            uint32_t tb0[4], tb1[4];
            LDSM4(tb0[0], tb0[1], tb0[2], tb0[3], sb + cur + swadr(rowt, (ln >> 3)));
            LDSM4(tb1[0], tb1[1], tb1[2], tb1[3], sb + cur + swadr(rowt, 4 + (ln >> 3)));
            float acc[2][4];
#pragma unroll
            for (int m = 0; m < 2; m++)
#pragma unroll
                for (int j = 0; j < 4; j++) acc[m][j] = 0.f;
#pragma unroll
            for (int m = 0; m < 2; m++) {
                MMAF16(acc[m][0], acc[m][1], acc[m][2], acc[m][3],
                       wa[m][0][0], wa[m][0][1], wa[m][0][2], wa[m][0][3],
                       tb0[0], tb0[1]);
                MMAF16(acc[m][0], acc[m][1], acc[m][2], acc[m][3],
                       wa[m][1][0], wa[m][1][1], wa[m][1][2], wa[m][1][3],
                       tb0[2], tb0[3]);
                MMAF16(acc[m][0], acc[m][1], acc[m][2], acc[m][3],
                       wa[m][2][0], wa[m][2][1], wa[m][2][2], wa[m][2][3],
                       tb1[0], tb1[1]);
                MMAF16(acc[m][0], acc[m][1], acc[m][2], acc[m][3],
                       wa[m][3][0], wa[m][3][1], wa[m][3][2], wa[m][3][3],
                       tb1[2], tb1[3]);
            }
#pragma unroll
            for (int m = 0; m < 2; m++)
#pragma unroll
                for (int j = 0; j < 4; j++)
                    best[m][ng][j] = fmaxf(best[m][ng][j], acc[m][j]);
        }
        if (s < 8) buildT(s + 1, (s & 1) ? ET0 : ET1);
        __syncthreads();
    }

    // epilogue: D frag rows = channels, cols = pixels -> sTr[ch][136], coalesced store
    float* sTr = (float*)smc;    // [64][136] floats = 34816 B (overlays ET0/ET1/EW)
    {
        int cr = ln >> 2, cx2 = (ln & 3) << 1;
#pragma unroll
        for (int m = 0; m < 2; m++) {
            int ch0 = mi * 32 + m * 16 + cr, ch1 = ch0 + 8;
#pragma unroll
            for (int ng = 0; ng < 4; ng++) {
                int px = ni * 32 + ng * 8 + cx2;
                *(float2*)(sTr + ch0 * 136 + px) = make_float2(best[m][ng][0], best[m][ng][1]);
                *(float2*)(sTr + ch1 * 136 + px) = make_float2(best[m][ng][2], best[m][ng][3]);
            }
        }
    }
    __syncthreads();
#pragma unroll
    for (int i = 0; i < 32; i++) {
        int e = t + i * 256;
        int o = e >> 7, pix = e & 127;
        float v = sTr[o * 136 + pix] + sB2[o];
        size_t idx = (((size_t)(b * 64 + o)) << 16) + (pl + pix);
        if (add_res) v += xres[idx];
        out[idx] = v;
    }
}

// ---------------------------------------------------------------------------
extern "C" void kernel_launch(void* const* d_in, const int* in_sizes, int n_in,
                              void* d_out, int out_size) {
    const float* x     = (const float*)d_in[0];
    const float* r     = (const float*)d_in[1];
    const float* n1_w  = (const float*)d_in[2];
    const float* n1_b  = (const float*)d_in[3];
    const float* c1_w1 = (const float*)d_in[4];
    const float* c1_b1 = (const float*)d_in[5];
    const float* c1_w2 = (const float*)d_in[6];
    const float* c1_b2 = (const float*)d_in[7];
    const float* n2_w  = (const float*)d_in[8];
    const float* n2_b  = (const float*)d_in[9];
    const float* c2_w1 = (const float*)d_in[10];
    const float* c2_b1 = (const float*)d_in[11];
    const float* c2_w2 = (const float*)d_in[12];
    const float* c2_b2 = (const float*)d_in[13];
    float* out = (float*)d_out;

    cudaFuncSetAttribute(gemm_mm_kernel,
                         cudaFuncAttributeMaxDynamicSharedMemorySize, G_SZ);
    cudaFuncSetAttribute(edge_mm_kernel,
                         cudaFuncAttributeMaxDynamicSharedMemorySize, E_SZ);

    gn_part_kernel<<<1024, 256>>>(x);
    gn_fin_kernel<<<1, 128>>>();
    gemm_mm_kernel<<<2048, 256, G_SZ>>>(x, r, c1_w1, c1_b1, n1_w, n1_b);
    edge_mm_kernel<<<2048, 256, E_SZ>>>(r, c1_w1, c1_w2, c1_b2, nullptr, out, 0);

    gn_part_kernel<<<1024, 256>>>(out);
    gn_fin_kernel<<<1, 128>>>();
    gemm_mm_kernel<<<2048, 256, G_SZ>>>(out, r, c2_w1, c2_b1, n2_w, n2_b);
    edge_mm_kernel<<<2048, 256, E_SZ>>>(r, c2_w1, c2_w2, c2_b2, x, out, 1);
}

// round 12
// speedup vs baseline: 2.0855x; 1.0647x over previous
#include <cuda_runtime.h>
#include <cuda_bf16.h>
#include <cuda_fp16.h>
#include <cstdint>

#define NPIX 262144
#define AZI_C 0.006135923151542565f
#define INC_C 0.008267349088394194f

// scratch (device globals; no runtime alloc)
__device__ __half g_UTh[(size_t)NPIX * 64];   // pixel-major U  [pix][64] fp16
__device__ __half g_VTh[(size_t)NPIX * 64];   // pixel-major V' [pix][64] fp16
__device__ float g_mean[128], g_rstd[128];
__device__ float2 g_part[1024];

// ---------------- helpers ----------------
__device__ __forceinline__ uint32_t smem_u32(const void* p) {
    uint32_t a;
    asm("{ .reg .u64 t; cvta.to.shared.u64 t, %1; cvt.u32.u64 %0, t; }" : "=r"(a) : "l"(p));
    return a;
}
#define LDSM4(r0, r1, r2, r3, a) \
    asm volatile("ldmatrix.sync.aligned.m8n8.x4.shared.b16 {%0,%1,%2,%3}, [%4];" \
        : "=r"(r0), "=r"(r1), "=r"(r2), "=r"(r3) : "r"(a))
#define MMAF16(c0, c1, c2, c3, a0, a1, a2, a3, b0, b1) \
    asm volatile("mma.sync.aligned.m16n8k16.row.col.f32.f16.f16.f32 " \
        "{%0,%1,%2,%3},{%4,%5,%6,%7},{%8,%9},{%0,%1,%2,%3};" \
        : "+f"(c0), "+f"(c1), "+f"(c2), "+f"(c3) \
        : "r"(a0), "r"(a1), "r"(a2), "r"(a3), "r"(b0), "r"(b1))

// swizzled tile addressing: pitch 128B, chunk = 16B unit
__device__ __forceinline__ uint32_t swadr(int row, int chunk) {
    return (uint32_t)(row * 128 + ((chunk ^ (row & 7)) << 4));
}

// ---------------- GroupNorm stats, two-phase ----------------
__global__ void gn_part_kernel(const float* __restrict__ in) {
    int c = blockIdx.x, t = threadIdx.x;
    const float4* base = reinterpret_cast<const float4*>(in + (size_t)c * 16384);
    float s = 0.f, q = 0.f;
    for (int i = t; i < 4096; i += 256) {
        float4 v = base[i];
        s += (v.x + v.y) + (v.z + v.w);
        q += (v.x * v.x + v.y * v.y) + (v.z * v.z + v.w * v.w);
    }
    __shared__ float rs[256], rq[256];
    rs[t] = s; rq[t] = q;
    __syncthreads();
    for (int off = 128; off > 0; off >>= 1) {
        if (t < off) { rs[t] += rs[t + off]; rq[t] += rq[t + off]; }
        __syncthreads();
    }
    if (t == 0) g_part[c] = make_float2(rs[0], rq[0]);
}
__global__ void gn_fin_kernel() {
    int t = threadIdx.x;
    if (t < 128) {
        float s = 0.f, q = 0.f;
#pragma unroll
        for (int i = 0; i < 8; i++) { float2 p = g_part[t * 8 + i]; s += p.x; q += p.y; }
        float m = s * (1.f / 131072.f);
        g_mean[t] = m;
        g_rstd[t] = rsqrtf(q * (1.f / 131072.f) - m * m + 1e-6f);
    }
}

// ---------------- GEMM1: U,V' = relu(gn(x)) @ [Wa;Wb]^T (single-pass fp16) ----------------
#define GA   0
#define GB   16384
#define G_CF 32768
#define G_SZ 33792

__global__ __launch_bounds__(256, 2) void gemm_mm_kernel(
    const float* __restrict__ xin, const float* __restrict__ r,
    const float* __restrict__ w1, const float* __restrict__ b1,
    const float* __restrict__ gnw, const float* __restrict__ gnb)
{
    extern __shared__ char smc[];
    uint32_t sb = smem_u32(smc);
    float* scf  = (float*)(smc + G_CF);
    float* bif  = scf + 64;
    float* b1f  = scf + 128;
    float* wp0f = scf + 192;

    int t = threadIdx.x, wid = t >> 5, ln = t & 31;
    int p0 = blockIdx.x << 7;
    int b = p0 >> 16, pl = p0 & 65535;

    if (t < 64) {
        int grp = (b << 5) + (t >> 1);
        float sc = g_rstd[grp] * gnw[t];
        scf[t]  = sc;
        bif[t]  = gnb[t] - g_mean[grp] * sc;
        b1f[t]  = b1[t];
        wp0f[t] = w1[t * 131 + 128];
    }
    // B = [Wa;Wb] fp16, swizzled
    for (int e = t; e < 8192; e += 256) {
        int n = e >> 6, k = e & 63;
        float v = (n < 64) ? w1[n * 131 + k] : w1[(n - 64) * 131 + 64 + k];
        *(__half*)(smc + GB + swadr(n, k >> 3) + (k & 7) * 2) = __float2half_rn(v);
    }
    {
        int p = t & 127, co = (t >> 7) << 5;
        const float* xb = xin + (((size_t)(b * 64 + co)) << 16) + pl + p;
#pragma unroll
        for (int kc = 0; kc < 4; kc++) {
            float xv[8];
#pragma unroll
            for (int i = 0; i < 8; i++) {
                int k = co + kc * 8 + i;
                float raw = xb[((size_t)(kc * 8 + i)) << 16];
                xv[i] = fmaxf(fmaf(raw, scf[k], bif[k]), 0.f);
            }
            __half2 h0 = __floats2half2_rn(xv[0], xv[1]);
            __half2 h1 = __floats2half2_rn(xv[2], xv[3]);
            __half2 h2 = __floats2half2_rn(xv[4], xv[5]);
            __half2 h3 = __floats2half2_rn(xv[6], xv[7]);
            *(uint4*)(smc + GA + swadr(p, (co >> 3) + kc)) = make_uint4(
                *reinterpret_cast<uint32_t*>(&h0), *reinterpret_cast<uint32_t*>(&h1),
                *reinterpret_cast<uint32_t*>(&h2), *reinterpret_cast<uint32_t*>(&h3));
        }
    }
    __syncthreads();

    int wm = wid << 4;
    float acc[16][4];
#pragma unroll
    for (int nb = 0; nb < 16; nb++)
#pragma unroll
        for (int j = 0; j < 4; j++) acc[nb][j] = 0.f;

#pragma unroll
    for (int kh = 0; kh < 2; kh++) {
        uint32_t ah[8];
        {
            int row = wm + (ln & 15);
            int c0 = kh * 4 + (ln >> 4);
            LDSM4(ah[0], ah[1], ah[2], ah[3], sb + GA + swadr(row, c0));
            LDSM4(ah[4], ah[5], ah[6], ah[7], sb + GA + swadr(row, c0 + 2));
        }
#pragma unroll
        for (int nb = 0; nb < 16; nb++) {
            int brow = nb * 8 + (ln & 7);
            int bc = kh * 4 + (ln >> 3);
            uint32_t bh[4];
            LDSM4(bh[0], bh[1], bh[2], bh[3], sb + GB + swadr(brow, bc));
            MMAF16(acc[nb][0], acc[nb][1], acc[nb][2], acc[nb][3],
                   ah[0], ah[1], ah[2], ah[3], bh[0], bh[1]);
            MMAF16(acc[nb][0], acc[nb][1], acc[nb][2], acc[nb][3],
                   ah[4], ah[5], ah[6], ah[7], bh[2], bh[3]);
        }
    }

    int pr0 = wm + (ln >> 2), pr1 = pr0 + 8;
    int cx = (ln & 3) << 1;
    size_t gp0 = (size_t)((b << 16) + pl + pr0);
    size_t gp1 = (size_t)((b << 16) + pl + pr1);
    float r0 = r[gp0], r1 = r[gp1];
#pragma unroll
    for (int nb = 0; nb < 16; nb++) {
        if (nb < 8) {
            int ch = nb * 8 + cx;
            *(__half2*)(g_UTh + gp0 * 64 + ch) = __floats2half2_rn(acc[nb][0], acc[nb][1]);
            *(__half2*)(g_UTh + gp1 * 64 + ch) = __floats2half2_rn(acc[nb][2], acc[nb][3]);
        } else {
            int ch = (nb - 8) * 8 + cx;
            float bb0 = b1f[ch], bb1 = b1f[ch + 1];
            float w0 = wp0f[ch], w1v = wp0f[ch + 1];
            *(__half2*)(g_VTh + gp0 * 64 + ch) =
                __floats2half2_rn(acc[nb][0] + bb0 - r0 * w0, acc[nb][1] + bb1 - r0 * w1v);
            *(__half2*)(g_VTh + gp1 * 64 + ch) =
                __floats2half2_rn(acc[nb][2] + bb0 - r1 * w0, acc[nb][3] + bb1 - r1 * w1v);
        }
    }
}

// ---------------- Edge-max: hoisted w2, half2 t-build, double-buffered ET, 1 sync/shift ----------------
// ET0 16KB | ET1 16KB | EW 8KB | EV 16KB | EQH (9*64 half) | EB2
#define ET0  0
#define ET1  16384
#define EW   32768
#define EV   40960
#define EQH  57344
#define EB2  58496
#define E_SZ 58752

__global__ __launch_bounds__(256, 2) void edge_mm_kernel(
    const float* __restrict__ r, const float* __restrict__ w1,
    const float* __restrict__ w2, const float* __restrict__ b2,
    const float* __restrict__ xres, float* __restrict__ out, int add_res)
{
    extern __shared__ char smc[];
    uint32_t sb = smem_u32(smc);
    float* sB2 = (float*)(smc + EB2);
    __half* sQh = (__half*)(smc + EQH);

    int t = threadIdx.x, wid = t >> 5, ln = t & 31;
    int p0 = blockIdx.x << 7;
    int b = p0 >> 16, pl = p0 & 65535;
    int w0 = pl >> 10, h0 = pl & 1023;
    int p = t & 127, co = (t >> 7) << 5, co8 = co >> 3;

    // w2 [o][k] fp16 swizzled
    for (int e = t; e < 4096; e += 256) {
        int o = e >> 6, k = e & 63;
        *(__half*)(smc + EW + swadr(o, k >> 3) + (k & 7) * 2) = __float2half_rn(w2[e]);
    }
    {   // V' fp16 -> EV (swizzled)
        const uint4* vsrc = reinterpret_cast<const uint4*>(
            g_VTh + ((size_t)((b << 16) + pl + p)) * 64 + co);
#pragma unroll
        for (int kc = 0; kc < 4; kc++)
            *(uint4*)(smc + EV + swadr(p, co8 + kc)) = vsrc[kc];
    }
    for (int e = t; e < 576; e += 256) {
        int s = e >> 6, k = e & 63;
        int swv = s / 3 - 1, shv = s % 3 - 1;
        float ca = cosf(swv * AZI_C), sa = sinf(swv * AZI_C);
        float ci = cosf(shv * INC_C), si = sinf(shv * INC_C);
        sQh[e] = __float2half_rn(ca * ci * w1[k * 131 + 128]
                               + ca * si * w1[k * 131 + 129]
                               + sa * w1[k * 131 + 130]);
    }
    if (t < 64) sB2[t] = b2[t];
    __syncthreads();

    // hoist w2 A-fragments: warp = (mi: 2 x 32ch, ni: 4 x 32px)
    int mi = wid & 1, ni = wid >> 1;
    uint32_t wa[2][4][4];
#pragma unroll
    for (int m = 0; m < 2; m++) {
        int row = mi * 32 + m * 16 + (ln & 15);
#pragma unroll
        for (int q = 0; q < 4; q++)
            LDSM4(wa[m][q][0], wa[m][q][1], wa[m][q][2], wa[m][q][3],
                  sb + EW + swadr(row, q * 2 + (ln >> 4)));
    }

    const __half2 z2 = __float2half2_rn(0.f);
    // half2 t-build into buffer `base`
    auto buildT = [&](int s, uint32_t base) {
        int swv = s / 3 - 1, shv = s % 3 - 1;
        int wsrc = (w0 - swv) & 63;
        size_t rowb = ((size_t)(b << 16)) + ((size_t)wsrc << 10);
        int hs = (h0 + p - shv) & 1023;
        const uint4* ub = reinterpret_cast<const uint4*>(
            g_UTh + (rowb + hs) * 64 + co);
        __half2 rs2 = __float2half2_rn(__ldg(r + rowb + hs));
        const __half2* qh = reinterpret_cast<const __half2*>(sQh + s * 64 + co);
#pragma unroll
        for (int kc = 0; kc < 4; kc++) {
            uint4 uu = ub[kc];
            uint4 vv = *(const uint4*)(smc + EV + swadr(p, co8 + kc));
            const __half2* u2 = reinterpret_cast<const __half2*>(&uu);
            const __half2* v2 = reinterpret_cast<const __half2*>(&vv);
            uint4 ov;
            __half2* o2 = reinterpret_cast<__half2*>(&ov);
#pragma unroll
            for (int j = 0; j < 4; j++)
                o2[j] = __hmax2(__hfma2(rs2, qh[kc * 4 + j],
                                        __hadd2(u2[j], v2[j])), z2);
            *(uint4*)(smc + base + swadr(p, co8 + kc)) = ov;
        }
    };

    float best[2][4][4];
#pragma unroll
    for (int m = 0; m < 2; m++)
#pragma unroll
        for (int ng = 0; ng < 4; ng++)
#pragma unroll
            for (int j = 0; j < 4; j++) best[m][ng][j] = -1e30f;

    buildT(0, ET0);
    __syncthreads();

    for (int s = 0; s < 9; s++) {
        uint32_t cur = (s & 1) ? ET1 : ET0;
#pragma unroll
        for (int ng = 0; ng < 4; ng++) {
            int rowt = ni * 32 + ng * 8 + (ln & 7);
            uint32_t tb0[4], tb1[4];
            LDSM4(tb0[0], tb0[1], tb0[2], tb0[3], sb + cur + swadr(rowt, (ln >> 3)));
            LDSM4(tb1[0], tb1[1], tb1[2], tb1[3], sb + cur + swadr(rowt, 4 + (ln >> 3)));
            float acc[2][4];
#pragma unroll
            for (int m = 0; m < 2; m++)
#pragma unroll
                for (int j = 0; j < 4; j++) acc[m][j] = 0.f;
#pragma unroll
            for (int m = 0; m < 2; m++) {
                MMAF16(acc[m][0], acc[m][1], acc[m][2], acc[m][3],
                       wa[m][0][0], wa[m][0][1], wa[m][0][2], wa[m][0][3],
                       tb0[0], tb0[1]);
                MMAF16(acc[m][0], acc[m][1], acc[m][2], acc[m][3],
                       wa[m][1][0], wa[m][1][1], wa[m][1][2], wa[m][1][3],
                       tb0[2], tb0[3]);
                MMAF16(acc[m][0], acc[m][1], acc[m][2], acc[m][3],
                       wa[m][2][0], wa[m][2][1], wa[m][2][2], wa[m][2][3],
                       tb1[0], tb1[1]);
                MMAF16(acc[m][0], acc[m][1], acc[m][2], acc[m][3],
                       wa[m][3][0], wa[m][3][1], wa[m][3][2], wa[m][3][3],
                       tb1[2], tb1[3]);
            }
#pragma unroll
            for (int m = 0; m < 2; m++)
#pragma unroll
                for (int j = 0; j < 4; j++)
                    best[m][ng][j] = fmaxf(best[m][ng][j], acc[m][j]);
        }
        if (s < 8) buildT(s + 1, (s & 1) ? ET0 : ET1);
        __syncthreads();
    }

    // epilogue: D frag rows = channels, cols = pixels -> sTr[ch][136], coalesced store
    float* sTr = (float*)smc;    // [64][136] floats = 34816 B (overlays ET0/ET1/EW)
    {
        int cr = ln >> 2, cx2 = (ln & 3) << 1;
#pragma unroll
        for (int m = 0; m < 2; m++) {
            int ch0 = mi * 32 + m * 16 + cr, ch1 = ch0 + 8;
#pragma unroll
            for (int ng = 0; ng < 4; ng++) {
                int px = ni * 32 + ng * 8 + cx2;
                *(float2*)(sTr + ch0 * 136 + px) = make_float2(best[m][ng][0], best[m][ng][1]);
                *(float2*)(sTr + ch1 * 136 + px) = make_float2(best[m][ng][2], best[m][ng][3]);
            }
        }
    }
    __syncthreads();
#pragma unroll
    for (int i = 0; i < 32; i++) {
        int e = t + i * 256;
        int o = e >> 7, pix = e & 127;
        float v = sTr[o * 136 + pix] + sB2[o];
        size_t idx = (((size_t)(b * 64 + o)) << 16) + (pl + pix);
        if (add_res) v += xres[idx];
        out[idx] = v;
    }
}

// ---------------------------------------------------------------------------
extern "C" void kernel_launch(void* const* d_in, const int* in_sizes, int n_in,
                              void* d_out, int out_size) {
    const float* x     = (const float*)d_in[0];
    const float* r     = (const float*)d_in[1];
    const float* n1_w  = (const float*)d_in[2];
    const float* n1_b  = (const float*)d_in[3];
    const float* c1_w1 = (const float*)d_in[4];
    const float* c1_b1 = (const float*)d_in[5];
    const float* c1_w2 = (const float*)d_in[6];
    const float* c1_b2 = (const float*)d_in[7];
    const float* n2_w  = (const float*)d_in[8];
    const float* n2_b  = (const float*)d_in[9];
    const float* c2_w1 = (const float*)d_in[10];
    const float* c2_b1 = (const float*)d_in[11];
    const float* c2_w2 = (const float*)d_in[12];
    const float* c2_b2 = (const float*)d_in[13];
    float* out = (float*)d_out;

    cudaFuncSetAttribute(gemm_mm_kernel,
                         cudaFuncAttributeMaxDynamicSharedMemorySize, G_SZ);
    cudaFuncSetAttribute(edge_mm_kernel,
                         cudaFuncAttributeMaxDynamicSharedMemorySize, E_SZ);

    gn_part_kernel<<<1024, 256>>>(x);
    gn_fin_kernel<<<1, 128>>>();
    gemm_mm_kernel<<<2048, 256, G_SZ>>>(x, r, c1_w1, c1_b1, n1_w, n1_b);
    edge_mm_kernel<<<2048, 256, E_SZ>>>(r, c1_w1, c1_w2, c1_b2, nullptr, out, 0);

    gn_part_kernel<<<1024, 256>>>(out);
    gn_fin_kernel<<<1, 128>>>();
    gemm_mm_kernel<<<2048, 256, G_SZ>>>(out, r, c2_w1, c2_b1, n2_w, n2_b);
    edge_mm_kernel<<<2048, 256, E_SZ>>>(r, c2_w1, c2_w2, c2_b2, x, out, 1);
}

// round 13
// speedup vs baseline: 2.1214x; 1.0172x over previous
#include <cuda_runtime.h>
#include <cuda_bf16.h>
#include <cuda_fp16.h>
#include <cstdint>

#define NPIX 262144
#define AZI_C 0.006135923151542565f
#define INC_C 0.008267349088394194f

// scratch (device globals; no runtime alloc)
__device__ __half g_UTh[(size_t)NPIX * 64];   // pixel-major U  [pix][64] fp16
__device__ __half g_VTh[(size_t)NPIX * 64];   // pixel-major V' [pix][64] fp16
__device__ float g_mean[128], g_rstd[128];
__device__ float2 g_part[1024];
__device__ float2 g_pp[128 * 512];            // per-CTA group partials (layer2 stats)

// ---------------- helpers ----------------
__device__ __forceinline__ uint32_t smem_u32(const void* p) {
    uint32_t a;
    asm("{ .reg .u64 t; cvta.to.shared.u64 t, %1; cvt.u32.u64 %0, t; }" : "=r"(a) : "l"(p));
    return a;
}
#define LDSM4(r0, r1, r2, r3, a) \
    asm volatile("ldmatrix.sync.aligned.m8n8.x4.shared.b16 {%0,%1,%2,%3}, [%4];" \
        : "=r"(r0), "=r"(r1), "=r"(r2), "=r"(r3) : "r"(a))
#define MMAF16(c0, c1, c2, c3, a0, a1, a2, a3, b0, b1) \
    asm volatile("mma.sync.aligned.m16n8k16.row.col.f32.f16.f16.f32 " \
        "{%0,%1,%2,%3},{%4,%5,%6,%7},{%8,%9},{%0,%1,%2,%3};" \
        : "+f"(c0), "+f"(c1), "+f"(c2), "+f"(c3) \
        : "r"(a0), "r"(a1), "r"(a2), "r"(a3), "r"(b0), "r"(b1))

// swizzled tile addressing: pitch 128B, chunk = 16B unit
__device__ __forceinline__ uint32_t swadr(int row, int chunk) {
    return (uint32_t)(row * 128 + ((chunk ^ (row & 7)) << 4));
}

// ---------------- GroupNorm stats (layer 1), two-phase ----------------
__global__ void gn_part_kernel(const float* __restrict__ in) {
    int c = blockIdx.x, t = threadIdx.x;
    const float4* base = reinterpret_cast<const float4*>(in + (size_t)c * 16384);
    float s = 0.f, q = 0.f;
    for (int i = t; i < 4096; i += 256) {
        float4 v = base[i];
        s += (v.x + v.y) + (v.z + v.w);
        q += (v.x * v.x + v.y * v.y) + (v.z * v.z + v.w * v.w);
    }
    __shared__ float rs[256], rq[256];
    rs[t] = s; rq[t] = q;
    __syncthreads();
    for (int off = 128; off > 0; off >>= 1) {
        if (t < off) { rs[t] += rs[t + off]; rq[t] += rq[t + off]; }
        __syncthreads();
    }
    if (t == 0) g_part[c] = make_float2(rs[0], rq[0]);
}
__global__ void gn_fin_kernel() {
    int t = threadIdx.x;
    if (t < 128) {
        float s = 0.f, q = 0.f;
#pragma unroll
        for (int i = 0; i < 8; i++) { float2 p = g_part[t * 8 + i]; s += p.x; q += p.y; }
        float m = s * (1.f / 131072.f);
        g_mean[t] = m;
        g_rstd[t] = rsqrtf(q * (1.f / 131072.f) - m * m + 1e-6f);
    }
}
// layer-2 stats finalize from per-CTA partials written by edge1
__global__ void gn_fin2_kernel() {
    int bg = blockIdx.x, t = threadIdx.x;
    __shared__ float ss[256], sq2[256];
    float2 a = g_pp[bg * 512 + t];
    float2 c = g_pp[bg * 512 + 256 + t];
    ss[t]  = a.x + c.x;
    sq2[t] = a.y + c.y;
    __syncthreads();
    for (int off = 128; off > 0; off >>= 1) {
        if (t < off) { ss[t] += ss[t + off]; sq2[t] += sq2[t + off]; }
        __syncthreads();
    }
    if (t == 0) {
        float m = ss[0] * (1.f / 131072.f);
        g_mean[bg] = m;
        g_rstd[bg] = rsqrtf(sq2[0] * (1.f / 131072.f) - m * m + 1e-6f);
    }
}

// ---------------- GEMM1: U,V' = relu(gn(x)) @ [Wa;Wb]^T (single-pass fp16) ----------------
#define GA   0
#define GB   16384
#define G_CF 32768
#define G_SZ 33792

__global__ __launch_bounds__(256, 2) void gemm_mm_kernel(
    const float* __restrict__ xin, const float* __restrict__ r,
    const float* __restrict__ w1, const float* __restrict__ b1,
    const float* __restrict__ gnw, const float* __restrict__ gnb)
{
    extern __shared__ char smc[];
    uint32_t sb = smem_u32(smc);
    float* scf  = (float*)(smc + G_CF);
    float* bif  = scf + 64;
    float* b1f  = scf + 128;
    float* wp0f = scf + 192;

    int t = threadIdx.x, wid = t >> 5, ln = t & 31;
    int p0 = blockIdx.x << 7;
    int b = p0 >> 16, pl = p0 & 65535;

    if (t < 64) {
        int grp = (b << 5) + (t >> 1);
        float sc = g_rstd[grp] * gnw[t];
        scf[t]  = sc;
        bif[t]  = gnb[t] - g_mean[grp] * sc;
        b1f[t]  = b1[t];
        wp0f[t] = w1[t * 131 + 128];
    }
    // B = [Wa;Wb] fp16, swizzled
    for (int e = t; e < 8192; e += 256) {
        int n = e >> 6, k = e & 63;
        float v = (n < 64) ? w1[n * 131 + k] : w1[(n - 64) * 131 + 64 + k];
        *(__half*)(smc + GB + swadr(n, k >> 3) + (k & 7) * 2) = __float2half_rn(v);
    }
    {
        int p = t & 127, co = (t >> 7) << 5;
        const float* xb = xin + (((size_t)(b * 64 + co)) << 16) + pl + p;
#pragma unroll
        for (int kc = 0; kc < 4; kc++) {
            float xv[8];
#pragma unroll
            for (int i = 0; i < 8; i++) {
                int k = co + kc * 8 + i;
                float raw = xb[((size_t)(kc * 8 + i)) << 16];
                xv[i] = fmaxf(fmaf(raw, scf[k], bif[k]), 0.f);
            }
            __half2 h0 = __floats2half2_rn(xv[0], xv[1]);
            __half2 h1 = __floats2half2_rn(xv[2], xv[3]);
            __half2 h2 = __floats2half2_rn(xv[4], xv[5]);
            __half2 h3 = __floats2half2_rn(xv[6], xv[7]);
            *(uint4*)(smc + GA + swadr(p, (co >> 3) + kc)) = make_uint4(
                *reinterpret_cast<uint32_t*>(&h0), *reinterpret_cast<uint32_t*>(&h1),
                *reinterpret_cast<uint32_t*>(&h2), *reinterpret_cast<uint32_t*>(&h3));
        }
    }
    __syncthreads();

    int wm = wid << 4;
    float acc[16][4];
#pragma unroll
    for (int nb = 0; nb < 16; nb++)
#pragma unroll
        for (int j = 0; j < 4; j++) acc[nb][j] = 0.f;

#pragma unroll
    for (int kh = 0; kh < 2; kh++) {
        uint32_t ah[8];
        {
            int row = wm + (ln & 15);
            int c0 = kh * 4 + (ln >> 4);
            LDSM4(ah[0], ah[1], ah[2], ah[3], sb + GA + swadr(row, c0));
            LDSM4(ah[4], ah[5], ah[6], ah[7], sb + GA + swadr(row, c0 + 2));
        }
#pragma unroll
        for (int nb = 0; nb < 16; nb++) {
            int brow = nb * 8 + (ln & 7);
            int bc = kh * 4 + (ln >> 3);
            uint32_t bh[4];
            LDSM4(bh[0], bh[1], bh[2], bh[3], sb + GB + swadr(brow, bc));
            MMAF16(acc[nb][0], acc[nb][1], acc[nb][2], acc[nb][3],
                   ah[0], ah[1], ah[2], ah[3], bh[0], bh[1]);
            MMAF16(acc[nb][0], acc[nb][1], acc[nb][2], acc[nb][3],
                   ah[4], ah[5], ah[6], ah[7], bh[2], bh[3]);
        }
    }

    int pr0 = wm + (ln >> 2), pr1 = pr0 + 8;
    int cx = (ln & 3) << 1;
    size_t gp0 = (size_t)((b << 16) + pl + pr0);
    size_t gp1 = (size_t)((b << 16) + pl + pr1);
    float r0 = r[gp0], r1 = r[gp1];
#pragma unroll
    for (int nb = 0; nb < 16; nb++) {
        if (nb < 8) {
            int ch = nb * 8 + cx;
            *(__half2*)(g_UTh + gp0 * 64 + ch) = __floats2half2_rn(acc[nb][0], acc[nb][1]);
            *(__half2*)(g_UTh + gp1 * 64 + ch) = __floats2half2_rn(acc[nb][2], acc[nb][3]);
        } else {
            int ch = (nb - 8) * 8 + cx;
            float bb0 = b1f[ch], bb1 = b1f[ch + 1];
            float w0 = wp0f[ch], w1v = wp0f[ch + 1];
            *(__half2*)(g_VTh + gp0 * 64 + ch) =
                __floats2half2_rn(acc[nb][0] + bb0 - r0 * w0, acc[nb][1] + bb1 - r0 * w1v);
            *(__half2*)(g_VTh + gp1 * 64 + ch) =
                __floats2half2_rn(acc[nb][2] + bb0 - r1 * w0, acc[nb][3] + bb1 - r1 * w1v);
        }
    }
}

// ---------------- Edge-max: hoisted w2, V' in regs, half2 best, dbl-buffered ET ----------------
// ET0 16KB | ET1 16KB | EW 8KB | EQH (9*64 half) | EB2
#define ET0  0
#define ET1  16384
#define EW   32768
#define EQH  40960
#define EB2  42112
#define E_SZ 42368

__global__ __launch_bounds__(256, 2) void edge_mm_kernel(
    const float* __restrict__ r, const float* __restrict__ w1,
    const float* __restrict__ w2, const float* __restrict__ b2,
    const float* __restrict__ xres, float* __restrict__ out, int add_res)
{
    extern __shared__ char smc[];
    uint32_t sb = smem_u32(smc);
    float* sB2 = (float*)(smc + EB2);
    __half* sQh = (__half*)(smc + EQH);

    int t = threadIdx.x, wid = t >> 5, ln = t & 31;
    int p0 = blockIdx.x << 7;
    int b = p0 >> 16, pl = p0 & 65535;
    int w0 = pl >> 10, h0 = pl & 1023;
    int p = t & 127, co = (t >> 7) << 5, co8 = co >> 3;

    // w2 [o][k] fp16 swizzled
    for (int e = t; e < 4096; e += 256) {
        int o = e >> 6, k = e & 63;
        *(__half*)(smc + EW + swadr(o, k >> 3) + (k & 7) * 2) = __float2half_rn(w2[e]);
    }
    // V' -> registers (16 regs as 4 x uint4)
    uint4 vR[4];
    {
        const uint4* vsrc = reinterpret_cast<const uint4*>(
            g_VTh + ((size_t)((b << 16) + pl + p)) * 64 + co);
#pragma unroll
        for (int kc = 0; kc < 4; kc++) vR[kc] = vsrc[kc];
    }
    for (int e = t; e < 576; e += 256) {
        int s = e >> 6, k = e & 63;
        int swv = s / 3 - 1, shv = s % 3 - 1;
        float ca = cosf(swv * AZI_C), sa = sinf(swv * AZI_C);
        float ci = cosf(shv * INC_C), si = sinf(shv * INC_C);
        sQh[e] = __float2half_rn(ca * ci * w1[k * 131 + 128]
                               + ca * si * w1[k * 131 + 129]
                               + sa * w1[k * 131 + 130]);
    }
    if (t < 64) sB2[t] = b2[t];
    __syncthreads();

    // hoist w2 A-fragments: warp = (mi: 2 x 32ch, ni: 4 x 32px)
    int mi = wid & 1, ni = wid >> 1;
    uint32_t wa[2][4][4];
#pragma unroll
    for (int m = 0; m < 2; m++) {
        int row = mi * 32 + m * 16 + (ln & 15);
#pragma unroll
        for (int q = 0; q < 4; q++)
            LDSM4(wa[m][q][0], wa[m][q][1], wa[m][q][2], wa[m][q][3],
                  sb + EW + swadr(row, q * 2 + (ln >> 4)));
    }

    const __half2 z2 = __float2half2_rn(0.f);
    // half2 t-build into buffer `base`
    auto buildT = [&](int s, uint32_t base) {
        int swv = s / 3 - 1, shv = s % 3 - 1;
        int wsrc = (w0 - swv) & 63;
        size_t rowb = ((size_t)(b << 16)) + ((size_t)wsrc << 10);
        int hs = (h0 + p - shv) & 1023;
        const uint4* ub = reinterpret_cast<const uint4*>(
            g_UTh + (rowb + hs) * 64 + co);
        __half2 rs2 = __float2half2_rn(__ldg(r + rowb + hs));
        const __half2* qh = reinterpret_cast<const __half2*>(sQh + s * 64 + co);
#pragma unroll
        for (int kc = 0; kc < 4; kc++) {
            uint4 uu = ub[kc];
            const __half2* u2 = reinterpret_cast<const __half2*>(&uu);
            const __half2* v2 = reinterpret_cast<const __half2*>(&vR[kc]);
            uint4 ov;
            __half2* o2 = reinterpret_cast<__half2*>(&ov);
#pragma unroll
            for (int j = 0; j < 4; j++)
                o2[j] = __hmax2(__hfma2(rs2, qh[kc * 4 + j],
                                        __hadd2(u2[j], v2[j])), z2);
            *(uint4*)(smc + base + swadr(p, co8 + kc)) = ov;
        }
    };

    __half2 bestH[2][4][2];
    const __half2 ninf = __float2half2_rn(-65504.f);
#pragma unroll
    for (int m = 0; m < 2; m++)
#pragma unroll
        for (int ng = 0; ng < 4; ng++) {
            bestH[m][ng][0] = ninf;
            bestH[m][ng][1] = ninf;
        }

    buildT(0, ET0);
    __syncthreads();

    for (int s = 0; s < 9; s++) {
        uint32_t cur = (s & 1) ? ET1 : ET0;
#pragma unroll
        for (int ng = 0; ng < 4; ng++) {
            int rowt = ni * 32 + ng * 8 + (ln & 7);
            uint32_t tb0[4], tb1[4];
            LDSM4(tb0[0], tb0[1], tb0[2], tb0[3], sb + cur + swadr(rowt, (ln >> 3)));
            LDSM4(tb1[0], tb1[1], tb1[2], tb1[3], sb + cur + swadr(rowt, 4 + (ln >> 3)));
            float acc[2][4];
#pragma unroll
            for (int m = 0; m < 2; m++)
#pragma unroll
                for (int j = 0; j < 4; j++) acc[m][j] = 0.f;
#pragma unroll
            for (int m = 0; m < 2; m++) {
                MMAF16(acc[m][0], acc[m][1], acc[m][2], acc[m][3],
                       wa[m][0][0], wa[m][0][1], wa[m][0][2], wa[m][0][3],
                       tb0[0], tb0[1]);
                MMAF16(acc[m][0], acc[m][1], acc[m][2], acc[m][3],
                       wa[m][1][0], wa[m][1][1], wa[m][1][2], wa[m][1][3],
                       tb0[2], tb0[3]);
                MMAF16(acc[m][0], acc[m][1], acc[m][2], acc[m][3],
                       wa[m][2][0], wa[m][2][1], wa[m][2][2], wa[m][2][3],
                       tb1[0], tb1[1]);
                MMAF16(acc[m][0], acc[m][1], acc[m][2], acc[m][3],
                       wa[m][3][0], wa[m][3][1], wa[m][3][2], wa[m][3][3],
                       tb1[2], tb1[3]);
            }
#pragma unroll
            for (int m = 0; m < 2; m++) {
                bestH[m][ng][0] = __hmax2(bestH[m][ng][0],
                                          __floats2half2_rn(acc[m][0], acc[m][1]));
                bestH[m][ng][1] = __hmax2(bestH[m][ng][1],
                                          __floats2half2_rn(acc[m][2], acc[m][3]));
            }
        }
        if (s < 8) buildT(s + 1, (s & 1) ? ET0 : ET1);
        __syncthreads();
    }

    // epilogue: D frag rows = channels, cols = pixels -> sTr[ch][136], coalesced store
    float* sTr = (float*)smc;    // [64][136] floats = 34816 B (overlays ET0/ET1/EW)
    {
        int cr = ln >> 2, cx2 = (ln & 3) << 1;
#pragma unroll
        for (int m = 0; m < 2; m++) {
            int ch0 = mi * 32 + m * 16 + cr, ch1 = ch0 + 8;
#pragma unroll
            for (int ng = 0; ng < 4; ng++) {
                int px = ni * 32 + ng * 8 + cx2;
                float2 f0 = __half22float2(bestH[m][ng][0]);
                float2 f1 = __half22float2(bestH[m][ng][1]);
                *(float2*)(sTr + ch0 * 136 + px) = f0;
                *(float2*)(sTr + ch1 * 136 + px) = f1;
            }
        }
    }
    __syncthreads();
#pragma unroll
    for (int i = 0; i < 32; i++) {
        int e = t + i * 256;
        int o = e >> 7, pix = e & 127;
        float v = sTr[o * 136 + pix] + sB2[o];
        size_t idx = (((size_t)(b * 64 + o)) << 16) + (pl + pix);
        if (add_res) v += xres[idx];
        out[idx] = v;
    }

    // layer-1 only: per-CTA group partial sums for gn2 (deterministic, no atomics)
    if (!add_res && t < 64) {
        float bias = sB2[t];
        float s = 0.f, q = 0.f;
        const float* row = sTr + t * 136;
#pragma unroll 4
        for (int px = 0; px < 128; px++) {
            float v = row[px] + bias;
            s += v;
            q += v * v;
        }
        s += __shfl_xor_sync(0xffffffffu, s, 1);
        q += __shfl_xor_sync(0xffffffffu, q, 1);
        if ((t & 1) == 0) {
            int g = t >> 1;
            g_pp[((b << 5) + g) * 512 + (blockIdx.x & 511)] = make_float2(s, q);
        }
    }
}

// ---------------------------------------------------------------------------
extern "C" void kernel_launch(void* const* d_in, const int* in_sizes, int n_in,
                              void* d_out, int out_size) {
    const float* x     = (const float*)d_in[0];
    const float* r     = (const float*)d_in[1];
    const float* n1_w  = (const float*)d_in[2];
    const float* n1_b  = (const float*)d_in[3];
    const float* c1_w1 = (const float*)d_in[4];
    const float* c1_b1 = (const float*)d_in[5];
    const float* c1_w2 = (const float*)d_in[6];
    const float* c1_b2 = (const float*)d_in[7];
    const float* n2_w  = (const float*)d_in[8];
    const float* n2_b  = (const float*)d_in[9];
    const float* c2_w1 = (const float*)d_in[10];
    const float* c2_b1 = (const float*)d_in[11];
    const float* c2_w2 = (const float*)d_in[12];
    const float* c2_b2 = (const float*)d_in[13];
    float* out = (float*)d_out;

    cudaFuncSetAttribute(gemm_mm_kernel,
                         cudaFuncAttributeMaxDynamicSharedMemorySize, G_SZ);
    cudaFuncSetAttribute(edge_mm_kernel,
                         cudaFuncAttributeMaxDynamicSharedMemorySize, E_SZ);

    gn_part_kernel<<<1024, 256>>>(x);
    gn_fin_kernel<<<1, 128>>>();
    gemm_mm_kernel<<<2048, 256, G_SZ>>>(x, r, c1_w1, c1_b1, n1_w, n1_b);
    edge_mm_kernel<<<2048, 256, E_SZ>>>(r, c1_w1, c1_w2, c1_b2, nullptr, out, 0);

    gn_fin2_kernel<<<128, 256>>>();
    gemm_mm_kernel<<<2048, 256, G_SZ>>>(out, r, c2_w1, c2_b1, n2_w, n2_b);
    edge_mm_kernel<<<2048, 256, E_SZ>>>(r, c2_w1, c2_w2, c2_b2, x, out, 1);
}

// round 14
// speedup vs baseline: 2.1306x; 1.0043x over previous
#include <cuda_runtime.h>
#include <cuda_bf16.h>
#include <cuda_fp16.h>
#include <cstdint>

#define NPIX 262144
#define AZI_C 0.006135923151542565f
#define INC_C 0.008267349088394194f

// scratch (device globals; no runtime alloc)
__device__ __half g_UTh[(size_t)NPIX * 64];   // pixel-major U  [pix][64] fp16
__device__ __half g_VTh[(size_t)NPIX * 64];   // pixel-major V' [pix][64] fp16
__device__ float g_mean[128], g_rstd[128];
__device__ float2 g_part[1024];
__device__ float2 g_pp[128 * 512];            // per-CTA group partials (layer2 stats)

// ---------------- helpers ----------------
__device__ __forceinline__ uint32_t smem_u32(const void* p) {
    uint32_t a;
    asm("{ .reg .u64 t; cvta.to.shared.u64 t, %1; cvt.u32.u64 %0, t; }" : "=r"(a) : "l"(p));
    return a;
}
#define LDSM4(r0, r1, r2, r3, a) \
    asm volatile("ldmatrix.sync.aligned.m8n8.x4.shared.b16 {%0,%1,%2,%3}, [%4];" \
        : "=r"(r0), "=r"(r1), "=r"(r2), "=r"(r3) : "r"(a))
#define MMAF16(c0, c1, c2, c3, a0, a1, a2, a3, b0, b1) \
    asm volatile("mma.sync.aligned.m16n8k16.row.col.f32.f16.f16.f32 " \
        "{%0,%1,%2,%3},{%4,%5,%6,%7},{%8,%9},{%0,%1,%2,%3};" \
        : "+f"(c0), "+f"(c1), "+f"(c2), "+f"(c3) \
        : "r"(a0), "r"(a1), "r"(a2), "r"(a3), "r"(b0), "r"(b1))

// swizzled tile addressing: pitch 128B, chunk = 16B unit
__device__ __forceinline__ uint32_t swadr(int row, int chunk) {
    return (uint32_t)(row * 128 + ((chunk ^ (row & 7)) << 4));
}

// ---------------- GroupNorm stats (layer 1), two-phase ----------------
__global__ void gn_part_kernel(const float* __restrict__ in) {
    int c = blockIdx.x, t = threadIdx.x;
    const float4* base = reinterpret_cast<const float4*>(in + (size_t)c * 16384);
    float s = 0.f, q = 0.f;
    for (int i = t; i < 4096; i += 256) {
        float4 v = base[i];
        s += (v.x + v.y) + (v.z + v.w);
        q += (v.x * v.x + v.y * v.y) + (v.z * v.z + v.w * v.w);
    }
    __shared__ float rs[256], rq[256];
    rs[t] = s; rq[t] = q;
    __syncthreads();
    for (int off = 128; off > 0; off >>= 1) {
        if (t < off) { rs[t] += rs[t + off]; rq[t] += rq[t + off]; }
        __syncthreads();
    }
    if (t == 0) g_part[c] = make_float2(rs[0], rq[0]);
}
__global__ void gn_fin_kernel() {
    int t = threadIdx.x;
    if (t < 128) {
        float s = 0.f, q = 0.f;
#pragma unroll
        for (int i = 0; i < 8; i++) { float2 p = g_part[t * 8 + i]; s += p.x; q += p.y; }
        float m = s * (1.f / 131072.f);
        g_mean[t] = m;
        g_rstd[t] = rsqrtf(q * (1.f / 131072.f) - m * m + 1e-6f);
    }
}
// layer-2 stats finalize from per-CTA partials written by edge1
__global__ void gn_fin2_kernel() {
    int bg = blockIdx.x, t = threadIdx.x;
    __shared__ float ss[256], sq2[256];
    float2 a = g_pp[bg * 512 + t];
    float2 c = g_pp[bg * 512 + 256 + t];
    ss[t]  = a.x + c.x;
    sq2[t] = a.y + c.y;
    __syncthreads();
    for (int off = 128; off > 0; off >>= 1) {
        if (t < off) { ss[t] += ss[t + off]; sq2[t] += sq2[t + off]; }
        __syncthreads();
    }
    if (t == 0) {
        float m = ss[0] * (1.f / 131072.f);
        g_mean[bg] = m;
        g_rstd[bg] = rsqrtf(sq2[0] * (1.f / 131072.f) - m * m + 1e-6f);
    }
}

// ---------------- GEMM1: U,V' = relu(gn(x)) @ [Wa;Wb]^T (single-pass fp16) ----------------
#define GA   0
#define GB   16384
#define G_CF 32768
#define G_SZ 33792

__global__ __launch_bounds__(256, 2) void gemm_mm_kernel(
    const float* __restrict__ xin, const float* __restrict__ r,
    const float* __restrict__ w1, const float* __restrict__ b1,
    const float* __restrict__ gnw, const float* __restrict__ gnb)
{
    extern __shared__ char smc[];
    uint32_t sb = smem_u32(smc);
    float* scf  = (float*)(smc + G_CF);
    float* bif  = scf + 64;
    float* b1f  = scf + 128;
    float* wp0f = scf + 192;

    int t = threadIdx.x, wid = t >> 5, ln = t & 31;
    int p0 = blockIdx.x << 7;
    int b = p0 >> 16, pl = p0 & 65535;

    if (t < 64) {
        int grp = (b << 5) + (t >> 1);
        float sc = g_rstd[grp] * gnw[t];
        scf[t]  = sc;
        bif[t]  = gnb[t] - g_mean[grp] * sc;
        b1f[t]  = b1[t];
        wp0f[t] = w1[t * 131 + 128];
    }
    // B = [Wa;Wb] fp16, swizzled
    for (int e = t; e < 8192; e += 256) {
        int n = e >> 6, k = e & 63;
        float v = (n < 64) ? w1[n * 131 + k] : w1[(n - 64) * 131 + 64 + k];
        *(__half*)(smc + GB + swadr(n, k >> 3) + (k & 7) * 2) = __float2half_rn(v);
    }
    {
        int p = t & 127, co = (t >> 7) << 5;
        const float* xb = xin + (((size_t)(b * 64 + co)) << 16) + pl + p;
#pragma unroll
        for (int kc = 0; kc < 4; kc++) {
            float xv[8];
#pragma unroll
            for (int i = 0; i < 8; i++) {
                int k = co + kc * 8 + i;
                float raw = xb[((size_t)(kc * 8 + i)) << 16];
                xv[i] = fmaxf(fmaf(raw, scf[k], bif[k]), 0.f);
            }
            __half2 h0 = __floats2half2_rn(xv[0], xv[1]);
            __half2 h1 = __floats2half2_rn(xv[2], xv[3]);
            __half2 h2 = __floats2half2_rn(xv[4], xv[5]);
            __half2 h3 = __floats2half2_rn(xv[6], xv[7]);
            *(uint4*)(smc + GA + swadr(p, (co >> 3) + kc)) = make_uint4(
                *reinterpret_cast<uint32_t*>(&h0), *reinterpret_cast<uint32_t*>(&h1),
                *reinterpret_cast<uint32_t*>(&h2), *reinterpret_cast<uint32_t*>(&h3));
        }
    }
    __syncthreads();

    int wm = wid << 4;
    float acc[16][4];
#pragma unroll
    for (int nb = 0; nb < 16; nb++)
#pragma unroll
        for (int j = 0; j < 4; j++) acc[nb][j] = 0.f;

#pragma unroll
    for (int kh = 0; kh < 2; kh++) {
        uint32_t ah[8];
        {
            int row = wm + (ln & 15);
            int c0 = kh * 4 + (ln >> 4);
            LDSM4(ah[0], ah[1], ah[2], ah[3], sb + GA + swadr(row, c0));
            LDSM4(ah[4], ah[5], ah[6], ah[7], sb + GA + swadr(row, c0 + 2));
        }
#pragma unroll
        for (int nb = 0; nb < 16; nb++) {
            int brow = nb * 8 + (ln & 7);
            int bc = kh * 4 + (ln >> 3);
            uint32_t bh[4];
            LDSM4(bh[0], bh[1], bh[2], bh[3], sb + GB + swadr(brow, bc));
            MMAF16(acc[nb][0], acc[nb][1], acc[nb][2], acc[nb][3],
                   ah[0], ah[1], ah[2], ah[3], bh[0], bh[1]);
            MMAF16(acc[nb][0], acc[nb][1], acc[nb][2], acc[nb][3],
                   ah[4], ah[5], ah[6], ah[7], bh[2], bh[3]);
        }
    }

    int pr0 = wm + (ln >> 2), pr1 = pr0 + 8;
    int cx = (ln & 3) << 1;
    size_t gp0 = (size_t)((b << 16) + pl + pr0);
    size_t gp1 = (size_t)((b << 16) + pl + pr1);
    float r0 = r[gp0], r1 = r[gp1];
#pragma unroll
    for (int nb = 0; nb < 16; nb++) {
        if (nb < 8) {
            int ch = nb * 8 + cx;
            *(__half2*)(g_UTh + gp0 * 64 + ch) = __floats2half2_rn(acc[nb][0], acc[nb][1]);
            *(__half2*)(g_UTh + gp1 * 64 + ch) = __floats2half2_rn(acc[nb][2], acc[nb][3]);
        } else {
            int ch = (nb - 8) * 8 + cx;
            float bb0 = b1f[ch], bb1 = b1f[ch + 1];
            float w0 = wp0f[ch], w1v = wp0f[ch + 1];
            *(__half2*)(g_VTh + gp0 * 64 + ch) =
                __floats2half2_rn(acc[nb][0] + bb0 - r0 * w0, acc[nb][1] + bb1 - r0 * w1v);
            *(__half2*)(g_VTh + gp1 * 64 + ch) =
                __floats2half2_rn(acc[nb][2] + bb0 - r1 * w0, acc[nb][3] + bb1 - r1 * w1v);
        }
    }
}

// ---------------- Edge-max: hoisted w2, prefetched U, half2 build/max, dbl-buffered ET ----------------
// ET0 16KB | ET1 16KB | EW 8KB | EV 16KB | EQH (9*64 half) | EB2
#define ET0  0
#define ET1  16384
#define EW   32768
#define EV   40960
#define EQH  57344
#define EB2  58496
#define E_SZ 58752

__global__ __launch_bounds__(256, 2) void edge_mm_kernel(
    const float* __restrict__ r, const float* __restrict__ w1,
    const float* __restrict__ w2, const float* __restrict__ b2,
    const float* __restrict__ xres, float* __restrict__ out, int add_res)
{
    extern __shared__ char smc[];
    uint32_t sb = smem_u32(smc);
    float* sB2 = (float*)(smc + EB2);
    __half* sQh = (__half*)(smc + EQH);

    int t = threadIdx.x, wid = t >> 5, ln = t & 31;
    int p0 = blockIdx.x << 7;
    int b = p0 >> 16, pl = p0 & 65535;
    int w0 = pl >> 10, h0 = pl & 1023;
    int p = t & 127, co = (t >> 7) << 5, co8 = co >> 3;

    // w2 [o][k] fp16 swizzled
    for (int e = t; e < 4096; e += 256) {
        int o = e >> 6, k = e & 63;
        *(__half*)(smc + EW + swadr(o, k >> 3) + (k & 7) * 2) = __float2half_rn(w2[e]);
    }
    {   // V' fp16 -> EV (swizzled)
        const uint4* vsrc = reinterpret_cast<const uint4*>(
            g_VTh + ((size_t)((b << 16) + pl + p)) * 64 + co);
#pragma unroll
        for (int kc = 0; kc < 4; kc++)
            *(uint4*)(smc + EV + swadr(p, co8 + kc)) = vsrc[kc];
    }
    for (int e = t; e < 576; e += 256) {
        int s = e >> 6, k = e & 63;
        int swv = s / 3 - 1, shv = s % 3 - 1;
        float ca = cosf(swv * AZI_C), sa = sinf(swv * AZI_C);
        float ci = cosf(shv * INC_C), si = sinf(shv * INC_C);
        sQh[e] = __float2half_rn(ca * ci * w1[k * 131 + 128]
                               + ca * si * w1[k * 131 + 129]
                               + sa * w1[k * 131 + 130]);
    }
    if (t < 64) sB2[t] = b2[t];
    __syncthreads();

    // hoist w2 A-fragments: warp = (mi: 2 x 32ch, ni: 4 x 32px)
    int mi = wid & 1, ni = wid >> 1;
    uint32_t wa[2][4][4];
#pragma unroll
    for (int m = 0; m < 2; m++) {
        int row = mi * 32 + m * 16 + (ln & 15);
#pragma unroll
        for (int q = 0; q < 4; q++)
            LDSM4(wa[m][q][0], wa[m][q][1], wa[m][q][2], wa[m][q][3],
                  sb + EW + swadr(row, q * 2 + (ln >> 4)));
    }

    // ---- U prefetch into registers (double-buffer across loop body) ----
    uint4 uR[4];
    float rsR;
    auto prefetchU = [&](int s) {
        int swv = s / 3 - 1, shv = s % 3 - 1;
        int wsrc = (w0 - swv) & 63;
        size_t rowb = ((size_t)(b << 16)) + ((size_t)wsrc << 10);
        int hs = (h0 + p - shv) & 1023;
        const uint4* ub = reinterpret_cast<const uint4*>(
            g_UTh + (rowb + hs) * 64 + co);
#pragma unroll
        for (int kc = 0; kc < 4; kc++) uR[kc] = ub[kc];
        rsR = __ldg(r + rowb + hs);
    };

    const __half2 z2 = __float2half2_rn(0.f);
    // half2 t-build into buffer `base`, consuming prefetched uR/rsR
    auto storeT = [&](int s, uint32_t base) {
        __half2 rs2 = __float2half2_rn(rsR);
        const __half2* qh = reinterpret_cast<const __half2*>(sQh + s * 64 + co);
#pragma unroll
        for (int kc = 0; kc < 4; kc++) {
            uint4 vv = *(const uint4*)(smc + EV + swadr(p, co8 + kc));
            const __half2* u2 = reinterpret_cast<const __half2*>(&uR[kc]);
            const __half2* v2 = reinterpret_cast<const __half2*>(&vv);
            uint4 ov;
            __half2* o2 = reinterpret_cast<__half2*>(&ov);
#pragma unroll
            for (int j = 0; j < 4; j++)
                o2[j] = __hmax2(__hfma2(rs2, qh[kc * 4 + j],
                                        __hadd2(u2[j], v2[j])), z2);
            *(uint4*)(smc + base + swadr(p, co8 + kc)) = ov;
        }
    };

    __half2 bestH[2][4][2];
    const __half2 ninf = __float2half2_rn(-65504.f);
#pragma unroll
    for (int m = 0; m < 2; m++)
#pragma unroll
        for (int ng = 0; ng < 4; ng++) {
            bestH[m][ng][0] = ninf;
            bestH[m][ng][1] = ninf;
        }

    prefetchU(0);
    storeT(0, ET0);
    prefetchU(1);          // LDG latency hidden under barrier + MMA(0)
    __syncthreads();

    for (int s = 0; s < 9; s++) {
        uint32_t cur = (s & 1) ? ET1 : ET0;
#pragma unroll
        for (int ng = 0; ng < 4; ng++) {
            int rowt = ni * 32 + ng * 8 + (ln & 7);
            uint32_t tb0[4], tb1[4];
            LDSM4(tb0[0], tb0[1], tb0[2], tb0[3], sb + cur + swadr(rowt, (ln >> 3)));
            LDSM4(tb1[0], tb1[1], tb1[2], tb1[3], sb + cur + swadr(rowt, 4 + (ln >> 3)));
            float acc[2][4];
#pragma unroll
            for (int m = 0; m < 2; m++)
#pragma unroll
                for (int j = 0; j < 4; j++) acc[m][j] = 0.f;
#pragma unroll
            for (int m = 0; m < 2; m++) {
                MMAF16(acc[m][0], acc[m][1], acc[m][2], acc[m][3],
                       wa[m][0][0], wa[m][0][1], wa[m][0][2], wa[m][0][3],
                       tb0[0], tb0[1]);
                MMAF16(acc[m][0], acc[m][1], acc[m][2], acc[m][3],
                       wa[m][1][0], wa[m][1][1], wa[m][1][2], wa[m][1][3],
                       tb0[2], tb0[3]);
                MMAF16(acc[m][0], acc[m][1], acc[m][2], acc[m][3],
                       wa[m][2][0], wa[m][2][1], wa[m][2][2], wa[m][2][3],
                       tb1[0], tb1[1]);
                MMAF16(acc[m][0], acc[m][1], acc[m][2], acc[m][3],
                       wa[m][3][0], wa[m][3][1], wa[m][3][2], wa[m][3][3],
                       tb1[2], tb1[3]);
            }
#pragma unroll
            for (int m = 0; m < 2; m++) {
                bestH[m][ng][0] = __hmax2(bestH[m][ng][0],
                                          __floats2half2_rn(acc[m][0], acc[m][1]));
                bestH[m][ng][1] = __hmax2(bestH[m][ng][1],
                                          __floats2half2_rn(acc[m][2], acc[m][3]));
            }
        }
        if (s < 8) {
            storeT(s + 1, (s & 1) ? ET0 : ET1);   // consume prefetched U(s+1)
            if (s < 7) prefetchU(s + 2);          // issue next LDG pre-barrier
            __syncthreads();
        }
    }
    __syncthreads();

    // epilogue: D frag rows = channels, cols = pixels -> sTr[ch][136], coalesced store
    float* sTr = (float*)smc;    // [64][136] floats = 34816 B (overlays ET0/ET1/EW)
    {
        int cr = ln >> 2, cx2 = (ln & 3) << 1;
#pragma unroll
        for (int m = 0; m < 2; m++) {
            int ch0 = mi * 32 + m * 16 + cr, ch1 = ch0 + 8;
#pragma unroll
            for (int ng = 0; ng < 4; ng++) {
                int px = ni * 32 + ng * 8 + cx2;
                float2 f0 = __half22float2(bestH[m][ng][0]);
                float2 f1 = __half22float2(bestH[m][ng][1]);
                *(float2*)(sTr + ch0 * 136 + px) = f0;
                *(float2*)(sTr + ch1 * 136 + px) = f1;
            }
        }
    }
    __syncthreads();
#pragma unroll
    for (int i = 0; i < 32; i++) {
        int e = t + i * 256;
        int o = e >> 7, pix = e & 127;
        float v = sTr[o * 136 + pix] + sB2[o];
        size_t idx = (((size_t)(b * 64 + o)) << 16) + (pl + pix);
        if (add_res) v += xres[idx];
        out[idx] = v;
    }

    // layer-1 only: per-CTA group partial sums for gn2 (deterministic, no atomics)
    if (!add_res && t < 64) {
        float bias = sB2[t];
        float s = 0.f, q = 0.f;
        const float* row = sTr + t * 136;
#pragma unroll 4
        for (int px = 0; px < 128; px++) {
            float v = row[px] + bias;
            s += v;
            q += v * v;
        }
        s += __shfl_xor_sync(0xffffffffu, s, 1);
        q += __shfl_xor_sync(0xffffffffu, q, 1);
        if ((t & 1) == 0) {
            int g = t >> 1;
            g_pp[((b << 5) + g) * 512 + (blockIdx.x & 511)] = make_float2(s, q);
        }
    }
}

// ---------------------------------------------------------------------------
extern "C" void kernel_launch(void* const* d_in, const int* in_sizes, int n_in,
                              void* d_out, int out_size) {
    const float* x     = (const float*)d_in[0];
    const float* r     = (const float*)d_in[1];
    const float* n1_w  = (const float*)d_in[2];
    const float* n1_b  = (const float*)d_in[3];
    const float* c1_w1 = (const float*)d_in[4];
    const float* c1_b1 = (const float*)d_in[5];
    const float* c1_w2 = (const float*)d_in[6];
    const float* c1_b2 = (const float*)d_in[7];
    const float* n2_w  = (const float*)d_in[8];
    const float* n2_b  = (const float*)d_in[9];
    const float* c2_w1 = (const float*)d_in[10];
    const float* c2_b1 = (const float*)d_in[11];
    const float* c2_w2 = (const float*)d_in[12];
    const float* c2_b2 = (const float*)d_in[13];
    float* out = (float*)d_out;

    cudaFuncSetAttribute(gemm_mm_kernel,
                         cudaFuncAttributeMaxDynamicSharedMemorySize, G_SZ);
    cudaFuncSetAttribute(edge_mm_kernel,
                         cudaFuncAttributeMaxDynamicSharedMemorySize, E_SZ);

    gn_part_kernel<<<1024, 256>>>(x);
    gn_fin_kernel<<<1, 128>>>();
    gemm_mm_kernel<<<2048, 256, G_SZ>>>(x, r, c1_w1, c1_b1, n1_w, n1_b);
    edge_mm_kernel<<<2048, 256, E_SZ>>>(r, c1_w1, c1_w2, c1_b2, nullptr, out, 0);

    gn_fin2_kernel<<<128, 256>>>();
    gemm_mm_kernel<<<2048, 256, G_SZ>>>(out, r, c2_w1, c2_b1, n2_w, n2_b);
    edge_mm_kernel<<<2048, 256, E_SZ>>>(r, c2_w1, c2_w2, c2_b2, x, out, 1);
}